// round 9
// baseline (speedup 1.0000x reference)
#include <cuda_runtime.h>
#include <cuda_bf16.h>
#include <math.h>
#include <stdint.h>

// Problem dims
constexpr int Bn = 2, Sn = 2048, Hn = 4096, NHn = 32, NKVn = 8, HDn = 128;
constexpr int Mn = Bn * Sn;
constexpr float QK_SCALE = 0.08838834764831845f; // 1/sqrt(128)
constexpr float L2E = 1.4426950408889634f;

// bf16 split scratch
__device__ __nv_bfloat16 g_Xhi[(size_t)Mn * Hn];   // X split; reused for attn out
__device__ __nv_bfloat16 g_Xlo[(size_t)Mn * Hn];
__device__ __nv_bfloat16 g_WqThi[(size_t)4096 * 4096];
__device__ __nv_bfloat16 g_WqTlo[(size_t)4096 * 4096];
__device__ __nv_bfloat16 g_WkThi[(size_t)1024 * 4096];
__device__ __nv_bfloat16 g_WkTlo[(size_t)1024 * 4096];
__device__ __nv_bfloat16 g_WvThi[(size_t)1024 * 4096];
__device__ __nv_bfloat16 g_WvTlo[(size_t)1024 * 4096];
__device__ __nv_bfloat16 g_WoThi[(size_t)4096 * 4096];
__device__ __nv_bfloat16 g_WoTlo[(size_t)4096 * 4096];
// attention operands (hi/lo, post-RoPE), written by GEMM epilogues
__device__ __nv_bfloat16 g_Qh[(size_t)Bn * NHn * Sn * HDn];
__device__ __nv_bfloat16 g_Ql[(size_t)Bn * NHn * Sn * HDn];
__device__ __nv_bfloat16 g_Kh[(size_t)Bn * NKVn * Sn * HDn];
__device__ __nv_bfloat16 g_Kl[(size_t)Bn * NKVn * Sn * HDn];
__device__ __nv_bfloat16 g_Vh[(size_t)Bn * NKVn * Sn * HDn];
__device__ __nv_bfloat16 g_Vl[(size_t)Bn * NKVn * Sn * HDn];
// RoPE cos/sin table [s][d<64]
__device__ float2 g_RT[(size_t)Sn * 64];

// ---------------------------------------------------------------------------
// helpers
// ---------------------------------------------------------------------------
__device__ __forceinline__ uint32_t smem_u32(const void* p) {
    uint32_t a;
    asm("{ .reg .u64 t; cvta.to.shared.u64 t, %1; cvt.u32.u64 %0, t; }"
        : "=r"(a) : "l"(p));
    return a;
}
__device__ __forceinline__ void cpa16(uint32_t dst, const void* src) {
    asm volatile("cp.async.cg.shared.global [%0], [%1], 16;"
                 :: "r"(dst), "l"(src) : "memory");
}
__device__ __forceinline__ void ldsm4(uint32_t& r0, uint32_t& r1,
                                      uint32_t& r2, uint32_t& r3, uint32_t a) {
    asm volatile("ldmatrix.sync.aligned.m8n8.x4.shared.b16 {%0,%1,%2,%3}, [%4];"
                 : "=r"(r0), "=r"(r1), "=r"(r2), "=r"(r3) : "r"(a));
}
__device__ __forceinline__ void ldsm4t(uint32_t& r0, uint32_t& r1,
                                       uint32_t& r2, uint32_t& r3, uint32_t a) {
    asm volatile("ldmatrix.sync.aligned.m8n8.x4.trans.shared.b16 {%0,%1,%2,%3}, [%4];"
                 : "=r"(r0), "=r"(r1), "=r"(r2), "=r"(r3) : "r"(a));
}
__device__ __forceinline__ void mma_bf16(float* c, const uint32_t* a,
                                         const uint32_t* b) {
    asm volatile(
        "mma.sync.aligned.m16n8k16.row.col.f32.bf16.bf16.f32 "
        "{%0,%1,%2,%3}, {%4,%5,%6,%7}, {%8,%9}, {%0,%1,%2,%3};"
        : "+f"(c[0]), "+f"(c[1]), "+f"(c[2]), "+f"(c[3])
        : "r"(a[0]), "r"(a[1]), "r"(a[2]), "r"(a[3]), "r"(b[0]), "r"(b[1]));
}
// fast exp2 on the FMA pipe (y <= 0; clamp makes masked rows vanish)
__device__ __forceinline__ float fexp2(float y) {
    y = fmaxf(y, -126.f);
    float fl = floorf(y);
    float f = y - fl;
    float p = 1.8775767e-3f;
    p = fmaf(p, f, 8.9893397e-3f);
    p = fmaf(p, f, 5.5826318e-2f);
    p = fmaf(p, f, 2.4015361e-1f);
    p = fmaf(p, f, 6.9315308e-1f);
    p = fmaf(p, f, 9.9999994e-1f);
    return __int_as_float(((int)fl + 127) << 23) * p;
}
__device__ __forceinline__ uint32_t pack_bf2(float a, float b) {
    __nv_bfloat162 v = __floats2bfloat162_rn(a, b);
    return *reinterpret_cast<uint32_t*>(&v);
}
__device__ __forceinline__ uint32_t pack_bf2_res(float a, float b, uint32_t hi) {
    __nv_bfloat162 hv = *reinterpret_cast<__nv_bfloat162*>(&hi);
    return pack_bf2(a - __bfloat162float(hv.x), b - __bfloat162float(hv.y));
}

// ---------------------------------------------------------------------------
// Fused glue kernel: split X + tsplit {Wq,Wk,Wv,Wo} + RoPE table, one launch.
// Flat grid, block-uniform branch per segment.
// ---------------------------------------------------------------------------
constexpr int SPLIT_BLK = (Mn * Hn / 4) / 256;   // 16384
constexpr int TWQ_BLK = 16384;                    // (128,128)
constexpr int TWK_BLK = 4096;                     // (32,128)
constexpr int TWV_BLK = 4096;
constexpr int TWO_BLK = 16384;
constexpr int RT_BLK = 512;
constexpr int GLUE_BLKS =
    SPLIT_BLK + TWQ_BLK + TWK_BLK + TWV_BLK + TWO_BLK + RT_BLK; // 57856

__device__ __forceinline__ void tsplit_dev(
    const float* __restrict__ W, __nv_bfloat16* __restrict__ Thi,
    __nv_bfloat16* __restrict__ Tlo, int K, int N, int bx, int by, int tid)
{
    __shared__ float t[32][33];
    int tx = tid & 31, ty = tid >> 5;
#pragma unroll
    for (int i = 0; i < 4; i++) {
        int r = by * 32 + ty + i * 8;
        t[ty + i * 8][tx] = W[(size_t)r * N + bx * 32 + tx];
    }
    __syncthreads();
#pragma unroll
    for (int i = 0; i < 4; i++) {
        int n = bx * 32 + ty + i * 8;
        int k = by * 32 + tx;
        float v = t[tx][ty + i * 8];
        __nv_bfloat16 h = __float2bfloat16(v);
        __nv_bfloat16 l = __float2bfloat16(v - __bfloat162float(h));
        Thi[(size_t)n * K + k] = h;
        Tlo[(size_t)n * K + k] = l;
    }
}

__global__ __launch_bounds__(256) void glue_kernel(
    const float* __restrict__ X, const float* __restrict__ Wq,
    const float* __restrict__ Wk, const float* __restrict__ Wv,
    const float* __restrict__ Wo)
{
    int bid = blockIdx.x, tid = threadIdx.x;
    if (bid < SPLIT_BLK) {
        int i = bid * 256 + tid;
        float4 v = reinterpret_cast<const float4*>(X)[i];
        __nv_bfloat16 h0 = __float2bfloat16(v.x), h1 = __float2bfloat16(v.y);
        __nv_bfloat16 h2 = __float2bfloat16(v.z), h3 = __float2bfloat16(v.w);
        __nv_bfloat16 l0 = __float2bfloat16(v.x - __bfloat162float(h0));
        __nv_bfloat16 l1 = __float2bfloat16(v.y - __bfloat162float(h1));
        __nv_bfloat16 l2 = __float2bfloat16(v.z - __bfloat162float(h2));
        __nv_bfloat16 l3 = __float2bfloat16(v.w - __bfloat162float(h3));
        reinterpret_cast<__nv_bfloat162*>(g_Xhi)[i * 2 + 0] = __halves2bfloat162(h0, h1);
        reinterpret_cast<__nv_bfloat162*>(g_Xhi)[i * 2 + 1] = __halves2bfloat162(h2, h3);
        reinterpret_cast<__nv_bfloat162*>(g_Xlo)[i * 2 + 0] = __halves2bfloat162(l0, l1);
        reinterpret_cast<__nv_bfloat162*>(g_Xlo)[i * 2 + 1] = __halves2bfloat162(l2, l3);
        return;
    }
    bid -= SPLIT_BLK;
    if (bid < TWQ_BLK) {
        tsplit_dev(Wq, g_WqThi, g_WqTlo, Hn, 4096, bid & 127, bid >> 7, tid);
        return;
    }
    bid -= TWQ_BLK;
    if (bid < TWK_BLK) {
        tsplit_dev(Wk, g_WkThi, g_WkTlo, Hn, 1024, bid & 31, bid >> 5, tid);
        return;
    }
    bid -= TWK_BLK;
    if (bid < TWV_BLK) {
        tsplit_dev(Wv, g_WvThi, g_WvTlo, Hn, 1024, bid & 31, bid >> 5, tid);
        return;
    }
    bid -= TWV_BLK;
    if (bid < TWO_BLK) {
        tsplit_dev(Wo, g_WoThi, g_WoTlo, 4096, Hn, bid & 127, bid >> 7, tid);
        return;
    }
    bid -= TWO_BLK;
    {   // RoPE table
        int idx = bid * 256 + tid;      // Sn*64 = 131072
        int s = idx >> 6, d = idx & 63;
        float inv = powf(10000.f, -(float)d / 64.f);
        float sn, cs;
        sincosf((float)s * inv, &sn, &cs);
        g_RT[idx] = make_float2(cs, sn);
    }
}

// ---------------------------------------------------------------------------
// GEMM mainloop constants (3-stage cp.async pipeline)
// ---------------------------------------------------------------------------
constexpr int TROW = 144;
constexpr int TTILE = 128 * TROW;
constexpr int TSTAGE = 4 * TTILE;        // 73728 B
constexpr int HG_SMEM = 3 * TSTAGE;      // 221184 B

// ---------------------------------------------------------------------------
// Fused QKV projection GEMM: one launch, runtime mode decode.
//  bid <  1024 : Q (N=4096, RoPE+split, scale=QK_SCALE)
//  bid <  1280 : K (N=1024, RoPE+split, scale=1)
//  else        : V (N=1024, split only)
// ---------------------------------------------------------------------------
__global__ __launch_bounds__(256) void qkv_gemm_kernel()
{
    extern __shared__ char smem[];
    const uint32_t sb = smem_u32(smem);

    const int tid = threadIdx.x;
    const int wid = tid >> 5, lane = tid & 31;
    const int g = lane >> 2, t4 = lane & 3;
    const int wr = wid >> 2, wc = wid & 3;
    const int wm = wr * 64, wn = wc * 32;

    int bid = blockIdx.x;
    int mode, bx, by, N, heads;
    float scale;
    const __nv_bfloat16 *Bh, *Bl;
    __nv_bfloat16 *Oh, *Ol;
    if (bid < 1024) {
        mode = 1; bx = bid & 31; by = bid >> 5; N = 4096;
        Bh = g_WqThi; Bl = g_WqTlo; Oh = g_Qh; Ol = g_Ql;
        heads = NHn; scale = QK_SCALE;
    } else if (bid < 1280) {
        int l = bid - 1024;
        mode = 2; bx = l & 7; by = l >> 3; N = 1024;
        Bh = g_WkThi; Bl = g_WkTlo; Oh = g_Kh; Ol = g_Kl;
        heads = NKVn; scale = 1.f;
    } else {
        int l = bid - 1280;
        mode = 3; bx = l & 7; by = l >> 3; N = 1024;
        Bh = g_WvThi; Bl = g_WvTlo; Oh = g_Vh; Ol = g_Vl;
        heads = NKVn; scale = 1.f;
    }
    const int m0 = by * 128, n0 = bx * 128;
    const int K = Hn;

    const __nv_bfloat16* Ah = g_Xhi + (size_t)m0 * K;
    const __nv_bfloat16* Al = g_Xlo + (size_t)m0 * K;
    const __nv_bfloat16* Bhp = Bh + (size_t)n0 * K;
    const __nv_bfloat16* Blp = Bl + (size_t)n0 * K;

    float c[4][4][4];
#pragma unroll
    for (int mi = 0; mi < 4; mi++)
#pragma unroll
        for (int ni = 0; ni < 4; ni++)
#pragma unroll
            for (int r = 0; r < 4; r++) c[mi][ni][r] = 0.f;

    const int rb = tid >> 3;
    const int c8 = tid & 7;

    auto load_chunk = [&](int stage, int koff) {
        const uint32_t base = sb + stage * TSTAGE;
#pragma unroll
        for (int i = 0; i < 16; i++) {
            const int tile = i >> 2;
            const int r = (i & 3) * 32 + rb;
            const __nv_bfloat16* s =
                (tile == 0) ? Ah : (tile == 1) ? Al : (tile == 2) ? Bhp : Blp;
            cpa16(base + tile * TTILE + r * TROW + c8 * 16,
                  s + (size_t)r * K + koff + c8 * 8);
        }
        asm volatile("cp.async.commit_group;" ::: "memory");
    };

    const int NC = K / 64;
    load_chunk(0, 0);
    load_chunk(1, 64);

    const int arow_off = (lane & 7) + ((lane >> 3) & 1) * 8;
    const int acol_off = (lane >> 4) * 8;
    const int brow_off = (lane & 7) + (lane >> 4) * 8;
    const int bcol_off = ((lane >> 3) & 1) * 8;

    for (int ch = 0; ch < NC; ch++) {
        if (ch + 1 < NC)
            asm volatile("cp.async.wait_group 1;" ::: "memory");
        else
            asm volatile("cp.async.wait_group 0;" ::: "memory");
        __syncthreads();
        if (ch + 2 < NC) load_chunk((ch + 2) % 3, (ch + 2) * 64);

        const uint32_t st = sb + (ch % 3) * TSTAGE;
        const uint32_t ah_b = st, al_b = st + TTILE;
        const uint32_t bh_b = st + 2 * TTILE, bl_b = st + 3 * TTILE;

#pragma unroll
        for (int kk = 0; kk < 64; kk += 16) {
            uint32_t fah[4][4], fal[4][4], fbh[4][2], fbl[4][2];
#pragma unroll
            for (int mi = 0; mi < 4; mi++) {
                const uint32_t ro = (wm + mi * 16 + arow_off) * TROW +
                                    (kk + acol_off) * 2;
                ldsm4(fah[mi][0], fah[mi][1], fah[mi][2], fah[mi][3], ah_b + ro);
                ldsm4(fal[mi][0], fal[mi][1], fal[mi][2], fal[mi][3], al_b + ro);
            }
#pragma unroll
            for (int bt = 0; bt < 2; bt++) {
                const uint32_t ro = (wn + bt * 16 + brow_off) * TROW +
                                    (kk + bcol_off) * 2;
                ldsm4(fbh[2 * bt][0], fbh[2 * bt][1],
                      fbh[2 * bt + 1][0], fbh[2 * bt + 1][1], bh_b + ro);
                ldsm4(fbl[2 * bt][0], fbl[2 * bt][1],
                      fbl[2 * bt + 1][0], fbl[2 * bt + 1][1], bl_b + ro);
            }
#pragma unroll
            for (int mi = 0; mi < 4; mi++)
#pragma unroll
                for (int ni = 0; ni < 4; ni++) {
                    mma_bf16(c[mi][ni], fah[mi], fbh[ni]);
                    mma_bf16(c[mi][ni], fah[mi], fbl[ni]);
                    mma_bf16(c[mi][ni], fal[mi], fbh[ni]);
                }
        }
    }

    const int hh = n0 >> 7;
    if (mode == 3) {
        // split-only, KV layout (V projection)
#pragma unroll
        for (int mi = 0; mi < 4; mi++)
#pragma unroll
            for (int ni = 0; ni < 4; ni++) {
                const int row0 = m0 + wm + mi * 16 + g;
                const int col = wn + ni * 8 + 2 * t4;
#pragma unroll
                for (int half = 0; half < 2; half++) {
                    const int m = row0 + half * 8;
                    float v0 = half ? c[mi][ni][2] : c[mi][ni][0];
                    float v1 = half ? c[mi][ni][3] : c[mi][ni][1];
                    const int bb = m >> 11, s = m & 2047;
                    size_t base =
                        (((size_t)(bb * NKVn + hh) * Sn) + s) * HDn + col;
                    uint32_t hv = pack_bf2(v0, v1);
                    *reinterpret_cast<uint32_t*>(&Oh[base]) = hv;
                    *reinterpret_cast<uint32_t*>(&Ol[base]) =
                        pack_bf2_res(v0, v1, hv);
                }
            }
    } else {
        // Q/K: stage tile to smem, apply RoPE pairing (d, d+64), split.
        __syncthreads();    // stage 0 may still be read by last chunk's mma
        float* stg = reinterpret_cast<float*>(smem);
#pragma unroll
        for (int mi = 0; mi < 4; mi++)
#pragma unroll
            for (int ni = 0; ni < 4; ni++) {
                const int rl = wm + mi * 16 + g;
                const int cl = wn + ni * 8 + 2 * t4;
                stg[rl * 132 + cl] = c[mi][ni][0];
                stg[rl * 132 + cl + 1] = c[mi][ni][1];
                stg[(rl + 8) * 132 + cl] = c[mi][ni][2];
                stg[(rl + 8) * 132 + cl + 1] = c[mi][ni][3];
            }
        __syncthreads();
#pragma unroll
        for (int i = 0; i < 32; i++) {
            int p = tid + i * 256;          // 8192 pairs
            int r = p >> 6, d = p & 63;
            int m = m0 + r;
            int bb = m >> 11, s = m & 2047;
            float x0 = stg[r * 132 + d];
            float x1 = stg[r * 132 + d + 64];
            float2 t = g_RT[s * 64 + d];
            float r0 = (x0 * t.x - x1 * t.y) * scale;
            float r1 = (x1 * t.x + x0 * t.y) * scale;
            __nv_bfloat16 h0 = __float2bfloat16(r0);
            __nv_bfloat16 h1 = __float2bfloat16(r1);
            size_t base = (((size_t)(bb * heads + hh) * Sn) + s) * HDn;
            Oh[base + d] = h0;
            Oh[base + d + 64] = h1;
            Ol[base + d] = __float2bfloat16(r0 - __bfloat162float(h0));
            Ol[base + d + 64] = __float2bfloat16(r1 - __bfloat162float(h1));
        }
    }
}

// ---------------------------------------------------------------------------
// Output-projection GEMM (MODE 0 of the old template, unchanged math)
// ---------------------------------------------------------------------------
__global__ __launch_bounds__(256) void ogemm_kernel(float* __restrict__ C)
{
    extern __shared__ char smem[];
    const uint32_t sb = smem_u32(smem);

    const int tid = threadIdx.x;
    const int wid = tid >> 5, lane = tid & 31;
    const int g = lane >> 2, t4 = lane & 3;
    const int wr = wid >> 2, wc = wid & 3;
    const int wm = wr * 64, wn = wc * 32;
    const int m0 = blockIdx.y * 128, n0 = blockIdx.x * 128;
    const int N = 4096, K = Hn;

    const __nv_bfloat16* Ah = g_Xhi + (size_t)m0 * K;
    const __nv_bfloat16* Al = g_Xlo + (size_t)m0 * K;
    const __nv_bfloat16* Bhp = g_WoThi + (size_t)n0 * K;
    const __nv_bfloat16* Blp = g_WoTlo + (size_t)n0 * K;

    float c[4][4][4];
#pragma unroll
    for (int mi = 0; mi < 4; mi++)
#pragma unroll
        for (int ni = 0; ni < 4; ni++)
#pragma unroll
            for (int r = 0; r < 4; r++) c[mi][ni][r] = 0.f;

    const int rb = tid >> 3;
    const int c8 = tid & 7;

    auto load_chunk = [&](int stage, int koff) {
        const uint32_t base = sb + stage * TSTAGE;
#pragma unroll
        for (int i = 0; i < 16; i++) {
            const int tile = i >> 2;
            const int r = (i & 3) * 32 + rb;
            const __nv_bfloat16* s =
                (tile == 0) ? Ah : (tile == 1) ? Al : (tile == 2) ? Bhp : Blp;
            cpa16(base + tile * TTILE + r * TROW + c8 * 16,
                  s + (size_t)r * K + koff + c8 * 8);
        }
        asm volatile("cp.async.commit_group;" ::: "memory");
    };

    const int NC = K / 64;
    load_chunk(0, 0);
    load_chunk(1, 64);

    const int arow_off = (lane & 7) + ((lane >> 3) & 1) * 8;
    const int acol_off = (lane >> 4) * 8;
    const int brow_off = (lane & 7) + (lane >> 4) * 8;
    const int bcol_off = ((lane >> 3) & 1) * 8;

    for (int ch = 0; ch < NC; ch++) {
        if (ch + 1 < NC)
            asm volatile("cp.async.wait_group 1;" ::: "memory");
        else
            asm volatile("cp.async.wait_group 0;" ::: "memory");
        __syncthreads();
        if (ch + 2 < NC) load_chunk((ch + 2) % 3, (ch + 2) * 64);

        const uint32_t st = sb + (ch % 3) * TSTAGE;
        const uint32_t ah_b = st, al_b = st + TTILE;
        const uint32_t bh_b = st + 2 * TTILE, bl_b = st + 3 * TTILE;

#pragma unroll
        for (int kk = 0; kk < 64; kk += 16) {
            uint32_t fah[4][4], fal[4][4], fbh[4][2], fbl[4][2];
#pragma unroll
            for (int mi = 0; mi < 4; mi++) {
                const uint32_t ro = (wm + mi * 16 + arow_off) * TROW +
                                    (kk + acol_off) * 2;
                ldsm4(fah[mi][0], fah[mi][1], fah[mi][2], fah[mi][3], ah_b + ro);
                ldsm4(fal[mi][0], fal[mi][1], fal[mi][2], fal[mi][3], al_b + ro);
            }
#pragma unroll
            for (int bt = 0; bt < 2; bt++) {
                const uint32_t ro = (wn + bt * 16 + brow_off) * TROW +
                                    (kk + bcol_off) * 2;
                ldsm4(fbh[2 * bt][0], fbh[2 * bt][1],
                      fbh[2 * bt + 1][0], fbh[2 * bt + 1][1], bh_b + ro);
                ldsm4(fbl[2 * bt][0], fbl[2 * bt][1],
                      fbl[2 * bt + 1][0], fbl[2 * bt + 1][1], bl_b + ro);
            }
#pragma unroll
            for (int mi = 0; mi < 4; mi++)
#pragma unroll
                for (int ni = 0; ni < 4; ni++) {
                    mma_bf16(c[mi][ni], fah[mi], fbh[ni]);
                    mma_bf16(c[mi][ni], fah[mi], fbl[ni]);
                    mma_bf16(c[mi][ni], fal[mi], fbh[ni]);
                }
        }
    }

#pragma unroll
    for (int mi = 0; mi < 4; mi++)
#pragma unroll
        for (int ni = 0; ni < 4; ni++) {
            const int row0 = m0 + wm + mi * 16 + g;
            const int col = n0 + wn + ni * 8 + 2 * t4;
#pragma unroll
            for (int half = 0; half < 2; half++) {
                const int m = row0 + half * 8;
                float2 v = half ? make_float2(c[mi][ni][2], c[mi][ni][3])
                                : make_float2(c[mi][ni][0], c[mi][ni][1]);
                *reinterpret_cast<float2*>(&C[(size_t)m * N + col]) = v;
            }
        }
}

// ---------------------------------------------------------------------------
// Flash attention on mma.sync, bf16 split, BQ=128, BK=64, 8 warps,
// 3-stage cp.async pipeline. Output hi/lo bf16 into g_Xhi/g_Xlo.
// ---------------------------------------------------------------------------
constexpr int ARB = 272;                  // padded row bytes (136 bf16)
constexpr int KVT = 64 * ARB;             // one 64x128 bf16 tile = 17408 B
constexpr int ASTG = 4 * KVT;             // Kh,Kl,Vh,Vl per stage = 69632 B
constexpr int AT_SMEM = 3 * ASTG;         // 208896 B

__global__ __launch_bounds__(256, 1) void attn_mma_kernel()
{
    extern __shared__ char smem[];
    const uint32_t sb = smem_u32(smem);
    const int qt = blockIdx.x, h = blockIdx.y, b = blockIdx.z;
    const int tid = threadIdx.x, wid = tid >> 5, lane = tid & 31;
    const int g = lane >> 2, t4 = lane & 3;
    const int wm = wid * 16;
    const int kvh = h >> 2;
    const int NT = 2 * (qt + 1);

    const __nv_bfloat16* Qhp = g_Qh + ((size_t)(b * NHn + h) * Sn + qt * 128) * HDn;
    const __nv_bfloat16* Qlp = g_Ql + ((size_t)(b * NHn + h) * Sn + qt * 128) * HDn;
    const __nv_bfloat16* Khp = g_Kh + ((size_t)(b * NKVn + kvh) * Sn) * HDn;
    const __nv_bfloat16* Klp = g_Kl + ((size_t)(b * NKVn + kvh) * Sn) * HDn;
    const __nv_bfloat16* Vhp = g_Vh + ((size_t)(b * NKVn + kvh) * Sn) * HDn;
    const __nv_bfloat16* Vlp = g_Vl + ((size_t)(b * NKVn + kvh) * Sn) * HDn;

    const uint32_t qhb = sb + 2 * ASTG, qlb = sb + 2 * ASTG + 34816;
#pragma unroll
    for (int i = 0; i < 8; i++) {
        int id = tid + i * 256, r = id >> 4, c = id & 15;
        cpa16(qhb + r * ARB + c * 16, Qhp + r * HDn + c * 8);
        cpa16(qlb + r * ARB + c * 16, Qlp + r * HDn + c * 8);
    }
    asm volatile("cp.async.commit_group;" ::: "memory");

    auto load_stage = [&](int stg, int t) {
        const uint32_t st = sb + stg * ASTG;
        const __nv_bfloat16* kh = Khp + (size_t)t * 64 * HDn;
        const __nv_bfloat16* kl = Klp + (size_t)t * 64 * HDn;
        const __nv_bfloat16* vh = Vhp + (size_t)t * 64 * HDn;
        const __nv_bfloat16* vl = Vlp + (size_t)t * 64 * HDn;
#pragma unroll
        for (int i = 0; i < 4; i++) {
            int id = tid + i * 256, r = id >> 4, c = id & 15;
            cpa16(st + 0 * KVT + r * ARB + c * 16, kh + r * HDn + c * 8);
            cpa16(st + 1 * KVT + r * ARB + c * 16, kl + r * HDn + c * 8);
            cpa16(st + 2 * KVT + r * ARB + c * 16, vh + r * HDn + c * 8);
            cpa16(st + 3 * KVT + r * ARB + c * 16, vl + r * HDn + c * 8);
        }
        asm volatile("cp.async.commit_group;" ::: "memory");
    };
    load_stage(0, 0);

    asm volatile("cp.async.wait_group 1;" ::: "memory");  // Q arrived
    __syncthreads();

    const int arow = (lane & 7) + ((lane >> 3) & 1) * 8;
    const int acolB = (lane >> 4) * 16;
    uint32_t qhf[8][4], qlf[8][4];
#pragma unroll
    for (int ks = 0; ks < 8; ks++) {
        uint32_t ro = (wm + arow) * ARB + ks * 32 + acolB;
        ldsm4(qhf[ks][0], qhf[ks][1], qhf[ks][2], qhf[ks][3], qhb + ro);
        ldsm4(qlf[ks][0], qlf[ks][1], qlf[ks][2], qlf[ks][3], qlb + ro);
    }
    __syncthreads();
    if (1 < NT) load_stage(1, 1);

    float o[16][4];
#pragma unroll
    for (int j = 0; j < 16; j++)
#pragma unroll
        for (int e = 0; e < 4; e++) o[j][e] = 0.f;
    float m0 = -1e30f, m1 = -1e30f, l0 = 0.f, l1 = 0.f;

    const int brow = (lane & 7) + (lane >> 4) * 8;
    const int bcolB = ((lane >> 3) & 1) * 16;
    const int vcolB = (lane >> 4) * 16;
    const int row0g = qt * 128 + wm + g;

    for (int t = 0; t < NT; t++) {
        if (t + 1 < NT)
            asm volatile("cp.async.wait_group 1;" ::: "memory");
        else
            asm volatile("cp.async.wait_group 0;" ::: "memory");
        __syncthreads();
        if (t + 2 < NT) load_stage((t + 2) % 3, t + 2);
        const uint32_t st = sb + (t % 3) * ASTG;

        float s[8][4];
#pragma unroll
        for (int j = 0; j < 8; j++)
#pragma unroll
            for (int e = 0; e < 4; e++) s[j][e] = 0.f;

#pragma unroll
        for (int ks = 0; ks < 8; ks++) {
#pragma unroll
            for (int gr = 0; gr < 4; gr++) {
                uint32_t kh4[4], kl4[4];
                uint32_t ro = st + (gr * 16 + brow) * ARB + ks * 32 + bcolB;
                ldsm4(kh4[0], kh4[1], kh4[2], kh4[3], ro);
                ldsm4(kl4[0], kl4[1], kl4[2], kl4[3], ro + KVT);
                mma_bf16(s[2 * gr], qhf[ks], kh4);
                mma_bf16(s[2 * gr], qhf[ks], kl4);
                mma_bf16(s[2 * gr], qlf[ks], kh4);
                mma_bf16(s[2 * gr + 1], qhf[ks], kh4 + 2);
                mma_bf16(s[2 * gr + 1], qhf[ks], kl4 + 2);
                mma_bf16(s[2 * gr + 1], qlf[ks], kh4 + 2);
            }
        }

        if (t >= 2 * qt) {
#pragma unroll
            for (int j = 0; j < 8; j++) {
                int c0 = t * 64 + j * 8 + 2 * t4;
                if (c0 > row0g)     s[j][0] = -1e30f;
                if (c0 + 1 > row0g) s[j][1] = -1e30f;
                if (c0 > row0g + 8)     s[j][2] = -1e30f;
                if (c0 + 1 > row0g + 8) s[j][3] = -1e30f;
            }
        }

        float tm0 = -1e30f, tm1 = -1e30f;
#pragma unroll
        for (int j = 0; j < 8; j++) {
            tm0 = fmaxf(tm0, fmaxf(s[j][0], s[j][1]));
            tm1 = fmaxf(tm1, fmaxf(s[j][2], s[j][3]));
        }
        tm0 = fmaxf(tm0, __shfl_xor_sync(0xffffffffu, tm0, 1));
        tm0 = fmaxf(tm0, __shfl_xor_sync(0xffffffffu, tm0, 2));
        tm1 = fmaxf(tm1, __shfl_xor_sync(0xffffffffu, tm1, 1));
        tm1 = fmaxf(tm1, __shfl_xor_sync(0xffffffffu, tm1, 2));
        float mn0 = fmaxf(m0, tm0), mn1 = fmaxf(m1, tm1);
        float cor0 = fexp2((m0 - mn0) * L2E);
        float cor1 = fexp2((m1 - mn1) * L2E);
        m0 = mn0; m1 = mn1;
#pragma unroll
        for (int j = 0; j < 16; j++) {
            o[j][0] *= cor0; o[j][1] *= cor0;
            o[j][2] *= cor1; o[j][3] *= cor1;
        }
        float rs0 = 0.f, rs1 = 0.f;
#pragma unroll
        for (int j = 0; j < 8; j++) {
            s[j][0] = fexp2((s[j][0] - mn0) * L2E);
            s[j][1] = fexp2((s[j][1] - mn0) * L2E);
            s[j][2] = fexp2((s[j][2] - mn1) * L2E);
            s[j][3] = fexp2((s[j][3] - mn1) * L2E);
            rs0 += s[j][0] + s[j][1];
            rs1 += s[j][2] + s[j][3];
        }
        rs0 += __shfl_xor_sync(0xffffffffu, rs0, 1);
        rs0 += __shfl_xor_sync(0xffffffffu, rs0, 2);
        rs1 += __shfl_xor_sync(0xffffffffu, rs1, 1);
        rs1 += __shfl_xor_sync(0xffffffffu, rs1, 2);
        l0 = l0 * cor0 + rs0;
        l1 = l1 * cor1 + rs1;

#pragma unroll
        for (int ks = 0; ks < 4; ks++) {
            uint32_t pha[4], pla[4];
            pha[0] = pack_bf2(s[2 * ks][0], s[2 * ks][1]);
            pha[1] = pack_bf2(s[2 * ks][2], s[2 * ks][3]);
            pha[2] = pack_bf2(s[2 * ks + 1][0], s[2 * ks + 1][1]);
            pha[3] = pack_bf2(s[2 * ks + 1][2], s[2 * ks + 1][3]);
            pla[0] = pack_bf2_res(s[2 * ks][0], s[2 * ks][1], pha[0]);
            pla[1] = pack_bf2_res(s[2 * ks][2], s[2 * ks][3], pha[1]);
            pla[2] = pack_bf2_res(s[2 * ks + 1][0], s[2 * ks + 1][1], pha[2]);
            pla[3] = pack_bf2_res(s[2 * ks + 1][2], s[2 * ks + 1][3], pha[3]);
#pragma unroll
            for (int gr = 0; gr < 8; gr++) {
                uint32_t vh4[4], vl4[4];
                uint32_t ro = st + 2 * KVT + (ks * 16 + arow) * ARB +
                              gr * 32 + vcolB;
                ldsm4t(vh4[0], vh4[1], vh4[2], vh4[3], ro);
                ldsm4t(vl4[0], vl4[1], vl4[2], vl4[3], ro + KVT);
                mma_bf16(o[2 * gr], pha, vh4);
                mma_bf16(o[2 * gr], pha, vl4);
                mma_bf16(o[2 * gr], pla, vh4);
                mma_bf16(o[2 * gr + 1], pha, vh4 + 2);
                mma_bf16(o[2 * gr + 1], pha, vl4 + 2);
                mma_bf16(o[2 * gr + 1], pla, vh4 + 2);
            }
        }
    }

    float inv0 = 1.f / l0, inv1 = 1.f / l1;
    const int r0 = qt * 128 + wm + g, r1 = r0 + 8;
#pragma unroll
    for (int j = 0; j < 16; j++) {
        int col = h * 128 + j * 8 + 2 * t4;
        float a0 = o[j][0] * inv0, a1 = o[j][1] * inv0;
        float b0 = o[j][2] * inv1, b1 = o[j][3] * inv1;
        size_t i0 = ((size_t)(b * Sn + r0)) * 4096 + col;
        size_t i1 = ((size_t)(b * Sn + r1)) * 4096 + col;
        uint32_t h0 = pack_bf2(a0, a1);
        uint32_t h1 = pack_bf2(b0, b1);
        *reinterpret_cast<uint32_t*>(&g_Xhi[i0]) = h0;
        *reinterpret_cast<uint32_t*>(&g_Xlo[i0]) = pack_bf2_res(a0, a1, h0);
        *reinterpret_cast<uint32_t*>(&g_Xhi[i1]) = h1;
        *reinterpret_cast<uint32_t*>(&g_Xlo[i1]) = pack_bf2_res(b0, b1, h1);
    }
}

// ---------------------------------------------------------------------------
extern "C" void kernel_launch(void* const* d_in, const int* in_sizes, int n_in,
                              void* d_out, int out_size)
{
    const float* hidden = (const float*)d_in[0];
    const float* Wq = (const float*)d_in[2];
    const float* Wk = (const float*)d_in[3];
    const float* Wv = (const float*)d_in[4];
    const float* Wo = (const float*)d_in[5];
    float* out = (float*)d_out;

    cudaFuncSetAttribute(qkv_gemm_kernel,
                         cudaFuncAttributeMaxDynamicSharedMemorySize, HG_SMEM);
    cudaFuncSetAttribute(ogemm_kernel,
                         cudaFuncAttributeMaxDynamicSharedMemorySize, HG_SMEM);
    cudaFuncSetAttribute(attn_mma_kernel,
                         cudaFuncAttributeMaxDynamicSharedMemorySize, AT_SMEM);

    // 1) all conversions + RoPE table, one launch
    glue_kernel<<<GLUE_BLKS, 256>>>(hidden, Wq, Wk, Wv, Wo);

    // 2) Q/K/V projections with fused RoPE/split epilogues, one launch
    qkv_gemm_kernel<<<1536, 256, HG_SMEM>>>();

    // 3) causal flash attention (writes hi/lo into g_Xhi/g_Xlo)
    dim3 ga(Sn / 128, NHn, Bn);
    attn_mma_kernel<<<ga, 256, AT_SMEM>>>();

    // 4) output projection (4th launch = ncu capture slot)
    ogemm_kernel<<<dim3(32, 32), 256, HG_SMEM>>>(out);
}

// round 10
// speedup vs baseline: 1.7304x; 1.7304x over previous
#include <cuda_runtime.h>
#include <cuda_bf16.h>
#include <math.h>
#include <stdint.h>

// Problem dims
constexpr int Bn = 2, Sn = 2048, Hn = 4096, NHn = 32, NKVn = 8, HDn = 128;
constexpr int Mn = Bn * Sn;
constexpr float QK_SCALE = 0.08838834764831845f; // 1/sqrt(128)
constexpr float L2E = 1.4426950408889634f;

// fp32 scratch
__device__ float g_Q[(size_t)Bn * NHn * Sn * HDn];   // [b][h][s][d]
__device__ float g_K[(size_t)Bn * NKVn * Sn * HDn];  // [b][kh][s][d]
__device__ float g_V[(size_t)Bn * NKVn * Sn * HDn];
__device__ float g_A[(size_t)Bn * Sn * NHn * HDn];   // [b][s][h*d]

// bf16 split scratch
__device__ __nv_bfloat16 g_Xhi[(size_t)Mn * Hn];
__device__ __nv_bfloat16 g_Xlo[(size_t)Mn * Hn];
__device__ __nv_bfloat16 g_WqThi[(size_t)4096 * 4096];
__device__ __nv_bfloat16 g_WqTlo[(size_t)4096 * 4096];
__device__ __nv_bfloat16 g_WkThi[(size_t)1024 * 4096];
__device__ __nv_bfloat16 g_WkTlo[(size_t)1024 * 4096];
__device__ __nv_bfloat16 g_WvThi[(size_t)1024 * 4096];
__device__ __nv_bfloat16 g_WvTlo[(size_t)1024 * 4096];
__device__ __nv_bfloat16 g_WoThi[(size_t)4096 * 4096];
__device__ __nv_bfloat16 g_WoTlo[(size_t)4096 * 4096];
// attention operands (hi/lo, post-RoPE)
__device__ __nv_bfloat16 g_Qh[(size_t)Bn * NHn * Sn * HDn];
__device__ __nv_bfloat16 g_Ql[(size_t)Bn * NHn * Sn * HDn];
__device__ __nv_bfloat16 g_Kh[(size_t)Bn * NKVn * Sn * HDn];
__device__ __nv_bfloat16 g_Kl[(size_t)Bn * NKVn * Sn * HDn];
__device__ __nv_bfloat16 g_Vh[(size_t)Bn * NKVn * Sn * HDn];
__device__ __nv_bfloat16 g_Vl[(size_t)Bn * NKVn * Sn * HDn];

// ---------------------------------------------------------------------------
// helpers
// ---------------------------------------------------------------------------
__device__ __forceinline__ uint32_t smem_u32(const void* p) {
    uint32_t a;
    asm("{ .reg .u64 t; cvta.to.shared.u64 t, %1; cvt.u32.u64 %0, t; }"
        : "=r"(a) : "l"(p));
    return a;
}
__device__ __forceinline__ void cpa16(uint32_t dst, const void* src) {
    asm volatile("cp.async.cg.shared.global [%0], [%1], 16;"
                 :: "r"(dst), "l"(src) : "memory");
}
__device__ __forceinline__ void ldsm4(uint32_t& r0, uint32_t& r1,
                                      uint32_t& r2, uint32_t& r3, uint32_t a) {
    asm volatile("ldmatrix.sync.aligned.m8n8.x4.shared.b16 {%0,%1,%2,%3}, [%4];"
                 : "=r"(r0), "=r"(r1), "=r"(r2), "=r"(r3) : "r"(a));
}
__device__ __forceinline__ void ldsm4t(uint32_t& r0, uint32_t& r1,
                                       uint32_t& r2, uint32_t& r3, uint32_t a) {
    asm volatile("ldmatrix.sync.aligned.m8n8.x4.trans.shared.b16 {%0,%1,%2,%3}, [%4];"
                 : "=r"(r0), "=r"(r1), "=r"(r2), "=r"(r3) : "r"(a));
}
__device__ __forceinline__ void mma_bf16(float* c, const uint32_t* a,
                                         const uint32_t* b) {
    asm volatile(
        "mma.sync.aligned.m16n8k16.row.col.f32.bf16.bf16.f32 "
        "{%0,%1,%2,%3}, {%4,%5,%6,%7}, {%8,%9}, {%0,%1,%2,%3};"
        : "+f"(c[0]), "+f"(c[1]), "+f"(c[2]), "+f"(c[3])
        : "r"(a[0]), "r"(a[1]), "r"(a[2]), "r"(a[3]), "r"(b[0]), "r"(b[1]));
}
// fast exp2 on the FMA pipe (y <= 0; clamp makes masked rows vanish)
__device__ __forceinline__ float fexp2(float y) {
    y = fmaxf(y, -126.f);
    float fl = floorf(y);
    float f = y - fl;
    float p = 1.8775767e-3f;
    p = fmaf(p, f, 8.9893397e-3f);
    p = fmaf(p, f, 5.5826318e-2f);
    p = fmaf(p, f, 2.4015361e-1f);
    p = fmaf(p, f, 6.9315308e-1f);
    p = fmaf(p, f, 9.9999994e-1f);
    return __int_as_float(((int)fl + 127) << 23) * p;
}
__device__ __forceinline__ uint32_t pack_bf2(float a, float b) {
    __nv_bfloat162 v = __floats2bfloat162_rn(a, b);
    return *reinterpret_cast<uint32_t*>(&v);
}
__device__ __forceinline__ uint32_t pack_bf2_res(float a, float b, uint32_t hi) {
    __nv_bfloat162 hv = *reinterpret_cast<__nv_bfloat162*>(&hi);
    return pack_bf2(a - __bfloat162float(hv.x), b - __bfloat162float(hv.y));
}

// ---------------------------------------------------------------------------
// Split conversion: x -> (hi, lo) bf16
// ---------------------------------------------------------------------------
__global__ void split_kernel(const float* __restrict__ x,
                             __nv_bfloat16* __restrict__ hi,
                             __nv_bfloat16* __restrict__ lo, int n4)
{
    int i = blockIdx.x * 256 + threadIdx.x;
    if (i >= n4) return;
    float4 v = reinterpret_cast<const float4*>(x)[i];
    __nv_bfloat16 h0 = __float2bfloat16(v.x), h1 = __float2bfloat16(v.y);
    __nv_bfloat16 h2 = __float2bfloat16(v.z), h3 = __float2bfloat16(v.w);
    __nv_bfloat16 l0 = __float2bfloat16(v.x - __bfloat162float(h0));
    __nv_bfloat16 l1 = __float2bfloat16(v.y - __bfloat162float(h1));
    __nv_bfloat16 l2 = __float2bfloat16(v.z - __bfloat162float(h2));
    __nv_bfloat16 l3 = __float2bfloat16(v.w - __bfloat162float(h3));
    reinterpret_cast<__nv_bfloat162*>(hi)[i * 2 + 0] = __halves2bfloat162(h0, h1);
    reinterpret_cast<__nv_bfloat162*>(hi)[i * 2 + 1] = __halves2bfloat162(h2, h3);
    reinterpret_cast<__nv_bfloat162*>(lo)[i * 2 + 0] = __halves2bfloat162(l0, l1);
    reinterpret_cast<__nv_bfloat162*>(lo)[i * 2 + 1] = __halves2bfloat162(l2, l3);
}

// ---------------------------------------------------------------------------
// Transpose + split: W[K][N] fp32 -> T{hi,lo}[N][K] bf16
// ---------------------------------------------------------------------------
__global__ void tsplit_kernel(const float* __restrict__ W,
                              __nv_bfloat16* __restrict__ Thi,
                              __nv_bfloat16* __restrict__ Tlo, int K, int N)
{
    __shared__ float t[32][33];
    int tx = threadIdx.x, ty = threadIdx.y;
    int bx = blockIdx.x, by = blockIdx.y;
#pragma unroll
    for (int i = 0; i < 4; i++) {
        int r = by * 32 + ty + i * 8;
        t[ty + i * 8][tx] = W[(size_t)r * N + bx * 32 + tx];
    }
    __syncthreads();
#pragma unroll
    for (int i = 0; i < 4; i++) {
        int n = bx * 32 + ty + i * 8;
        int k = by * 32 + tx;
        float v = t[tx][ty + i * 8];
        __nv_bfloat16 h = __float2bfloat16(v);
        __nv_bfloat16 l = __float2bfloat16(v - __bfloat162float(h));
        Thi[(size_t)n * K + k] = h;
        Tlo[(size_t)n * K + k] = l;
    }
}

// ---------------------------------------------------------------------------
// RoPE + hi/lo split (+ optional scale), [bh][s][128] layout, pos == s.
// ---------------------------------------------------------------------------
__global__ void rope_split_kernel(const float* __restrict__ X,
                                  __nv_bfloat16* __restrict__ H,
                                  __nv_bfloat16* __restrict__ L,
                                  int total, float scale)
{
    int idx = blockIdx.x * 256 + threadIdx.x;
    if (idx >= total) return;
    int d = idx & 63;
    int s = (idx >> 6) & (Sn - 1);
    int bh = idx >> 17;
    float inv = powf(10000.f, -(float)d / 64.f);
    float ang = (float)s * inv;
    float sn, cs;
    sincosf(ang, &sn, &cs);
    size_t base = ((size_t)bh * Sn + s) * HDn;
    float x0 = X[base + d];
    float x1 = X[base + d + 64];
    float r0 = (x0 * cs - x1 * sn) * scale;
    float r1 = (x1 * cs + x0 * sn) * scale;
    __nv_bfloat16 h0 = __float2bfloat16(r0);
    __nv_bfloat16 h1 = __float2bfloat16(r1);
    H[base + d] = h0;
    H[base + d + 64] = h1;
    L[base + d] = __float2bfloat16(r0 - __bfloat162float(h0));
    L[base + d + 64] = __float2bfloat16(r1 - __bfloat162float(h1));
}

// ---------------------------------------------------------------------------
// bf16 split GEMM on mma.sync: CTA tile 256(M) x 128(N), K-chunk 64,
// 2-stage cp.async pipeline. 8 warps as 4(M) x 2(N) -> warp tile 64x64.
// 25% less smem-load traffic per FLOP vs 128x128 (L2-BW-bound regime).
// MODE 0: C row-major fp32; MODE 1: Q layout fp32; MODE 2: KV layout fp32.
// ---------------------------------------------------------------------------
constexpr int TROW = 144;
constexpr int TTILE_A = 256 * TROW;       // 36864 B
constexpr int TTILE_B = 128 * TROW;       // 18432 B
constexpr int TSTAGE = 2 * TTILE_A + 2 * TTILE_B;  // 110592 B
constexpr int HG_SMEM = 2 * TSTAGE;       // 221184 B

template <int MODE>
__global__ __launch_bounds__(256) void hgemm_kernel(
    const __nv_bfloat16* __restrict__ Ahi, const __nv_bfloat16* __restrict__ Alo,
    const __nv_bfloat16* __restrict__ Bhi, const __nv_bfloat16* __restrict__ Blo,
    float* __restrict__ C, int N, int K)
{
    extern __shared__ char smem[];
    const uint32_t sb = smem_u32(smem);

    const int tid = threadIdx.x;
    const int wid = tid >> 5, lane = tid & 31;
    const int g = lane >> 2, t4 = lane & 3;
    const int wr = wid >> 1, wc = wid & 1;     // 4 x 2 warp grid
    const int wm = wr * 64, wn = wc * 64;
    const int m0 = blockIdx.y * 256, n0 = blockIdx.x * 128;

    const __nv_bfloat16* Ah = Ahi + (size_t)m0 * K;
    const __nv_bfloat16* Al = Alo + (size_t)m0 * K;
    const __nv_bfloat16* Bh = Bhi + (size_t)n0 * K;
    const __nv_bfloat16* Bl = Blo + (size_t)n0 * K;

    float c[4][8][4];
#pragma unroll
    for (int mi = 0; mi < 4; mi++)
#pragma unroll
        for (int ni = 0; ni < 8; ni++)
#pragma unroll
            for (int r = 0; r < 4; r++) c[mi][ni][r] = 0.f;

    const int rb = tid >> 3;          // 0..31
    const int c8 = tid & 7;           // 16B chunk within 128B row

    auto load_chunk = [&](int stage, int koff) {
        const uint32_t base = sb + stage * TSTAGE;
        // A tiles: 256 rows (hi + lo)
#pragma unroll
        for (int i = 0; i < 8; i++) {
            const int r = i * 32 + rb;
            cpa16(base + r * TROW + c8 * 16,
                  Ah + (size_t)r * K + koff + c8 * 8);
            cpa16(base + TTILE_A + r * TROW + c8 * 16,
                  Al + (size_t)r * K + koff + c8 * 8);
        }
        // B tiles: 128 rows (hi + lo)
#pragma unroll
        for (int i = 0; i < 4; i++) {
            const int r = i * 32 + rb;
            cpa16(base + 2 * TTILE_A + r * TROW + c8 * 16,
                  Bh + (size_t)r * K + koff + c8 * 8);
            cpa16(base + 2 * TTILE_A + TTILE_B + r * TROW + c8 * 16,
                  Bl + (size_t)r * K + koff + c8 * 8);
        }
        asm volatile("cp.async.commit_group;" ::: "memory");
    };

    const int NC = K / 64;
    load_chunk(0, 0);
    if (NC > 1) load_chunk(1, 64);

    const int arow_off = (lane & 7) + ((lane >> 3) & 1) * 8;
    const int acol_off = (lane >> 4) * 8;
    const int brow_off = (lane & 7) + (lane >> 4) * 8;
    const int bcol_off = ((lane >> 3) & 1) * 8;

    for (int ch = 0; ch < NC; ch++) {
        if (ch + 1 < NC)
            asm volatile("cp.async.wait_group 1;" ::: "memory");
        else
            asm volatile("cp.async.wait_group 0;" ::: "memory");
        __syncthreads();

        const uint32_t st = sb + (ch & 1) * TSTAGE;
        const uint32_t ah_b = st, al_b = st + TTILE_A;
        const uint32_t bh_b = st + 2 * TTILE_A;
        const uint32_t bl_b = st + 2 * TTILE_A + TTILE_B;

#pragma unroll
        for (int kk = 0; kk < 64; kk += 16) {
            uint32_t fah[4][4], fal[4][4], fbh[8][2], fbl[8][2];
#pragma unroll
            for (int mi = 0; mi < 4; mi++) {
                const uint32_t ro = (wm + mi * 16 + arow_off) * TROW +
                                    (kk + acol_off) * 2;
                ldsm4(fah[mi][0], fah[mi][1], fah[mi][2], fah[mi][3], ah_b + ro);
                ldsm4(fal[mi][0], fal[mi][1], fal[mi][2], fal[mi][3], al_b + ro);
            }
#pragma unroll
            for (int bt = 0; bt < 4; bt++) {
                const uint32_t ro = (wn + bt * 16 + brow_off) * TROW +
                                    (kk + bcol_off) * 2;
                ldsm4(fbh[2 * bt][0], fbh[2 * bt][1],
                      fbh[2 * bt + 1][0], fbh[2 * bt + 1][1], bh_b + ro);
                ldsm4(fbl[2 * bt][0], fbl[2 * bt][1],
                      fbl[2 * bt + 1][0], fbl[2 * bt + 1][1], bl_b + ro);
            }
#pragma unroll
            for (int mi = 0; mi < 4; mi++)
#pragma unroll
                for (int ni = 0; ni < 8; ni++) {
                    mma_bf16(c[mi][ni], fah[mi], fbh[ni]);
                    mma_bf16(c[mi][ni], fah[mi], fbl[ni]);
                    mma_bf16(c[mi][ni], fal[mi], fbh[ni]);
                }
        }
        __syncthreads();
        if (ch + 2 < NC) load_chunk(ch & 1, (ch + 2) * 64);
    }

    // Epilogue (fragment (g,2t4) layout; halves at +8 rows)
#pragma unroll
    for (int mi = 0; mi < 4; mi++) {
#pragma unroll
        for (int ni = 0; ni < 8; ni++) {
            const int row0 = m0 + wm + mi * 16 + g;
            const int col = n0 + wn + ni * 8 + 2 * t4;
#pragma unroll
            for (int half = 0; half < 2; half++) {
                const int m = row0 + half * 8;
                float2 v = half ? make_float2(c[mi][ni][2], c[mi][ni][3])
                                : make_float2(c[mi][ni][0], c[mi][ni][1]);
                if (MODE == 0) {
                    *reinterpret_cast<float2*>(&C[(size_t)m * N + col]) = v;
                } else if (MODE == 1) {
                    int b = m >> 11, s = m & 2047;
                    int h = col >> 7, d = col & 127;
                    *reinterpret_cast<float2*>(
                        &C[(((size_t)(b * NHn + h) * Sn) + s) * HDn + d]) = v;
                } else {
                    int b = m >> 11, s = m & 2047;
                    int h = col >> 7, d = col & 127;
                    *reinterpret_cast<float2*>(
                        &C[(((size_t)(b * NKVn + h) * Sn) + s) * HDn + d]) = v;
                }
            }
        }
    }
}

// ---------------------------------------------------------------------------
// Flash attention on mma.sync, bf16 split, BQ=128, BK=64, 8 warps,
// 2-stage pipeline (round-6 proven version, verbatim).
// ---------------------------------------------------------------------------
constexpr int ARB = 272;                  // padded row bytes (136 bf16)
constexpr int KVT = 64 * ARB;             // one 64x128 bf16 tile = 17408 B
constexpr int ASTG = 4 * KVT;             // Kh,Kl,Vh,Vl per stage = 69632 B
constexpr int AT_SMEM = 2 * ASTG;         // 139264 B

__global__ __launch_bounds__(256, 1) void attn_mma_kernel()
{
    extern __shared__ char smem[];
    const uint32_t sb = smem_u32(smem);
    const int qt = blockIdx.x, h = blockIdx.y, b = blockIdx.z;
    const int tid = threadIdx.x, wid = tid >> 5, lane = tid & 31;
    const int g = lane >> 2, t4 = lane & 3;
    const int wm = wid * 16;
    const int kvh = h >> 2;
    const int NT = 2 * (qt + 1);

    const __nv_bfloat16* Qhp = g_Qh + ((size_t)(b * NHn + h) * Sn + qt * 128) * HDn;
    const __nv_bfloat16* Qlp = g_Ql + ((size_t)(b * NHn + h) * Sn + qt * 128) * HDn;
    const __nv_bfloat16* Khp = g_Kh + ((size_t)(b * NKVn + kvh) * Sn) * HDn;
    const __nv_bfloat16* Klp = g_Kl + ((size_t)(b * NKVn + kvh) * Sn) * HDn;
    const __nv_bfloat16* Vhp = g_Vh + ((size_t)(b * NKVn + kvh) * Sn) * HDn;
    const __nv_bfloat16* Vlp = g_Vl + ((size_t)(b * NKVn + kvh) * Sn) * HDn;

    const uint32_t qhb = sb + ASTG, qlb = sb + ASTG + 34816;
#pragma unroll
    for (int i = 0; i < 8; i++) {
        int id = tid + i * 256, r = id >> 4, c = id & 15;
        cpa16(qhb + r * ARB + c * 16, Qhp + r * HDn + c * 8);
        cpa16(qlb + r * ARB + c * 16, Qlp + r * HDn + c * 8);
    }
    asm volatile("cp.async.commit_group;" ::: "memory");

    auto load_stage = [&](int stg, int t) {
        const uint32_t st = sb + stg * ASTG;
        const __nv_bfloat16* kh = Khp + (size_t)t * 64 * HDn;
        const __nv_bfloat16* kl = Klp + (size_t)t * 64 * HDn;
        const __nv_bfloat16* vh = Vhp + (size_t)t * 64 * HDn;
        const __nv_bfloat16* vl = Vlp + (size_t)t * 64 * HDn;
#pragma unroll
        for (int i = 0; i < 4; i++) {
            int id = tid + i * 256, r = id >> 4, c = id & 15;
            cpa16(st + 0 * KVT + r * ARB + c * 16, kh + r * HDn + c * 8);
            cpa16(st + 1 * KVT + r * ARB + c * 16, kl + r * HDn + c * 8);
            cpa16(st + 2 * KVT + r * ARB + c * 16, vh + r * HDn + c * 8);
            cpa16(st + 3 * KVT + r * ARB + c * 16, vl + r * HDn + c * 8);
        }
        asm volatile("cp.async.commit_group;" ::: "memory");
    };
    load_stage(0, 0);

    asm volatile("cp.async.wait_group 1;" ::: "memory");  // Q arrived
    __syncthreads();

    const int arow = (lane & 7) + ((lane >> 3) & 1) * 8;
    const int acolB = (lane >> 4) * 16;
    uint32_t qhf[8][4], qlf[8][4];
#pragma unroll
    for (int ks = 0; ks < 8; ks++) {
        uint32_t ro = (wm + arow) * ARB + ks * 32 + acolB;
        ldsm4(qhf[ks][0], qhf[ks][1], qhf[ks][2], qhf[ks][3], qhb + ro);
        ldsm4(qlf[ks][0], qlf[ks][1], qlf[ks][2], qlf[ks][3], qlb + ro);
    }
    __syncthreads();
    load_stage(1, 1);

    float o[16][4];
#pragma unroll
    for (int j = 0; j < 16; j++)
#pragma unroll
        for (int e = 0; e < 4; e++) o[j][e] = 0.f;
    float m0 = -1e30f, m1 = -1e30f, l0 = 0.f, l1 = 0.f;

    const int brow = (lane & 7) + (lane >> 4) * 8;
    const int bcolB = ((lane >> 3) & 1) * 16;
    const int vcolB = (lane >> 4) * 16;
    const int row0g = qt * 128 + wm + g;

    for (int t = 0; t < NT; t++) {
        if (t + 1 < NT)
            asm volatile("cp.async.wait_group 1;" ::: "memory");
        else
            asm volatile("cp.async.wait_group 0;" ::: "memory");
        __syncthreads();
        const uint32_t st = sb + (t & 1) * ASTG;

        float s[8][4];
#pragma unroll
        for (int j = 0; j < 8; j++)
#pragma unroll
            for (int e = 0; e < 4; e++) s[j][e] = 0.f;

#pragma unroll
        for (int ks = 0; ks < 8; ks++) {
#pragma unroll
            for (int gr = 0; gr < 4; gr++) {
                uint32_t kh4[4], kl4[4];
                uint32_t ro = st + (gr * 16 + brow) * ARB + ks * 32 + bcolB;
                ldsm4(kh4[0], kh4[1], kh4[2], kh4[3], ro);
                ldsm4(kl4[0], kl4[1], kl4[2], kl4[3], ro + KVT);
                mma_bf16(s[2 * gr], qhf[ks], kh4);
                mma_bf16(s[2 * gr], qhf[ks], kl4);
                mma_bf16(s[2 * gr], qlf[ks], kh4);
                mma_bf16(s[2 * gr + 1], qhf[ks], kh4 + 2);
                mma_bf16(s[2 * gr + 1], qhf[ks], kl4 + 2);
                mma_bf16(s[2 * gr + 1], qlf[ks], kh4 + 2);
            }
        }

        if (t >= 2 * qt) {
#pragma unroll
            for (int j = 0; j < 8; j++) {
                int c0 = t * 64 + j * 8 + 2 * t4;
                if (c0 > row0g)     s[j][0] = -1e30f;
                if (c0 + 1 > row0g) s[j][1] = -1e30f;
                if (c0 > row0g + 8)     s[j][2] = -1e30f;
                if (c0 + 1 > row0g + 8) s[j][3] = -1e30f;
            }
        }

        float tm0 = -1e30f, tm1 = -1e30f;
#pragma unroll
        for (int j = 0; j < 8; j++) {
            tm0 = fmaxf(tm0, fmaxf(s[j][0], s[j][1]));
            tm1 = fmaxf(tm1, fmaxf(s[j][2], s[j][3]));
        }
        tm0 = fmaxf(tm0, __shfl_xor_sync(0xffffffffu, tm0, 1));
        tm0 = fmaxf(tm0, __shfl_xor_sync(0xffffffffu, tm0, 2));
        tm1 = fmaxf(tm1, __shfl_xor_sync(0xffffffffu, tm1, 1));
        tm1 = fmaxf(tm1, __shfl_xor_sync(0xffffffffu, tm1, 2));
        float mn0 = fmaxf(m0, tm0), mn1 = fmaxf(m1, tm1);
        float cor0 = fexp2((m0 - mn0) * L2E);
        float cor1 = fexp2((m1 - mn1) * L2E);
        m0 = mn0; m1 = mn1;
#pragma unroll
        for (int j = 0; j < 16; j++) {
            o[j][0] *= cor0; o[j][1] *= cor0;
            o[j][2] *= cor1; o[j][3] *= cor1;
        }
        float rs0 = 0.f, rs1 = 0.f;
#pragma unroll
        for (int j = 0; j < 8; j++) {
            s[j][0] = fexp2((s[j][0] - mn0) * L2E);
            s[j][1] = fexp2((s[j][1] - mn0) * L2E);
            s[j][2] = fexp2((s[j][2] - mn1) * L2E);
            s[j][3] = fexp2((s[j][3] - mn1) * L2E);
            rs0 += s[j][0] + s[j][1];
            rs1 += s[j][2] + s[j][3];
        }
        rs0 += __shfl_xor_sync(0xffffffffu, rs0, 1);
        rs0 += __shfl_xor_sync(0xffffffffu, rs0, 2);
        rs1 += __shfl_xor_sync(0xffffffffu, rs1, 1);
        rs1 += __shfl_xor_sync(0xffffffffu, rs1, 2);
        l0 = l0 * cor0 + rs0;
        l1 = l1 * cor1 + rs1;

#pragma unroll
        for (int ks = 0; ks < 4; ks++) {
            uint32_t pha[4], pla[4];
            pha[0] = pack_bf2(s[2 * ks][0], s[2 * ks][1]);
            pha[1] = pack_bf2(s[2 * ks][2], s[2 * ks][3]);
            pha[2] = pack_bf2(s[2 * ks + 1][0], s[2 * ks + 1][1]);
            pha[3] = pack_bf2(s[2 * ks + 1][2], s[2 * ks + 1][3]);
            pla[0] = pack_bf2_res(s[2 * ks][0], s[2 * ks][1], pha[0]);
            pla[1] = pack_bf2_res(s[2 * ks][2], s[2 * ks][3], pha[1]);
            pla[2] = pack_bf2_res(s[2 * ks + 1][0], s[2 * ks + 1][1], pha[2]);
            pla[3] = pack_bf2_res(s[2 * ks + 1][2], s[2 * ks + 1][3], pha[3]);
#pragma unroll
            for (int gr = 0; gr < 8; gr++) {
                uint32_t vh4[4], vl4[4];
                uint32_t ro = st + 2 * KVT + (ks * 16 + arow) * ARB +
                              gr * 32 + vcolB;
                ldsm4t(vh4[0], vh4[1], vh4[2], vh4[3], ro);
                ldsm4t(vl4[0], vl4[1], vl4[2], vl4[3], ro + KVT);
                mma_bf16(o[2 * gr], pha, vh4);
                mma_bf16(o[2 * gr], pha, vl4);
                mma_bf16(o[2 * gr], pla, vh4);
                mma_bf16(o[2 * gr + 1], pha, vh4 + 2);
                mma_bf16(o[2 * gr + 1], pha, vl4 + 2);
                mma_bf16(o[2 * gr + 1], pla, vh4 + 2);
            }
        }
        __syncthreads();
        if (t + 2 < NT) load_stage(t & 1, t + 2);
    }

    float inv0 = 1.f / l0, inv1 = 1.f / l1;
    const int r0 = qt * 128 + wm + g, r1 = r0 + 8;
#pragma unroll
    for (int j = 0; j < 16; j++) {
        int col = h * 128 + j * 8 + 2 * t4;
        *reinterpret_cast<float2*>(&g_A[((size_t)(b * Sn + r0)) * 4096 + col]) =
            make_float2(o[j][0] * inv0, o[j][1] * inv0);
        *reinterpret_cast<float2*>(&g_A[((size_t)(b * Sn + r1)) * 4096 + col]) =
            make_float2(o[j][2] * inv1, o[j][3] * inv1);
    }
}

// ---------------------------------------------------------------------------
extern "C" void kernel_launch(void* const* d_in, const int* in_sizes, int n_in,
                              void* d_out, int out_size)
{
    const float* hidden = (const float*)d_in[0];
    const float* Wq = (const float*)d_in[2];
    const float* Wk = (const float*)d_in[3];
    const float* Wv = (const float*)d_in[4];
    const float* Wo = (const float*)d_in[5];
    float* out = (float*)d_out;

    float *pQ, *pK, *pV, *pA;
    __nv_bfloat16 *pXh, *pXl, *pQTh, *pQTl, *pKTh, *pKTl, *pVTh, *pVTl, *pOTh, *pOTl;
    __nv_bfloat16 *pQh, *pQl, *pKh, *pKl, *pVh, *pVl;
    cudaGetSymbolAddress((void**)&pQ, g_Q);
    cudaGetSymbolAddress((void**)&pK, g_K);
    cudaGetSymbolAddress((void**)&pV, g_V);
    cudaGetSymbolAddress((void**)&pA, g_A);
    cudaGetSymbolAddress((void**)&pXh, g_Xhi);
    cudaGetSymbolAddress((void**)&pXl, g_Xlo);
    cudaGetSymbolAddress((void**)&pQTh, g_WqThi);
    cudaGetSymbolAddress((void**)&pQTl, g_WqTlo);
    cudaGetSymbolAddress((void**)&pKTh, g_WkThi);
    cudaGetSymbolAddress((void**)&pKTl, g_WkTlo);
    cudaGetSymbolAddress((void**)&pVTh, g_WvThi);
    cudaGetSymbolAddress((void**)&pVTl, g_WvTlo);
    cudaGetSymbolAddress((void**)&pOTh, g_WoThi);
    cudaGetSymbolAddress((void**)&pOTl, g_WoTlo);
    cudaGetSymbolAddress((void**)&pQh, g_Qh);
    cudaGetSymbolAddress((void**)&pQl, g_Ql);
    cudaGetSymbolAddress((void**)&pKh, g_Kh);
    cudaGetSymbolAddress((void**)&pKl, g_Kl);
    cudaGetSymbolAddress((void**)&pVh, g_Vh);
    cudaGetSymbolAddress((void**)&pVl, g_Vl);

    cudaFuncSetAttribute(hgemm_kernel<0>,
                         cudaFuncAttributeMaxDynamicSharedMemorySize, HG_SMEM);
    cudaFuncSetAttribute(hgemm_kernel<1>,
                         cudaFuncAttributeMaxDynamicSharedMemorySize, HG_SMEM);
    cudaFuncSetAttribute(hgemm_kernel<2>,
                         cudaFuncAttributeMaxDynamicSharedMemorySize, HG_SMEM);
    cudaFuncSetAttribute(attn_mma_kernel,
                         cudaFuncAttributeMaxDynamicSharedMemorySize, AT_SMEM);

    // 0) split/transpose conversions
    const int n4x = Mn * Hn / 4;
    split_kernel<<<n4x / 256, 256>>>(hidden, pXh, pXl, n4x);
    dim3 tb(32, 8);
    tsplit_kernel<<<dim3(4096 / 32, 4096 / 32), tb>>>(Wq, pQTh, pQTl, Hn, 4096);
    tsplit_kernel<<<dim3(1024 / 32, 4096 / 32), tb>>>(Wk, pKTh, pKTl, Hn, 1024);
    tsplit_kernel<<<dim3(1024 / 32, 4096 / 32), tb>>>(Wv, pVTh, pVTl, Hn, 1024);
    tsplit_kernel<<<dim3(4096 / 32, 4096 / 32), tb>>>(Wo, pOTh, pOTl, 4096, Hn);

    // 1) projections (256x128 CTA tiles)
    hgemm_kernel<1><<<dim3(4096 / 128, Mn / 256), 256, HG_SMEM>>>(
        pXh, pXl, pQTh, pQTl, pQ, 4096, Hn);
    hgemm_kernel<2><<<dim3(1024 / 128, Mn / 256), 256, HG_SMEM>>>(
        pXh, pXl, pKTh, pKTl, pK, 1024, Hn);
    hgemm_kernel<2><<<dim3(1024 / 128, Mn / 256), 256, HG_SMEM>>>(
        pXh, pXl, pVTh, pVTl, pV, 1024, Hn);

    // 2) RoPE + split (Q gets QK_SCALE folded in); V split
    int totQ = Bn * NHn * Sn * 64;
    int totK = Bn * NKVn * Sn * 64;
    rope_split_kernel<<<totQ / 256, 256>>>(pQ, pQh, pQl, totQ, QK_SCALE);
    rope_split_kernel<<<totK / 256, 256>>>(pK, pKh, pKl, totK, 1.f);
    const int nv4 = Bn * NKVn * Sn * HDn / 4;
    split_kernel<<<nv4 / 256, 256>>>(pV, pVh, pVl, nv4);

    // 3) causal flash attention (bf16 split mma)
    dim3 ga(Sn / 128, NHn, Bn);
    attn_mma_kernel<<<ga, 256, AT_SMEM>>>();

    // 4) output projection: split g_A then GEMM
    split_kernel<<<n4x / 256, 256>>>(pA, pXh, pXl, n4x);
    hgemm_kernel<0><<<dim3(4096 / 128, Mn / 256), 256, HG_SMEM>>>(
        pXh, pXl, pOTh, pOTl, out, 4096, Hn);
}

// round 11
// speedup vs baseline: 1.7765x; 1.0267x over previous
#include <cuda_runtime.h>
#include <cuda_bf16.h>
#include <math.h>
#include <stdint.h>

// Problem dims
constexpr int Bn = 2, Sn = 2048, Hn = 4096, NHn = 32, NKVn = 8, HDn = 128;
constexpr int Mn = Bn * Sn;
constexpr float QK_SCALE = 0.08838834764831845f; // 1/sqrt(128)
constexpr float L2E = 1.4426950408889634f;

// fp32 scratch
__device__ float g_Q[(size_t)Bn * NHn * Sn * HDn];   // [b][h][s][d]
__device__ float g_K[(size_t)Bn * NKVn * Sn * HDn];  // [b][kh][s][d]
__device__ float g_V[(size_t)Bn * NKVn * Sn * HDn];
__device__ float g_A[(size_t)Bn * Sn * NHn * HDn];   // [b][s][h*d]

// bf16 split scratch
__device__ __nv_bfloat16 g_Xhi[(size_t)Mn * Hn];
__device__ __nv_bfloat16 g_Xlo[(size_t)Mn * Hn];
__device__ __nv_bfloat16 g_WqThi[(size_t)4096 * 4096];
__device__ __nv_bfloat16 g_WqTlo[(size_t)4096 * 4096];
__device__ __nv_bfloat16 g_WkThi[(size_t)1024 * 4096];
__device__ __nv_bfloat16 g_WkTlo[(size_t)1024 * 4096];
__device__ __nv_bfloat16 g_WvThi[(size_t)1024 * 4096];
__device__ __nv_bfloat16 g_WvTlo[(size_t)1024 * 4096];
__device__ __nv_bfloat16 g_WoThi[(size_t)4096 * 4096];
__device__ __nv_bfloat16 g_WoTlo[(size_t)4096 * 4096];
// attention operands (hi/lo, post-RoPE)
__device__ __nv_bfloat16 g_Qh[(size_t)Bn * NHn * Sn * HDn];
__device__ __nv_bfloat16 g_Ql[(size_t)Bn * NHn * Sn * HDn];
__device__ __nv_bfloat16 g_Kh[(size_t)Bn * NKVn * Sn * HDn];
__device__ __nv_bfloat16 g_Kl[(size_t)Bn * NKVn * Sn * HDn];
__device__ __nv_bfloat16 g_Vh[(size_t)Bn * NKVn * Sn * HDn];
__device__ __nv_bfloat16 g_Vl[(size_t)Bn * NKVn * Sn * HDn];

// ---------------------------------------------------------------------------
// helpers
// ---------------------------------------------------------------------------
__device__ __forceinline__ uint32_t smem_u32(const void* p) {
    uint32_t a;
    asm("{ .reg .u64 t; cvta.to.shared.u64 t, %1; cvt.u32.u64 %0, t; }"
        : "=r"(a) : "l"(p));
    return a;
}
__device__ __forceinline__ void cpa16(uint32_t dst, const void* src) {
    asm volatile("cp.async.cg.shared.global [%0], [%1], 16;"
                 :: "r"(dst), "l"(src) : "memory");
}
__device__ __forceinline__ void ldsm4(uint32_t& r0, uint32_t& r1,
                                      uint32_t& r2, uint32_t& r3, uint32_t a) {
    asm volatile("ldmatrix.sync.aligned.m8n8.x4.shared.b16 {%0,%1,%2,%3}, [%4];"
                 : "=r"(r0), "=r"(r1), "=r"(r2), "=r"(r3) : "r"(a));
}
__device__ __forceinline__ void ldsm4t(uint32_t& r0, uint32_t& r1,
                                       uint32_t& r2, uint32_t& r3, uint32_t a) {
    asm volatile("ldmatrix.sync.aligned.m8n8.x4.trans.shared.b16 {%0,%1,%2,%3}, [%4];"
                 : "=r"(r0), "=r"(r1), "=r"(r2), "=r"(r3) : "r"(a));
}
__device__ __forceinline__ void mma_bf16(float* c, const uint32_t* a,
                                         const uint32_t* b) {
    asm volatile(
        "mma.sync.aligned.m16n8k16.row.col.f32.bf16.bf16.f32 "
        "{%0,%1,%2,%3}, {%4,%5,%6,%7}, {%8,%9}, {%0,%1,%2,%3};"
        : "+f"(c[0]), "+f"(c[1]), "+f"(c[2]), "+f"(c[3])
        : "r"(a[0]), "r"(a[1]), "r"(a[2]), "r"(a[3]), "r"(b[0]), "r"(b[1]));
}
// fast exp2 on the FMA pipe (y <= 0; clamp makes masked rows vanish)
__device__ __forceinline__ float fexp2(float y) {
    y = fmaxf(y, -126.f);
    float fl = floorf(y);
    float f = y - fl;
    float p = 1.8775767e-3f;
    p = fmaf(p, f, 8.9893397e-3f);
    p = fmaf(p, f, 5.5826318e-2f);
    p = fmaf(p, f, 2.4015361e-1f);
    p = fmaf(p, f, 6.9315308e-1f);
    p = fmaf(p, f, 9.9999994e-1f);
    return __int_as_float(((int)fl + 127) << 23) * p;
}
__device__ __forceinline__ uint32_t pack_bf2(float a, float b) {
    __nv_bfloat162 v = __floats2bfloat162_rn(a, b);
    return *reinterpret_cast<uint32_t*>(&v);
}
__device__ __forceinline__ uint32_t pack_bf2_res(float a, float b, uint32_t hi) {
    __nv_bfloat162 hv = *reinterpret_cast<__nv_bfloat162*>(&hi);
    return pack_bf2(a - __bfloat162float(hv.x), b - __bfloat162float(hv.y));
}

// ---------------------------------------------------------------------------
// Split conversion: x -> (hi, lo) bf16
// ---------------------------------------------------------------------------
__global__ void split_kernel(const float* __restrict__ x,
                             __nv_bfloat16* __restrict__ hi,
                             __nv_bfloat16* __restrict__ lo, int n4)
{
    int i = blockIdx.x * 256 + threadIdx.x;
    if (i >= n4) return;
    float4 v = reinterpret_cast<const float4*>(x)[i];
    __nv_bfloat16 h0 = __float2bfloat16(v.x), h1 = __float2bfloat16(v.y);
    __nv_bfloat16 h2 = __float2bfloat16(v.z), h3 = __float2bfloat16(v.w);
    __nv_bfloat16 l0 = __float2bfloat16(v.x - __bfloat162float(h0));
    __nv_bfloat16 l1 = __float2bfloat16(v.y - __bfloat162float(h1));
    __nv_bfloat16 l2 = __float2bfloat16(v.z - __bfloat162float(h2));
    __nv_bfloat16 l3 = __float2bfloat16(v.w - __bfloat162float(h3));
    reinterpret_cast<__nv_bfloat162*>(hi)[i * 2 + 0] = __halves2bfloat162(h0, h1);
    reinterpret_cast<__nv_bfloat162*>(hi)[i * 2 + 1] = __halves2bfloat162(h2, h3);
    reinterpret_cast<__nv_bfloat162*>(lo)[i * 2 + 0] = __halves2bfloat162(l0, l1);
    reinterpret_cast<__nv_bfloat162*>(lo)[i * 2 + 1] = __halves2bfloat162(l2, l3);
}

// ---------------------------------------------------------------------------
// Transpose + split: W[K][N] fp32 -> T{hi,lo}[N][K] bf16
// ---------------------------------------------------------------------------
__global__ void tsplit_kernel(const float* __restrict__ W,
                              __nv_bfloat16* __restrict__ Thi,
                              __nv_bfloat16* __restrict__ Tlo, int K, int N)
{
    __shared__ float t[32][33];
    int tx = threadIdx.x, ty = threadIdx.y;
    int bx = blockIdx.x, by = blockIdx.y;
#pragma unroll
    for (int i = 0; i < 4; i++) {
        int r = by * 32 + ty + i * 8;
        t[ty + i * 8][tx] = W[(size_t)r * N + bx * 32 + tx];
    }
    __syncthreads();
#pragma unroll
    for (int i = 0; i < 4; i++) {
        int n = bx * 32 + ty + i * 8;
        int k = by * 32 + tx;
        float v = t[tx][ty + i * 8];
        __nv_bfloat16 h = __float2bfloat16(v);
        __nv_bfloat16 l = __float2bfloat16(v - __bfloat162float(h));
        Thi[(size_t)n * K + k] = h;
        Tlo[(size_t)n * K + k] = l;
    }
}

// ---------------------------------------------------------------------------
// RoPE + hi/lo split (+ optional scale), [bh][s][128] layout, pos == s.
// ---------------------------------------------------------------------------
__global__ void rope_split_kernel(const float* __restrict__ X,
                                  __nv_bfloat16* __restrict__ H,
                                  __nv_bfloat16* __restrict__ L,
                                  int total, float scale)
{
    int idx = blockIdx.x * 256 + threadIdx.x;
    if (idx >= total) return;
    int d = idx & 63;
    int s = (idx >> 6) & (Sn - 1);
    int bh = idx >> 17;
    float inv = powf(10000.f, -(float)d / 64.f);
    float ang = (float)s * inv;
    float sn, cs;
    sincosf(ang, &sn, &cs);
    size_t base = ((size_t)bh * Sn + s) * HDn;
    float x0 = X[base + d];
    float x1 = X[base + d + 64];
    float r0 = (x0 * cs - x1 * sn) * scale;
    float r1 = (x1 * cs + x0 * sn) * scale;
    __nv_bfloat16 h0 = __float2bfloat16(r0);
    __nv_bfloat16 h1 = __float2bfloat16(r1);
    H[base + d] = h0;
    H[base + d + 64] = h1;
    L[base + d] = __float2bfloat16(r0 - __bfloat162float(h0));
    L[base + d + 64] = __float2bfloat16(r1 - __bfloat162float(h1));
}

// ---------------------------------------------------------------------------
// bf16 split GEMM on mma.sync: CTA 128x128, K-chunk 32, 2-stage cp.async,
// 80 B/row (64 data + 16 pad; 80 mod 128 = 16 -> conflict-free ldsm, same
// class as 144). Stage = 40 KB -> 2 stages = 80 KB -> 2 CTAs/SM.
// MODE 0: C row-major; MODE 1: Q layout; MODE 2: KV layout.
// ---------------------------------------------------------------------------
constexpr int TROW = 80;                  // bytes per 32-element bf16 row
constexpr int TTILE = 128 * TROW;         // 10240 B
constexpr int TSTAGE = 4 * TTILE;         // 40960 B
constexpr int HG_SMEM = 2 * TSTAGE;       // 81920 B  (>= 128*132*4 staging)

template <int MODE>
__global__ __launch_bounds__(256, 2) void hgemm_kernel(
    const __nv_bfloat16* __restrict__ Ahi, const __nv_bfloat16* __restrict__ Alo,
    const __nv_bfloat16* __restrict__ Bhi, const __nv_bfloat16* __restrict__ Blo,
    float* __restrict__ C, int N, int K)
{
    extern __shared__ char smem[];
    const uint32_t sb = smem_u32(smem);

    const int tid = threadIdx.x;
    const int wid = tid >> 5, lane = tid & 31;
    const int g = lane >> 2, t4 = lane & 3;
    const int wr = wid >> 2, wc = wid & 3;
    const int wm = wr * 64, wn = wc * 32;
    const int m0 = blockIdx.y * 128, n0 = blockIdx.x * 128;

    const __nv_bfloat16* Ah = Ahi + (size_t)m0 * K;
    const __nv_bfloat16* Al = Alo + (size_t)m0 * K;
    const __nv_bfloat16* Bh = Bhi + (size_t)n0 * K;
    const __nv_bfloat16* Bl = Blo + (size_t)n0 * K;

    float c[4][4][4];
#pragma unroll
    for (int mi = 0; mi < 4; mi++)
#pragma unroll
        for (int ni = 0; ni < 4; ni++)
#pragma unroll
            for (int r = 0; r < 4; r++) c[mi][ni][r] = 0.f;

    // per-chunk load: 4 tiles x 128 rows x 4 chunks(16B) = 2048 cpa16
    // i in [0,8): tile = i>>1, within-tile id = tid + (i&1)*256 in [0,512)
    auto load_chunk = [&](int stage, int koff) {
        const uint32_t base = sb + stage * TSTAGE;
#pragma unroll
        for (int i = 0; i < 8; i++) {
            const int tile = i >> 1;
            const int id = tid + (i & 1) * 256;
            const int r = id >> 2, c4 = id & 3;
            const __nv_bfloat16* s =
                (tile == 0) ? Ah : (tile == 1) ? Al : (tile == 2) ? Bh : Bl;
            cpa16(base + tile * TTILE + r * TROW + c4 * 16,
                  s + (size_t)r * K + koff + c4 * 8);
        }
        asm volatile("cp.async.commit_group;" ::: "memory");
    };

    const int NC = K / 32;
    load_chunk(0, 0);
    load_chunk(1, 32);

    const int arow_off = (lane & 7) + ((lane >> 3) & 1) * 8;
    const int acol_off = (lane >> 4) * 8;
    const int brow_off = (lane & 7) + (lane >> 4) * 8;
    const int bcol_off = ((lane >> 3) & 1) * 8;

    for (int ch = 0; ch < NC; ch++) {
        if (ch + 1 < NC)
            asm volatile("cp.async.wait_group 1;" ::: "memory");
        else
            asm volatile("cp.async.wait_group 0;" ::: "memory");
        __syncthreads();

        const uint32_t st = sb + (ch & 1) * TSTAGE;
        const uint32_t ah_b = st, al_b = st + TTILE;
        const uint32_t bh_b = st + 2 * TTILE, bl_b = st + 3 * TTILE;

#pragma unroll
        for (int kk = 0; kk < 32; kk += 16) {
            uint32_t fah[4][4], fal[4][4], fbh[4][2], fbl[4][2];
#pragma unroll
            for (int mi = 0; mi < 4; mi++) {
                const uint32_t ro = (wm + mi * 16 + arow_off) * TROW +
                                    (kk + acol_off) * 2;
                ldsm4(fah[mi][0], fah[mi][1], fah[mi][2], fah[mi][3], ah_b + ro);
                ldsm4(fal[mi][0], fal[mi][1], fal[mi][2], fal[mi][3], al_b + ro);
            }
#pragma unroll
            for (int bt = 0; bt < 2; bt++) {
                const uint32_t ro = (wn + bt * 16 + brow_off) * TROW +
                                    (kk + bcol_off) * 2;
                ldsm4(fbh[2 * bt][0], fbh[2 * bt][1],
                      fbh[2 * bt + 1][0], fbh[2 * bt + 1][1], bh_b + ro);
                ldsm4(fbl[2 * bt][0], fbl[2 * bt][1],
                      fbl[2 * bt + 1][0], fbl[2 * bt + 1][1], bl_b + ro);
            }
#pragma unroll
            for (int mi = 0; mi < 4; mi++)
#pragma unroll
                for (int ni = 0; ni < 4; ni++) {
                    mma_bf16(c[mi][ni], fah[mi], fbh[ni]);
                    mma_bf16(c[mi][ni], fah[mi], fbl[ni]);
                    mma_bf16(c[mi][ni], fal[mi], fbh[ni]);
                }
        }
        __syncthreads();
        if (ch + 2 < NC) load_chunk(ch & 1, (ch + 2) * 32);
    }

    // Epilogue: c-frag (g,2t4),(g,2t4+1),(g+8,2t4),(g+8,2t4+1)
    if (MODE == 0) {
#pragma unroll
        for (int mi = 0; mi < 4; mi++)
#pragma unroll
            for (int ni = 0; ni < 4; ni++) {
                const int row0 = m0 + wm + mi * 16 + g;
                const int col = n0 + wn + ni * 8 + 2 * t4;
#pragma unroll
                for (int half = 0; half < 2; half++) {
                    const int m = row0 + half * 8;
                    float2 v = half ? make_float2(c[mi][ni][2], c[mi][ni][3])
                                    : make_float2(c[mi][ni][0], c[mi][ni][1]);
                    *reinterpret_cast<float2*>(&C[(size_t)m * N + col]) = v;
                }
            }
    } else {
#pragma unroll
        for (int mi = 0; mi < 4; mi++)
#pragma unroll
            for (int ni = 0; ni < 4; ni++) {
                const int row0 = m0 + wm + mi * 16 + g;
                const int col = n0 + wn + ni * 8 + 2 * t4;
#pragma unroll
                for (int half = 0; half < 2; half++) {
                    const int m = row0 + half * 8;
                    float2 v = half ? make_float2(c[mi][ni][2], c[mi][ni][3])
                                    : make_float2(c[mi][ni][0], c[mi][ni][1]);
                    int b = m >> 11, s = m & 2047;
                    int h = col >> 7, d = col & 127;
                    const int heads = (MODE == 1) ? NHn : NKVn;
                    *reinterpret_cast<float2*>(
                        &C[(((size_t)(b * heads + h) * Sn) + s) * HDn + d]) = v;
                }
            }
    }
}

// ---------------------------------------------------------------------------
// Flash attention on mma.sync, bf16 split, BQ=128, BK=64, 8 warps,
// 2-stage pipeline (round-6 proven version, verbatim).
// ---------------------------------------------------------------------------
constexpr int ARB = 272;                  // padded row bytes (136 bf16)
constexpr int KVT = 64 * ARB;             // one 64x128 bf16 tile = 17408 B
constexpr int ASTG = 4 * KVT;             // Kh,Kl,Vh,Vl per stage = 69632 B
constexpr int AT_SMEM = 2 * ASTG;         // 139264 B

__global__ __launch_bounds__(256, 1) void attn_mma_kernel()
{
    extern __shared__ char smem[];
    const uint32_t sb = smem_u32(smem);
    const int qt = blockIdx.x, h = blockIdx.y, b = blockIdx.z;
    const int tid = threadIdx.x, wid = tid >> 5, lane = tid & 31;
    const int g = lane >> 2, t4 = lane & 3;
    const int wm = wid * 16;
    const int kvh = h >> 2;
    const int NT = 2 * (qt + 1);

    const __nv_bfloat16* Qhp = g_Qh + ((size_t)(b * NHn + h) * Sn + qt * 128) * HDn;
    const __nv_bfloat16* Qlp = g_Ql + ((size_t)(b * NHn + h) * Sn + qt * 128) * HDn;
    const __nv_bfloat16* Khp = g_Kh + ((size_t)(b * NKVn + kvh) * Sn) * HDn;
    const __nv_bfloat16* Klp = g_Kl + ((size_t)(b * NKVn + kvh) * Sn) * HDn;
    const __nv_bfloat16* Vhp = g_Vh + ((size_t)(b * NKVn + kvh) * Sn) * HDn;
    const __nv_bfloat16* Vlp = g_Vl + ((size_t)(b * NKVn + kvh) * Sn) * HDn;

    const uint32_t qhb = sb + ASTG, qlb = sb + ASTG + 34816;
#pragma unroll
    for (int i = 0; i < 8; i++) {
        int id = tid + i * 256, r = id >> 4, c = id & 15;
        cpa16(qhb + r * ARB + c * 16, Qhp + r * HDn + c * 8);
        cpa16(qlb + r * ARB + c * 16, Qlp + r * HDn + c * 8);
    }
    asm volatile("cp.async.commit_group;" ::: "memory");

    auto load_stage = [&](int stg, int t) {
        const uint32_t st = sb + stg * ASTG;
        const __nv_bfloat16* kh = Khp + (size_t)t * 64 * HDn;
        const __nv_bfloat16* kl = Klp + (size_t)t * 64 * HDn;
        const __nv_bfloat16* vh = Vhp + (size_t)t * 64 * HDn;
        const __nv_bfloat16* vl = Vlp + (size_t)t * 64 * HDn;
#pragma unroll
        for (int i = 0; i < 4; i++) {
            int id = tid + i * 256, r = id >> 4, c = id & 15;
            cpa16(st + 0 * KVT + r * ARB + c * 16, kh + r * HDn + c * 8);
            cpa16(st + 1 * KVT + r * ARB + c * 16, kl + r * HDn + c * 8);
            cpa16(st + 2 * KVT + r * ARB + c * 16, vh + r * HDn + c * 8);
            cpa16(st + 3 * KVT + r * ARB + c * 16, vl + r * HDn + c * 8);
        }
        asm volatile("cp.async.commit_group;" ::: "memory");
    };
    load_stage(0, 0);

    asm volatile("cp.async.wait_group 1;" ::: "memory");  // Q arrived
    __syncthreads();

    const int arow = (lane & 7) + ((lane >> 3) & 1) * 8;
    const int acolB = (lane >> 4) * 16;
    uint32_t qhf[8][4], qlf[8][4];
#pragma unroll
    for (int ks = 0; ks < 8; ks++) {
        uint32_t ro = (wm + arow) * ARB + ks * 32 + acolB;
        ldsm4(qhf[ks][0], qhf[ks][1], qhf[ks][2], qhf[ks][3], qhb + ro);
        ldsm4(qlf[ks][0], qlf[ks][1], qlf[ks][2], qlf[ks][3], qlb + ro);
    }
    __syncthreads();
    load_stage(1, 1);

    float o[16][4];
#pragma unroll
    for (int j = 0; j < 16; j++)
#pragma unroll
        for (int e = 0; e < 4; e++) o[j][e] = 0.f;
    float m0 = -1e30f, m1 = -1e30f, l0 = 0.f, l1 = 0.f;

    const int brow = (lane & 7) + (lane >> 4) * 8;
    const int bcolB = ((lane >> 3) & 1) * 16;
    const int vcolB = (lane >> 4) * 16;
    const int row0g = qt * 128 + wm + g;

    for (int t = 0; t < NT; t++) {
        if (t + 1 < NT)
            asm volatile("cp.async.wait_group 1;" ::: "memory");
        else
            asm volatile("cp.async.wait_group 0;" ::: "memory");
        __syncthreads();
        const uint32_t st = sb + (t & 1) * ASTG;

        float s[8][4];
#pragma unroll
        for (int j = 0; j < 8; j++)
#pragma unroll
            for (int e = 0; e < 4; e++) s[j][e] = 0.f;

#pragma unroll
        for (int ks = 0; ks < 8; ks++) {
#pragma unroll
            for (int gr = 0; gr < 4; gr++) {
                uint32_t kh4[4], kl4[4];
                uint32_t ro = st + (gr * 16 + brow) * ARB + ks * 32 + bcolB;
                ldsm4(kh4[0], kh4[1], kh4[2], kh4[3], ro);
                ldsm4(kl4[0], kl4[1], kl4[2], kl4[3], ro + KVT);
                mma_bf16(s[2 * gr], qhf[ks], kh4);
                mma_bf16(s[2 * gr], qhf[ks], kl4);
                mma_bf16(s[2 * gr], qlf[ks], kh4);
                mma_bf16(s[2 * gr + 1], qhf[ks], kh4 + 2);
                mma_bf16(s[2 * gr + 1], qhf[ks], kl4 + 2);
                mma_bf16(s[2 * gr + 1], qlf[ks], kh4 + 2);
            }
        }

        if (t >= 2 * qt) {
#pragma unroll
            for (int j = 0; j < 8; j++) {
                int c0 = t * 64 + j * 8 + 2 * t4;
                if (c0 > row0g)     s[j][0] = -1e30f;
                if (c0 + 1 > row0g) s[j][1] = -1e30f;
                if (c0 > row0g + 8)     s[j][2] = -1e30f;
                if (c0 + 1 > row0g + 8) s[j][3] = -1e30f;
            }
        }

        float tm0 = -1e30f, tm1 = -1e30f;
#pragma unroll
        for (int j = 0; j < 8; j++) {
            tm0 = fmaxf(tm0, fmaxf(s[j][0], s[j][1]));
            tm1 = fmaxf(tm1, fmaxf(s[j][2], s[j][3]));
        }
        tm0 = fmaxf(tm0, __shfl_xor_sync(0xffffffffu, tm0, 1));
        tm0 = fmaxf(tm0, __shfl_xor_sync(0xffffffffu, tm0, 2));
        tm1 = fmaxf(tm1, __shfl_xor_sync(0xffffffffu, tm1, 1));
        tm1 = fmaxf(tm1, __shfl_xor_sync(0xffffffffu, tm1, 2));
        float mn0 = fmaxf(m0, tm0), mn1 = fmaxf(m1, tm1);
        float cor0 = fexp2((m0 - mn0) * L2E);
        float cor1 = fexp2((m1 - mn1) * L2E);
        m0 = mn0; m1 = mn1;
#pragma unroll
        for (int j = 0; j < 16; j++) {
            o[j][0] *= cor0; o[j][1] *= cor0;
            o[j][2] *= cor1; o[j][3] *= cor1;
        }
        float rs0 = 0.f, rs1 = 0.f;
#pragma unroll
        for (int j = 0; j < 8; j++) {
            s[j][0] = fexp2((s[j][0] - mn0) * L2E);
            s[j][1] = fexp2((s[j][1] - mn0) * L2E);
            s[j][2] = fexp2((s[j][2] - mn1) * L2E);
            s[j][3] = fexp2((s[j][3] - mn1) * L2E);
            rs0 += s[j][0] + s[j][1];
            rs1 += s[j][2] + s[j][3];
        }
        rs0 += __shfl_xor_sync(0xffffffffu, rs0, 1);
        rs0 += __shfl_xor_sync(0xffffffffu, rs0, 2);
        rs1 += __shfl_xor_sync(0xffffffffu, rs1, 1);
        rs1 += __shfl_xor_sync(0xffffffffu, rs1, 2);
        l0 = l0 * cor0 + rs0;
        l1 = l1 * cor1 + rs1;

#pragma unroll
        for (int ks = 0; ks < 4; ks++) {
            uint32_t pha[4], pla[4];
            pha[0] = pack_bf2(s[2 * ks][0], s[2 * ks][1]);
            pha[1] = pack_bf2(s[2 * ks][2], s[2 * ks][3]);
            pha[2] = pack_bf2(s[2 * ks + 1][0], s[2 * ks + 1][1]);
            pha[3] = pack_bf2(s[2 * ks + 1][2], s[2 * ks + 1][3]);
            pla[0] = pack_bf2_res(s[2 * ks][0], s[2 * ks][1], pha[0]);
            pla[1] = pack_bf2_res(s[2 * ks][2], s[2 * ks][3], pha[1]);
            pla[2] = pack_bf2_res(s[2 * ks + 1][0], s[2 * ks + 1][1], pha[2]);
            pla[3] = pack_bf2_res(s[2 * ks + 1][2], s[2 * ks + 1][3], pha[3]);
#pragma unroll
            for (int gr = 0; gr < 8; gr++) {
                uint32_t vh4[4], vl4[4];
                uint32_t ro = st + 2 * KVT + (ks * 16 + arow) * ARB +
                              gr * 32 + vcolB;
                ldsm4t(vh4[0], vh4[1], vh4[2], vh4[3], ro);
                ldsm4t(vl4[0], vl4[1], vl4[2], vl4[3], ro + KVT);
                mma_bf16(o[2 * gr], pha, vh4);
                mma_bf16(o[2 * gr], pha, vl4);
                mma_bf16(o[2 * gr], pla, vh4);
                mma_bf16(o[2 * gr + 1], pha, vh4 + 2);
                mma_bf16(o[2 * gr + 1], pha, vl4 + 2);
                mma_bf16(o[2 * gr + 1], pla, vh4 + 2);
            }
        }
        __syncthreads();
        if (t + 2 < NT) load_stage(t & 1, t + 2);
    }

    float inv0 = 1.f / l0, inv1 = 1.f / l1;
    const int r0 = qt * 128 + wm + g, r1 = r0 + 8;
#pragma unroll
    for (int j = 0; j < 16; j++) {
        int col = h * 128 + j * 8 + 2 * t4;
        *reinterpret_cast<float2*>(&g_A[((size_t)(b * Sn + r0)) * 4096 + col]) =
            make_float2(o[j][0] * inv0, o[j][1] * inv0);
        *reinterpret_cast<float2*>(&g_A[((size_t)(b * Sn + r1)) * 4096 + col]) =
            make_float2(o[j][2] * inv1, o[j][3] * inv1);
    }
}

// ---------------------------------------------------------------------------
extern "C" void kernel_launch(void* const* d_in, const int* in_sizes, int n_in,
                              void* d_out, int out_size)
{
    const float* hidden = (const float*)d_in[0];
    const float* Wq = (const float*)d_in[2];
    const float* Wk = (const float*)d_in[3];
    const float* Wv = (const float*)d_in[4];
    const float* Wo = (const float*)d_in[5];
    float* out = (float*)d_out;

    float *pQ, *pK, *pV, *pA;
    __nv_bfloat16 *pXh, *pXl, *pQTh, *pQTl, *pKTh, *pKTl, *pVTh, *pVTl, *pOTh, *pOTl;
    __nv_bfloat16 *pQh, *pQl, *pKh, *pKl, *pVh, *pVl;
    cudaGetSymbolAddress((void**)&pQ, g_Q);
    cudaGetSymbolAddress((void**)&pK, g_K);
    cudaGetSymbolAddress((void**)&pV, g_V);
    cudaGetSymbolAddress((void**)&pA, g_A);
    cudaGetSymbolAddress((void**)&pXh, g_Xhi);
    cudaGetSymbolAddress((void**)&pXl, g_Xlo);
    cudaGetSymbolAddress((void**)&pQTh, g_WqThi);
    cudaGetSymbolAddress((void**)&pQTl, g_WqTlo);
    cudaGetSymbolAddress((void**)&pKTh, g_WkThi);
    cudaGetSymbolAddress((void**)&pKTl, g_WkTlo);
    cudaGetSymbolAddress((void**)&pVTh, g_WvThi);
    cudaGetSymbolAddress((void**)&pVTl, g_WvTlo);
    cudaGetSymbolAddress((void**)&pOTh, g_WoThi);
    cudaGetSymbolAddress((void**)&pOTl, g_WoTlo);
    cudaGetSymbolAddress((void**)&pQh, g_Qh);
    cudaGetSymbolAddress((void**)&pQl, g_Ql);
    cudaGetSymbolAddress((void**)&pKh, g_Kh);
    cudaGetSymbolAddress((void**)&pKl, g_Kl);
    cudaGetSymbolAddress((void**)&pVh, g_Vh);
    cudaGetSymbolAddress((void**)&pVl, g_Vl);

    cudaFuncSetAttribute(hgemm_kernel<0>,
                         cudaFuncAttributeMaxDynamicSharedMemorySize, HG_SMEM);
    cudaFuncSetAttribute(hgemm_kernel<1>,
                         cudaFuncAttributeMaxDynamicSharedMemorySize, HG_SMEM);
    cudaFuncSetAttribute(hgemm_kernel<2>,
                         cudaFuncAttributeMaxDynamicSharedMemorySize, HG_SMEM);
    cudaFuncSetAttribute(attn_mma_kernel,
                         cudaFuncAttributeMaxDynamicSharedMemorySize, AT_SMEM);

    // 0) split/transpose conversions
    const int n4x = Mn * Hn / 4;
    split_kernel<<<n4x / 256, 256>>>(hidden, pXh, pXl, n4x);
    dim3 tb(32, 8);
    tsplit_kernel<<<dim3(4096 / 32, 4096 / 32), tb>>>(Wq, pQTh, pQTl, Hn, 4096);
    tsplit_kernel<<<dim3(1024 / 32, 4096 / 32), tb>>>(Wk, pKTh, pKTl, Hn, 1024);
    tsplit_kernel<<<dim3(1024 / 32, 4096 / 32), tb>>>(Wv, pVTh, pVTl, Hn, 1024);
    tsplit_kernel<<<dim3(4096 / 32, 4096 / 32), tb>>>(Wo, pOTh, pOTl, 4096, Hn);

    // 1) projections (128x128 CTA tiles, 2 CTAs/SM)
    hgemm_kernel<1><<<dim3(4096 / 128, Mn / 128), 256, HG_SMEM>>>(
        pXh, pXl, pQTh, pQTl, pQ, 4096, Hn);
    hgemm_kernel<2><<<dim3(1024 / 128, Mn / 128), 256, HG_SMEM>>>(
        pXh, pXl, pKTh, pKTl, pK, 1024, Hn);
    hgemm_kernel<2><<<dim3(1024 / 128, Mn / 128), 256, HG_SMEM>>>(
        pXh, pXl, pVTh, pVTl, pV, 1024, Hn);

    // 2) RoPE + split (Q gets QK_SCALE folded in); V split
    int totQ = Bn * NHn * Sn * 64;
    int totK = Bn * NKVn * Sn * 64;
    rope_split_kernel<<<totQ / 256, 256>>>(pQ, pQh, pQl, totQ, QK_SCALE);
    rope_split_kernel<<<totK / 256, 256>>>(pK, pKh, pKl, totK, 1.f);
    const int nv4 = Bn * NKVn * Sn * HDn / 4;
    split_kernel<<<nv4 / 256, 256>>>(pV, pVh, pVl, nv4);

    // 3) causal flash attention (bf16 split mma)
    dim3 ga(Sn / 128, NHn, Bn);
    attn_mma_kernel<<<ga, 256, AT_SMEM>>>();

    // 4) output projection: split g_A then GEMM
    split_kernel<<<n4x / 256, 256>>>(pA, pXh, pXl, n4x);
    hgemm_kernel<0><<<dim3(4096 / 128, Mn / 128), 256, HG_SMEM>>>(
        pXh, pXl, pOTh, pOTl, out, 4096, Hn);
}

// round 12
// speedup vs baseline: 1.7871x; 1.0060x over previous
#include <cuda_runtime.h>
#include <cuda_bf16.h>
#include <math.h>
#include <stdint.h>

// Problem dims
constexpr int Bn = 2, Sn = 2048, Hn = 4096, NHn = 32, NKVn = 8, HDn = 128;
constexpr int Mn = Bn * Sn;
constexpr float QK_SCALE = 0.08838834764831845f; // 1/sqrt(128)
constexpr float L2E = 1.4426950408889634f;

// fp32 scratch (pre-RoPE projection outputs)
__device__ float g_Q[(size_t)Bn * NHn * Sn * HDn];   // [b][h][s][d]
__device__ float g_K[(size_t)Bn * NKVn * Sn * HDn];  // [b][kh][s][d]
__device__ float g_V[(size_t)Bn * NKVn * Sn * HDn];

// bf16 split scratch
__device__ __nv_bfloat16 g_Xhi[(size_t)Mn * Hn];   // X split; reused for attn out
__device__ __nv_bfloat16 g_Xlo[(size_t)Mn * Hn];
__device__ __nv_bfloat16 g_WqThi[(size_t)4096 * 4096];
__device__ __nv_bfloat16 g_WqTlo[(size_t)4096 * 4096];
__device__ __nv_bfloat16 g_WkThi[(size_t)1024 * 4096];
__device__ __nv_bfloat16 g_WkTlo[(size_t)1024 * 4096];
__device__ __nv_bfloat16 g_WvThi[(size_t)1024 * 4096];
__device__ __nv_bfloat16 g_WvTlo[(size_t)1024 * 4096];
__device__ __nv_bfloat16 g_WoThi[(size_t)4096 * 4096];
__device__ __nv_bfloat16 g_WoTlo[(size_t)4096 * 4096];
// attention operands (hi/lo, post-RoPE)
__device__ __nv_bfloat16 g_Qh[(size_t)Bn * NHn * Sn * HDn];
__device__ __nv_bfloat16 g_Ql[(size_t)Bn * NHn * Sn * HDn];
__device__ __nv_bfloat16 g_Kh[(size_t)Bn * NKVn * Sn * HDn];
__device__ __nv_bfloat16 g_Kl[(size_t)Bn * NKVn * Sn * HDn];
__device__ __nv_bfloat16 g_Vh[(size_t)Bn * NKVn * Sn * HDn];
__device__ __nv_bfloat16 g_Vl[(size_t)Bn * NKVn * Sn * HDn];

// ---------------------------------------------------------------------------
// helpers
// ---------------------------------------------------------------------------
__device__ __forceinline__ uint32_t smem_u32(const void* p) {
    uint32_t a;
    asm("{ .reg .u64 t; cvta.to.shared.u64 t, %1; cvt.u32.u64 %0, t; }"
        : "=r"(a) : "l"(p));
    return a;
}
__device__ __forceinline__ void cpa16(uint32_t dst, const void* src) {
    asm volatile("cp.async.cg.shared.global [%0], [%1], 16;"
                 :: "r"(dst), "l"(src) : "memory");
}
__device__ __forceinline__ void ldsm4(uint32_t& r0, uint32_t& r1,
                                      uint32_t& r2, uint32_t& r3, uint32_t a) {
    asm volatile("ldmatrix.sync.aligned.m8n8.x4.shared.b16 {%0,%1,%2,%3}, [%4];"
                 : "=r"(r0), "=r"(r1), "=r"(r2), "=r"(r3) : "r"(a));
}
__device__ __forceinline__ void ldsm4t(uint32_t& r0, uint32_t& r1,
                                       uint32_t& r2, uint32_t& r3, uint32_t a) {
    asm volatile("ldmatrix.sync.aligned.m8n8.x4.trans.shared.b16 {%0,%1,%2,%3}, [%4];"
                 : "=r"(r0), "=r"(r1), "=r"(r2), "=r"(r3) : "r"(a));
}
__device__ __forceinline__ void mma_bf16(float* c, const uint32_t* a,
                                         const uint32_t* b) {
    asm volatile(
        "mma.sync.aligned.m16n8k16.row.col.f32.bf16.bf16.f32 "
        "{%0,%1,%2,%3}, {%4,%5,%6,%7}, {%8,%9}, {%0,%1,%2,%3};"
        : "+f"(c[0]), "+f"(c[1]), "+f"(c[2]), "+f"(c[3])
        : "r"(a[0]), "r"(a[1]), "r"(a[2]), "r"(a[3]), "r"(b[0]), "r"(b[1]));
}
// fast exp2 on the FMA pipe (y <= 0; clamp makes masked rows vanish)
__device__ __forceinline__ float fexp2(float y) {
    y = fmaxf(y, -126.f);
    float fl = floorf(y);
    float f = y - fl;
    float p = 1.8775767e-3f;
    p = fmaf(p, f, 8.9893397e-3f);
    p = fmaf(p, f, 5.5826318e-2f);
    p = fmaf(p, f, 2.4015361e-1f);
    p = fmaf(p, f, 6.9315308e-1f);
    p = fmaf(p, f, 9.9999994e-1f);
    return __int_as_float(((int)fl + 127) << 23) * p;
}
__device__ __forceinline__ uint32_t pack_bf2(float a, float b) {
    __nv_bfloat162 v = __floats2bfloat162_rn(a, b);
    return *reinterpret_cast<uint32_t*>(&v);
}
__device__ __forceinline__ uint32_t pack_bf2_res(float a, float b, uint32_t hi) {
    __nv_bfloat162 hv = *reinterpret_cast<__nv_bfloat162*>(&hi);
    return pack_bf2(a - __bfloat162float(hv.x), b - __bfloat162float(hv.y));
}

// ---------------------------------------------------------------------------
// Split conversion: x -> (hi, lo) bf16
// ---------------------------------------------------------------------------
__global__ void split_kernel(const float* __restrict__ x,
                             __nv_bfloat16* __restrict__ hi,
                             __nv_bfloat16* __restrict__ lo, int n4)
{
    int i = blockIdx.x * 256 + threadIdx.x;
    if (i >= n4) return;
    float4 v = reinterpret_cast<const float4*>(x)[i];
    __nv_bfloat16 h0 = __float2bfloat16(v.x), h1 = __float2bfloat16(v.y);
    __nv_bfloat16 h2 = __float2bfloat16(v.z), h3 = __float2bfloat16(v.w);
    __nv_bfloat16 l0 = __float2bfloat16(v.x - __bfloat162float(h0));
    __nv_bfloat16 l1 = __float2bfloat16(v.y - __bfloat162float(h1));
    __nv_bfloat16 l2 = __float2bfloat16(v.z - __bfloat162float(h2));
    __nv_bfloat16 l3 = __float2bfloat16(v.w - __bfloat162float(h3));
    reinterpret_cast<__nv_bfloat162*>(hi)[i * 2 + 0] = __halves2bfloat162(h0, h1);
    reinterpret_cast<__nv_bfloat162*>(hi)[i * 2 + 1] = __halves2bfloat162(h2, h3);
    reinterpret_cast<__nv_bfloat162*>(lo)[i * 2 + 0] = __halves2bfloat162(l0, l1);
    reinterpret_cast<__nv_bfloat162*>(lo)[i * 2 + 1] = __halves2bfloat162(l2, l3);
}

// ---------------------------------------------------------------------------
// Transpose + split: W[K][N] fp32 -> T{hi,lo}[N][K] bf16
// ---------------------------------------------------------------------------
__global__ void tsplit_kernel(const float* __restrict__ W,
                              __nv_bfloat16* __restrict__ Thi,
                              __nv_bfloat16* __restrict__ Tlo, int K, int N)
{
    __shared__ float t[32][33];
    int tx = threadIdx.x, ty = threadIdx.y;
    int bx = blockIdx.x, by = blockIdx.y;
#pragma unroll
    for (int i = 0; i < 4; i++) {
        int r = by * 32 + ty + i * 8;
        t[ty + i * 8][tx] = W[(size_t)r * N + bx * 32 + tx];
    }
    __syncthreads();
#pragma unroll
    for (int i = 0; i < 4; i++) {
        int n = bx * 32 + ty + i * 8;
        int k = by * 32 + tx;
        float v = t[tx][ty + i * 8];
        __nv_bfloat16 h = __float2bfloat16(v);
        __nv_bfloat16 l = __float2bfloat16(v - __bfloat162float(h));
        Thi[(size_t)n * K + k] = h;
        Tlo[(size_t)n * K + k] = l;
    }
}

// ---------------------------------------------------------------------------
// RoPE + hi/lo split (+ optional scale), [bh][s][128] layout, pos == s.
// ---------------------------------------------------------------------------
__global__ void rope_split_kernel(const float* __restrict__ X,
                                  __nv_bfloat16* __restrict__ H,
                                  __nv_bfloat16* __restrict__ L,
                                  int total, float scale)
{
    int idx = blockIdx.x * 256 + threadIdx.x;
    if (idx >= total) return;
    int d = idx & 63;
    int s = (idx >> 6) & (Sn - 1);
    int bh = idx >> 17;
    float inv = powf(10000.f, -(float)d / 64.f);
    float ang = (float)s * inv;
    float sn, cs;
    sincosf(ang, &sn, &cs);
    size_t base = ((size_t)bh * Sn + s) * HDn;
    float x0 = X[base + d];
    float x1 = X[base + d + 64];
    float r0 = (x0 * cs - x1 * sn) * scale;
    float r1 = (x1 * cs + x0 * sn) * scale;
    __nv_bfloat16 h0 = __float2bfloat16(r0);
    __nv_bfloat16 h1 = __float2bfloat16(r1);
    H[base + d] = h0;
    H[base + d + 64] = h1;
    L[base + d] = __float2bfloat16(r0 - __bfloat162float(h0));
    L[base + d + 64] = __float2bfloat16(r1 - __bfloat162float(h1));
}

// ---------------------------------------------------------------------------
// bf16 split GEMM on mma.sync: CTA 128x128, K-chunk 32, 2-stage cp.async,
// 80 B/row (64 data + 16 pad). 2 CTAs/SM.
// MODE 0: C row-major; MODE 1: Q layout; MODE 2: KV layout;
// MODE 4: KV layout, K/V merged — blockIdx.z picks (B,C) vs (B2,C2).
// ---------------------------------------------------------------------------
constexpr int TROW = 80;                  // bytes per 32-element bf16 row
constexpr int TTILE = 128 * TROW;         // 10240 B
constexpr int TSTAGE = 4 * TTILE;         // 40960 B
constexpr int HG_SMEM = 2 * TSTAGE;       // 81920 B

template <int MODE>
__global__ __launch_bounds__(256, 2) void hgemm_kernel(
    const __nv_bfloat16* __restrict__ Ahi, const __nv_bfloat16* __restrict__ Alo,
    const __nv_bfloat16* __restrict__ Bhi, const __nv_bfloat16* __restrict__ Blo,
    const __nv_bfloat16* __restrict__ B2hi, const __nv_bfloat16* __restrict__ B2lo,
    float* __restrict__ C, float* __restrict__ C2, int N, int K)
{
    extern __shared__ char smem[];
    const uint32_t sb = smem_u32(smem);

    const int tid = threadIdx.x;
    const int wid = tid >> 5, lane = tid & 31;
    const int g = lane >> 2, t4 = lane & 3;
    const int wr = wid >> 2, wc = wid & 3;
    const int wm = wr * 64, wn = wc * 32;
    const int m0 = blockIdx.y * 128, n0 = blockIdx.x * 128;

    if (MODE == 4 && blockIdx.z == 1) { Bhi = B2hi; Blo = B2lo; C = C2; }

    const __nv_bfloat16* Ah = Ahi + (size_t)m0 * K;
    const __nv_bfloat16* Al = Alo + (size_t)m0 * K;
    const __nv_bfloat16* Bh = Bhi + (size_t)n0 * K;
    const __nv_bfloat16* Bl = Blo + (size_t)n0 * K;

    float c[4][4][4];
#pragma unroll
    for (int mi = 0; mi < 4; mi++)
#pragma unroll
        for (int ni = 0; ni < 4; ni++)
#pragma unroll
            for (int r = 0; r < 4; r++) c[mi][ni][r] = 0.f;

    auto load_chunk = [&](int stage, int koff) {
        const uint32_t base = sb + stage * TSTAGE;
#pragma unroll
        for (int i = 0; i < 8; i++) {
            const int tile = i >> 1;
            const int id = tid + (i & 1) * 256;
            const int r = id >> 2, c4 = id & 3;
            const __nv_bfloat16* s =
                (tile == 0) ? Ah : (tile == 1) ? Al : (tile == 2) ? Bh : Bl;
            cpa16(base + tile * TTILE + r * TROW + c4 * 16,
                  s + (size_t)r * K + koff + c4 * 8);
        }
        asm volatile("cp.async.commit_group;" ::: "memory");
    };

    const int NC = K / 32;
    load_chunk(0, 0);
    load_chunk(1, 32);

    const int arow_off = (lane & 7) + ((lane >> 3) & 1) * 8;
    const int acol_off = (lane >> 4) * 8;
    const int brow_off = (lane & 7) + (lane >> 4) * 8;
    const int bcol_off = ((lane >> 3) & 1) * 8;

    for (int ch = 0; ch < NC; ch++) {
        if (ch + 1 < NC)
            asm volatile("cp.async.wait_group 1;" ::: "memory");
        else
            asm volatile("cp.async.wait_group 0;" ::: "memory");
        __syncthreads();

        const uint32_t st = sb + (ch & 1) * TSTAGE;
        const uint32_t ah_b = st, al_b = st + TTILE;
        const uint32_t bh_b = st + 2 * TTILE, bl_b = st + 3 * TTILE;

#pragma unroll
        for (int kk = 0; kk < 32; kk += 16) {
            uint32_t fah[4][4], fal[4][4], fbh[4][2], fbl[4][2];
#pragma unroll
            for (int mi = 0; mi < 4; mi++) {
                const uint32_t ro = (wm + mi * 16 + arow_off) * TROW +
                                    (kk + acol_off) * 2;
                ldsm4(fah[mi][0], fah[mi][1], fah[mi][2], fah[mi][3], ah_b + ro);
                ldsm4(fal[mi][0], fal[mi][1], fal[mi][2], fal[mi][3], al_b + ro);
            }
#pragma unroll
            for (int bt = 0; bt < 2; bt++) {
                const uint32_t ro = (wn + bt * 16 + brow_off) * TROW +
                                    (kk + bcol_off) * 2;
                ldsm4(fbh[2 * bt][0], fbh[2 * bt][1],
                      fbh[2 * bt + 1][0], fbh[2 * bt + 1][1], bh_b + ro);
                ldsm4(fbl[2 * bt][0], fbl[2 * bt][1],
                      fbl[2 * bt + 1][0], fbl[2 * bt + 1][1], bl_b + ro);
            }
#pragma unroll
            for (int mi = 0; mi < 4; mi++)
#pragma unroll
                for (int ni = 0; ni < 4; ni++) {
                    mma_bf16(c[mi][ni], fah[mi], fbh[ni]);
                    mma_bf16(c[mi][ni], fah[mi], fbl[ni]);
                    mma_bf16(c[mi][ni], fal[mi], fbh[ni]);
                }
        }
        __syncthreads();
        if (ch + 2 < NC) load_chunk(ch & 1, (ch + 2) * 32);
    }

    // Epilogue: c-frag (g,2t4),(g,2t4+1),(g+8,2t4),(g+8,2t4+1)
    if (MODE == 0) {
#pragma unroll
        for (int mi = 0; mi < 4; mi++)
#pragma unroll
            for (int ni = 0; ni < 4; ni++) {
                const int row0 = m0 + wm + mi * 16 + g;
                const int col = n0 + wn + ni * 8 + 2 * t4;
#pragma unroll
                for (int half = 0; half < 2; half++) {
                    const int m = row0 + half * 8;
                    float2 v = half ? make_float2(c[mi][ni][2], c[mi][ni][3])
                                    : make_float2(c[mi][ni][0], c[mi][ni][1]);
                    *reinterpret_cast<float2*>(&C[(size_t)m * N + col]) = v;
                }
            }
    } else {
#pragma unroll
        for (int mi = 0; mi < 4; mi++)
#pragma unroll
            for (int ni = 0; ni < 4; ni++) {
                const int row0 = m0 + wm + mi * 16 + g;
                const int col = n0 + wn + ni * 8 + 2 * t4;
#pragma unroll
                for (int half = 0; half < 2; half++) {
                    const int m = row0 + half * 8;
                    float2 v = half ? make_float2(c[mi][ni][2], c[mi][ni][3])
                                    : make_float2(c[mi][ni][0], c[mi][ni][1]);
                    int b = m >> 11, s = m & 2047;
                    int h = col >> 7, d = col & 127;
                    const int heads = (MODE == 1) ? NHn : NKVn;
                    *reinterpret_cast<float2*>(
                        &C[(((size_t)(b * heads + h) * Sn) + s) * HDn + d]) = v;
                }
            }
    }
}

// ---------------------------------------------------------------------------
// Flash attention on mma.sync, bf16 split, BQ=128, BK=64, 8 warps,
// 2-stage pipeline. Output hi/lo bf16 straight into g_Xhi/g_Xlo (r7-proven).
// ---------------------------------------------------------------------------
constexpr int ARB = 272;                  // padded row bytes (136 bf16)
constexpr int KVT = 64 * ARB;             // one 64x128 bf16 tile = 17408 B
constexpr int ASTG = 4 * KVT;             // Kh,Kl,Vh,Vl per stage = 69632 B
constexpr int AT_SMEM = 2 * ASTG;         // 139264 B

__global__ __launch_bounds__(256, 1) void attn_mma_kernel()
{
    extern __shared__ char smem[];
    const uint32_t sb = smem_u32(smem);
    const int qt = blockIdx.x, h = blockIdx.y, b = blockIdx.z;
    const int tid = threadIdx.x, wid = tid >> 5, lane = tid & 31;
    const int g = lane >> 2, t4 = lane & 3;
    const int wm = wid * 16;
    const int kvh = h >> 2;
    const int NT = 2 * (qt + 1);

    const __nv_bfloat16* Qhp = g_Qh + ((size_t)(b * NHn + h) * Sn + qt * 128) * HDn;
    const __nv_bfloat16* Qlp = g_Ql + ((size_t)(b * NHn + h) * Sn + qt * 128) * HDn;
    const __nv_bfloat16* Khp = g_Kh + ((size_t)(b * NKVn + kvh) * Sn) * HDn;
    const __nv_bfloat16* Klp = g_Kl + ((size_t)(b * NKVn + kvh) * Sn) * HDn;
    const __nv_bfloat16* Vhp = g_Vh + ((size_t)(b * NKVn + kvh) * Sn) * HDn;
    const __nv_bfloat16* Vlp = g_Vl + ((size_t)(b * NKVn + kvh) * Sn) * HDn;

    const uint32_t qhb = sb + ASTG, qlb = sb + ASTG + 34816;
#pragma unroll
    for (int i = 0; i < 8; i++) {
        int id = tid + i * 256, r = id >> 4, c = id & 15;
        cpa16(qhb + r * ARB + c * 16, Qhp + r * HDn + c * 8);
        cpa16(qlb + r * ARB + c * 16, Qlp + r * HDn + c * 8);
    }
    asm volatile("cp.async.commit_group;" ::: "memory");

    auto load_stage = [&](int stg, int t) {
        const uint32_t st = sb + stg * ASTG;
        const __nv_bfloat16* kh = Khp + (size_t)t * 64 * HDn;
        const __nv_bfloat16* kl = Klp + (size_t)t * 64 * HDn;
        const __nv_bfloat16* vh = Vhp + (size_t)t * 64 * HDn;
        const __nv_bfloat16* vl = Vlp + (size_t)t * 64 * HDn;
#pragma unroll
        for (int i = 0; i < 4; i++) {
            int id = tid + i * 256, r = id >> 4, c = id & 15;
            cpa16(st + 0 * KVT + r * ARB + c * 16, kh + r * HDn + c * 8);
            cpa16(st + 1 * KVT + r * ARB + c * 16, kl + r * HDn + c * 8);
            cpa16(st + 2 * KVT + r * ARB + c * 16, vh + r * HDn + c * 8);
            cpa16(st + 3 * KVT + r * ARB + c * 16, vl + r * HDn + c * 8);
        }
        asm volatile("cp.async.commit_group;" ::: "memory");
    };
    load_stage(0, 0);

    asm volatile("cp.async.wait_group 1;" ::: "memory");  // Q arrived
    __syncthreads();

    const int arow = (lane & 7) + ((lane >> 3) & 1) * 8;
    const int acolB = (lane >> 4) * 16;
    uint32_t qhf[8][4], qlf[8][4];
#pragma unroll
    for (int ks = 0; ks < 8; ks++) {
        uint32_t ro = (wm + arow) * ARB + ks * 32 + acolB;
        ldsm4(qhf[ks][0], qhf[ks][1], qhf[ks][2], qhf[ks][3], qhb + ro);
        ldsm4(qlf[ks][0], qlf[ks][1], qlf[ks][2], qlf[ks][3], qlb + ro);
    }
    __syncthreads();
    load_stage(1, 1);

    float o[16][4];
#pragma unroll
    for (int j = 0; j < 16; j++)
#pragma unroll
        for (int e = 0; e < 4; e++) o[j][e] = 0.f;
    float m0 = -1e30f, m1 = -1e30f, l0 = 0.f, l1 = 0.f;

    const int brow = (lane & 7) + (lane >> 4) * 8;
    const int bcolB = ((lane >> 3) & 1) * 16;
    const int vcolB = (lane >> 4) * 16;
    const int row0g = qt * 128 + wm + g;

    for (int t = 0; t < NT; t++) {
        if (t + 1 < NT)
            asm volatile("cp.async.wait_group 1;" ::: "memory");
        else
            asm volatile("cp.async.wait_group 0;" ::: "memory");
        __syncthreads();
        const uint32_t st = sb + (t & 1) * ASTG;

        float s[8][4];
#pragma unroll
        for (int j = 0; j < 8; j++)
#pragma unroll
            for (int e = 0; e < 4; e++) s[j][e] = 0.f;

#pragma unroll
        for (int ks = 0; ks < 8; ks++) {
#pragma unroll
            for (int gr = 0; gr < 4; gr++) {
                uint32_t kh4[4], kl4[4];
                uint32_t ro = st + (gr * 16 + brow) * ARB + ks * 32 + bcolB;
                ldsm4(kh4[0], kh4[1], kh4[2], kh4[3], ro);
                ldsm4(kl4[0], kl4[1], kl4[2], kl4[3], ro + KVT);
                mma_bf16(s[2 * gr], qhf[ks], kh4);
                mma_bf16(s[2 * gr], qhf[ks], kl4);
                mma_bf16(s[2 * gr], qlf[ks], kh4);
                mma_bf16(s[2 * gr + 1], qhf[ks], kh4 + 2);
                mma_bf16(s[2 * gr + 1], qhf[ks], kl4 + 2);
                mma_bf16(s[2 * gr + 1], qlf[ks], kh4 + 2);
            }
        }

        if (t >= 2 * qt) {
#pragma unroll
            for (int j = 0; j < 8; j++) {
                int c0 = t * 64 + j * 8 + 2 * t4;
                if (c0 > row0g)     s[j][0] = -1e30f;
                if (c0 + 1 > row0g) s[j][1] = -1e30f;
                if (c0 > row0g + 8)     s[j][2] = -1e30f;
                if (c0 + 1 > row0g + 8) s[j][3] = -1e30f;
            }
        }

        float tm0 = -1e30f, tm1 = -1e30f;
#pragma unroll
        for (int j = 0; j < 8; j++) {
            tm0 = fmaxf(tm0, fmaxf(s[j][0], s[j][1]));
            tm1 = fmaxf(tm1, fmaxf(s[j][2], s[j][3]));
        }
        tm0 = fmaxf(tm0, __shfl_xor_sync(0xffffffffu, tm0, 1));
        tm0 = fmaxf(tm0, __shfl_xor_sync(0xffffffffu, tm0, 2));
        tm1 = fmaxf(tm1, __shfl_xor_sync(0xffffffffu, tm1, 1));
        tm1 = fmaxf(tm1, __shfl_xor_sync(0xffffffffu, tm1, 2));
        float mn0 = fmaxf(m0, tm0), mn1 = fmaxf(m1, tm1);
        float cor0 = fexp2((m0 - mn0) * L2E);
        float cor1 = fexp2((m1 - mn1) * L2E);
        m0 = mn0; m1 = mn1;
#pragma unroll
        for (int j = 0; j < 16; j++) {
            o[j][0] *= cor0; o[j][1] *= cor0;
            o[j][2] *= cor1; o[j][3] *= cor1;
        }
        float rs0 = 0.f, rs1 = 0.f;
#pragma unroll
        for (int j = 0; j < 8; j++) {
            s[j][0] = fexp2((s[j][0] - mn0) * L2E);
            s[j][1] = fexp2((s[j][1] - mn0) * L2E);
            s[j][2] = fexp2((s[j][2] - mn1) * L2E);
            s[j][3] = fexp2((s[j][3] - mn1) * L2E);
            rs0 += s[j][0] + s[j][1];
            rs1 += s[j][2] + s[j][3];
        }
        rs0 += __shfl_xor_sync(0xffffffffu, rs0, 1);
        rs0 += __shfl_xor_sync(0xffffffffu, rs0, 2);
        rs1 += __shfl_xor_sync(0xffffffffu, rs1, 1);
        rs1 += __shfl_xor_sync(0xffffffffu, rs1, 2);
        l0 = l0 * cor0 + rs0;
        l1 = l1 * cor1 + rs1;

#pragma unroll
        for (int ks = 0; ks < 4; ks++) {
            uint32_t pha[4], pla[4];
            pha[0] = pack_bf2(s[2 * ks][0], s[2 * ks][1]);
            pha[1] = pack_bf2(s[2 * ks][2], s[2 * ks][3]);
            pha[2] = pack_bf2(s[2 * ks + 1][0], s[2 * ks + 1][1]);
            pha[3] = pack_bf2(s[2 * ks + 1][2], s[2 * ks + 1][3]);
            pla[0] = pack_bf2_res(s[2 * ks][0], s[2 * ks][1], pha[0]);
            pla[1] = pack_bf2_res(s[2 * ks][2], s[2 * ks][3], pha[1]);
            pla[2] = pack_bf2_res(s[2 * ks + 1][0], s[2 * ks + 1][1], pha[2]);
            pla[3] = pack_bf2_res(s[2 * ks + 1][2], s[2 * ks + 1][3], pha[3]);
#pragma unroll
            for (int gr = 0; gr < 8; gr++) {
                uint32_t vh4[4], vl4[4];
                uint32_t ro = st + 2 * KVT + (ks * 16 + arow) * ARB +
                              gr * 32 + vcolB;
                ldsm4t(vh4[0], vh4[1], vh4[2], vh4[3], ro);
                ldsm4t(vl4[0], vl4[1], vl4[2], vl4[3], ro + KVT);
                mma_bf16(o[2 * gr], pha, vh4);
                mma_bf16(o[2 * gr], pha, vl4);
                mma_bf16(o[2 * gr], pla, vh4);
                mma_bf16(o[2 * gr + 1], pha, vh4 + 2);
                mma_bf16(o[2 * gr + 1], pha, vl4 + 2);
                mma_bf16(o[2 * gr + 1], pla, vh4 + 2);
            }
        }
        __syncthreads();
        if (t + 2 < NT) load_stage(t & 1, t + 2);
    }

    // ---- epilogue: normalize, split hi/lo, write g_Xhi/g_Xlo [b][s][h*d] ----
    float inv0 = 1.f / l0, inv1 = 1.f / l1;
    const int r0 = qt * 128 + wm + g, r1 = r0 + 8;
#pragma unroll
    for (int j = 0; j < 16; j++) {
        int col = h * 128 + j * 8 + 2 * t4;
        float a0 = o[j][0] * inv0, a1 = o[j][1] * inv0;
        float b0 = o[j][2] * inv1, b1 = o[j][3] * inv1;
        size_t i0 = ((size_t)(b * Sn + r0)) * 4096 + col;
        size_t i1 = ((size_t)(b * Sn + r1)) * 4096 + col;
        uint32_t h0 = pack_bf2(a0, a1);
        uint32_t h1 = pack_bf2(b0, b1);
        *reinterpret_cast<uint32_t*>(&g_Xhi[i0]) = h0;
        *reinterpret_cast<uint32_t*>(&g_Xlo[i0]) = pack_bf2_res(a0, a1, h0);
        *reinterpret_cast<uint32_t*>(&g_Xhi[i1]) = h1;
        *reinterpret_cast<uint32_t*>(&g_Xlo[i1]) = pack_bf2_res(b0, b1, h1);
    }
}

// ---------------------------------------------------------------------------
extern "C" void kernel_launch(void* const* d_in, const int* in_sizes, int n_in,
                              void* d_out, int out_size)
{
    const float* hidden = (const float*)d_in[0];
    const float* Wq = (const float*)d_in[2];
    const float* Wk = (const float*)d_in[3];
    const float* Wv = (const float*)d_in[4];
    const float* Wo = (const float*)d_in[5];
    float* out = (float*)d_out;

    float *pQ, *pK, *pV;
    __nv_bfloat16 *pXh, *pXl, *pQTh, *pQTl, *pKTh, *pKTl, *pVTh, *pVTl, *pOTh, *pOTl;
    __nv_bfloat16 *pQh, *pQl, *pKh, *pKl, *pVh, *pVl;
    cudaGetSymbolAddress((void**)&pQ, g_Q);
    cudaGetSymbolAddress((void**)&pK, g_K);
    cudaGetSymbolAddress((void**)&pV, g_V);
    cudaGetSymbolAddress((void**)&pXh, g_Xhi);
    cudaGetSymbolAddress((void**)&pXl, g_Xlo);
    cudaGetSymbolAddress((void**)&pQTh, g_WqThi);
    cudaGetSymbolAddress((void**)&pQTl, g_WqTlo);
    cudaGetSymbolAddress((void**)&pKTh, g_WkThi);
    cudaGetSymbolAddress((void**)&pKTl, g_WkTlo);
    cudaGetSymbolAddress((void**)&pVTh, g_WvThi);
    cudaGetSymbolAddress((void**)&pVTl, g_WvTlo);
    cudaGetSymbolAddress((void**)&pOTh, g_WoThi);
    cudaGetSymbolAddress((void**)&pOTl, g_WoTlo);
    cudaGetSymbolAddress((void**)&pQh, g_Qh);
    cudaGetSymbolAddress((void**)&pQl, g_Ql);
    cudaGetSymbolAddress((void**)&pKh, g_Kh);
    cudaGetSymbolAddress((void**)&pKl, g_Kl);
    cudaGetSymbolAddress((void**)&pVh, g_Vh);
    cudaGetSymbolAddress((void**)&pVl, g_Vl);

    cudaFuncSetAttribute(hgemm_kernel<0>,
                         cudaFuncAttributeMaxDynamicSharedMemorySize, HG_SMEM);
    cudaFuncSetAttribute(hgemm_kernel<1>,
                         cudaFuncAttributeMaxDynamicSharedMemorySize, HG_SMEM);
    cudaFuncSetAttribute(hgemm_kernel<4>,
                         cudaFuncAttributeMaxDynamicSharedMemorySize, HG_SMEM);
    cudaFuncSetAttribute(attn_mma_kernel,
                         cudaFuncAttributeMaxDynamicSharedMemorySize, AT_SMEM);

    const int n4x = Mn * Hn / 4;
    dim3 tb(32, 8);

    // Launch order: Q-projection GEMM is launch #4 (ncu capture slot).
    split_kernel<<<n4x / 256, 256>>>(hidden, pXh, pXl, n4x);                     // 1
    tsplit_kernel<<<dim3(4096 / 32, 4096 / 32), tb>>>(Wq, pQTh, pQTl, Hn, 4096); // 2
    tsplit_kernel<<<dim3(1024 / 32, 4096 / 32), tb>>>(Wk, pKTh, pKTl, Hn, 1024); // 3
    hgemm_kernel<1><<<dim3(4096 / 128, Mn / 128), 256, HG_SMEM>>>(               // 4 <- profiled
        pXh, pXl, pQTh, pQTl, nullptr, nullptr, pQ, nullptr, 4096, Hn);
    tsplit_kernel<<<dim3(1024 / 32, 4096 / 32), tb>>>(Wv, pVTh, pVTl, Hn, 1024); // 5
    tsplit_kernel<<<dim3(4096 / 32, 4096 / 32), tb>>>(Wo, pOTh, pOTl, 4096, Hn); // 6
    hgemm_kernel<4><<<dim3(1024 / 128, Mn / 128, 2), 256, HG_SMEM>>>(            // 7 (K+V merged)
        pXh, pXl, pKTh, pKTl, pVTh, pVTl, pK, pV, 1024, Hn);

    // RoPE + split (Q gets QK_SCALE folded in); V split
    int totQ = Bn * NHn * Sn * 64;
    int totK = Bn * NKVn * Sn * 64;
    rope_split_kernel<<<totQ / 256, 256>>>(pQ, pQh, pQl, totQ, QK_SCALE);        // 8
    rope_split_kernel<<<totK / 256, 256>>>(pK, pKh, pKl, totK, 1.f);             // 9
    const int nv4 = Bn * NKVn * Sn * HDn / 4;
    split_kernel<<<nv4 / 256, 256>>>(pV, pVh, pVl, nv4);                         // 10

    // causal flash attention (writes hi/lo output into g_Xhi/g_Xlo)
    dim3 ga(Sn / 128, NHn, Bn);
    attn_mma_kernel<<<ga, 256, AT_SMEM>>>();                                     // 11

    // output projection (reads g_Xhi/g_Xlo written by attention)
    hgemm_kernel<0><<<dim3(4096 / 128, Mn / 128), 256, HG_SMEM>>>(               // 12
        pXh, pXl, pOTh, pOTl, nullptr, nullptr, out, nullptr, 4096, Hn);
}

// round 13
// speedup vs baseline: 2.4471x; 1.3693x over previous
#include <cuda_runtime.h>
#include <cuda_fp16.h>
#include <math.h>
#include <stdint.h>

// Problem dims
constexpr int Bn = 2, Sn = 2048, Hn = 4096, NHn = 32, NKVn = 8, HDn = 128;
constexpr int Mn = Bn * Sn;
constexpr float QK_SCALE = 0.08838834764831845f; // 1/sqrt(128)
constexpr float L2E = 1.4426950408889634f;

// fp32 scratch (pre-RoPE projection outputs)
__device__ float g_Q[(size_t)Bn * NHn * Sn * HDn];   // [b][h][s][d]
__device__ float g_K[(size_t)Bn * NKVn * Sn * HDn];  // [b][kh][s][d]
__device__ float g_V[(size_t)Bn * NKVn * Sn * HDn];

// fp16 split scratch (A-side: hi+lo; B-side: hi only)
__device__ __half g_Xhi[(size_t)Mn * Hn];   // X split; reused for attn out
__device__ __half g_Xlo[(size_t)Mn * Hn];
__device__ __half g_WqTh[(size_t)4096 * 4096];
__device__ __half g_WkTh[(size_t)1024 * 4096];
__device__ __half g_WvTh[(size_t)1024 * 4096];
__device__ __half g_WoTh[(size_t)4096 * 4096];
// attention operands (post-RoPE): Q hi+lo (A-side), K/V hi only (B-side)
__device__ __half g_Qh[(size_t)Bn * NHn * Sn * HDn];
__device__ __half g_Ql[(size_t)Bn * NHn * Sn * HDn];
__device__ __half g_Kh[(size_t)Bn * NKVn * Sn * HDn];
__device__ __half g_Vh[(size_t)Bn * NKVn * Sn * HDn];

// ---------------------------------------------------------------------------
// helpers
// ---------------------------------------------------------------------------
__device__ __forceinline__ uint32_t smem_u32(const void* p) {
    uint32_t a;
    asm("{ .reg .u64 t; cvta.to.shared.u64 t, %1; cvt.u32.u64 %0, t; }"
        : "=r"(a) : "l"(p));
    return a;
}
__device__ __forceinline__ void cpa16(uint32_t dst, const void* src) {
    asm volatile("cp.async.cg.shared.global [%0], [%1], 16;"
                 :: "r"(dst), "l"(src) : "memory");
}
__device__ __forceinline__ void ldsm4(uint32_t& r0, uint32_t& r1,
                                      uint32_t& r2, uint32_t& r3, uint32_t a) {
    asm volatile("ldmatrix.sync.aligned.m8n8.x4.shared.b16 {%0,%1,%2,%3}, [%4];"
                 : "=r"(r0), "=r"(r1), "=r"(r2), "=r"(r3) : "r"(a));
}
__device__ __forceinline__ void ldsm4t(uint32_t& r0, uint32_t& r1,
                                       uint32_t& r2, uint32_t& r3, uint32_t a) {
    asm volatile("ldmatrix.sync.aligned.m8n8.x4.trans.shared.b16 {%0,%1,%2,%3}, [%4];"
                 : "=r"(r0), "=r"(r1), "=r"(r2), "=r"(r3) : "r"(a));
}
__device__ __forceinline__ void mma_f16(float* c, const uint32_t* a,
                                        const uint32_t* b) {
    asm volatile(
        "mma.sync.aligned.m16n8k16.row.col.f32.f16.f16.f32 "
        "{%0,%1,%2,%3}, {%4,%5,%6,%7}, {%8,%9}, {%0,%1,%2,%3};"
        : "+f"(c[0]), "+f"(c[1]), "+f"(c[2]), "+f"(c[3])
        : "r"(a[0]), "r"(a[1]), "r"(a[2]), "r"(a[3]), "r"(b[0]), "r"(b[1]));
}
// fast exp2 on the FMA pipe (y <= 0; clamp makes masked rows vanish)
__device__ __forceinline__ float fexp2(float y) {
    y = fmaxf(y, -126.f);
    float fl = floorf(y);
    float f = y - fl;
    float p = 1.8775767e-3f;
    p = fmaf(p, f, 8.9893397e-3f);
    p = fmaf(p, f, 5.5826318e-2f);
    p = fmaf(p, f, 2.4015361e-1f);
    p = fmaf(p, f, 6.9315308e-1f);
    p = fmaf(p, f, 9.9999994e-1f);
    return __int_as_float(((int)fl + 127) << 23) * p;
}
__device__ __forceinline__ uint32_t pack_h2(float a, float b) {
    __half2 v = __floats2half2_rn(a, b);
    return *reinterpret_cast<uint32_t*>(&v);
}
__device__ __forceinline__ uint32_t pack_h2_res(float a, float b, uint32_t hi) {
    __half2 hv = *reinterpret_cast<__half2*>(&hi);
    return pack_h2(a - __half2float(hv.x), b - __half2float(hv.y));
}

// ---------------------------------------------------------------------------
// Split conversion: x -> hi fp16 (+ optional lo fp16)
// ---------------------------------------------------------------------------
__global__ void split_kernel(const float* __restrict__ x,
                             __half* __restrict__ hi,
                             __half* __restrict__ lo, int n4)
{
    int i = blockIdx.x * 256 + threadIdx.x;
    if (i >= n4) return;
    float4 v = reinterpret_cast<const float4*>(x)[i];
    uint32_t h01 = pack_h2(v.x, v.y);
    uint32_t h23 = pack_h2(v.z, v.w);
    reinterpret_cast<uint32_t*>(hi)[i * 2 + 0] = h01;
    reinterpret_cast<uint32_t*>(hi)[i * 2 + 1] = h23;
    if (lo) {
        reinterpret_cast<uint32_t*>(lo)[i * 2 + 0] = pack_h2_res(v.x, v.y, h01);
        reinterpret_cast<uint32_t*>(lo)[i * 2 + 1] = pack_h2_res(v.z, v.w, h23);
    }
}

// ---------------------------------------------------------------------------
// Transpose + fp16 truncation: W[K][N] fp32 -> Th[N][K] fp16 (hi only)
// ---------------------------------------------------------------------------
__global__ void tsplit_kernel(const float* __restrict__ W,
                              __half* __restrict__ Thi, int K, int N)
{
    __shared__ float t[32][33];
    int tx = threadIdx.x, ty = threadIdx.y;
    int bx = blockIdx.x, by = blockIdx.y;
#pragma unroll
    for (int i = 0; i < 4; i++) {
        int r = by * 32 + ty + i * 8;
        t[ty + i * 8][tx] = W[(size_t)r * N + bx * 32 + tx];
    }
    __syncthreads();
#pragma unroll
    for (int i = 0; i < 4; i++) {
        int n = bx * 32 + ty + i * 8;
        int k = by * 32 + tx;
        Thi[(size_t)n * K + k] = __float2half_rn(t[tx][ty + i * 8]);
    }
}

// ---------------------------------------------------------------------------
// RoPE + fp16 hi (+ optional lo) split, [bh][s][128] layout, pos == s.
// ---------------------------------------------------------------------------
__global__ void rope_split_kernel(const float* __restrict__ X,
                                  __half* __restrict__ H,
                                  __half* __restrict__ L,
                                  int total, float scale)
{
    int idx = blockIdx.x * 256 + threadIdx.x;
    if (idx >= total) return;
    int d = idx & 63;
    int s = (idx >> 6) & (Sn - 1);
    int bh = idx >> 17;
    float inv = powf(10000.f, -(float)d / 64.f);
    float ang = (float)s * inv;
    float sn, cs;
    sincosf(ang, &sn, &cs);
    size_t base = ((size_t)bh * Sn + s) * HDn;
    float x0 = X[base + d];
    float x1 = X[base + d + 64];
    float r0 = (x0 * cs - x1 * sn) * scale;
    float r1 = (x1 * cs + x0 * sn) * scale;
    __half h0 = __float2half_rn(r0);
    __half h1 = __float2half_rn(r1);
    H[base + d] = h0;
    H[base + d + 64] = h1;
    if (L) {
        L[base + d] = __float2half_rn(r0 - __half2float(h0));
        L[base + d + 64] = __float2half_rn(r1 - __half2float(h1));
    }
}

// ---------------------------------------------------------------------------
// fp16 2-pass GEMM on mma.sync: C = (Ah+Al) @ Bh^T.  CTA 128x128, K-chunk 32,
// 2-stage cp.async, 80 B/row. 3 tiles/chunk (Ah, Al, Bh). 2 CTAs/SM.
// MODE 0: C row-major; MODE 1: Q layout; MODE 4: KV layout, K/V merged via z.
// ---------------------------------------------------------------------------
constexpr int TROW = 80;                  // bytes per 32-element fp16 row
constexpr int TTILE = 128 * TROW;         // 10240 B
constexpr int TSTAGE = 3 * TTILE;         // 30720 B (Ah, Al, Bh)
constexpr int HG_SMEM = 2 * TSTAGE;       // 61440 B

template <int MODE>
__global__ __launch_bounds__(256, 2) void hgemm_kernel(
    const __half* __restrict__ Ahi, const __half* __restrict__ Alo,
    const __half* __restrict__ Bh0, const __half* __restrict__ B2h,
    float* __restrict__ C, float* __restrict__ C2, int N, int K)
{
    extern __shared__ char smem[];
    const uint32_t sb = smem_u32(smem);

    const int tid = threadIdx.x;
    const int wid = tid >> 5, lane = tid & 31;
    const int g = lane >> 2, t4 = lane & 3;
    const int wr = wid >> 2, wc = wid & 3;
    const int wm = wr * 64, wn = wc * 32;
    const int m0 = blockIdx.y * 128, n0 = blockIdx.x * 128;

    const __half* Bsel = (MODE == 4 && blockIdx.z == 1) ? B2h : Bh0;
    float* Csel = (MODE == 4 && blockIdx.z == 1) ? C2 : C;

    const __half* Ah = Ahi + (size_t)m0 * K;
    const __half* Al = Alo + (size_t)m0 * K;
    const __half* Bh = Bsel + (size_t)n0 * K;

    float c[4][4][4];
#pragma unroll
    for (int mi = 0; mi < 4; mi++)
#pragma unroll
        for (int ni = 0; ni < 4; ni++)
#pragma unroll
            for (int r = 0; r < 4; r++) c[mi][ni][r] = 0.f;

    // per-chunk load: 3 tiles x 128 rows x 4 chunks(16B) = 1536 cpa16
    auto load_chunk = [&](int stage, int koff) {
        const uint32_t base = sb + stage * TSTAGE;
#pragma unroll
        for (int i = 0; i < 6; i++) {
            const int tile = i >> 1;
            const int id = tid + (i & 1) * 256;
            const int r = id >> 2, c4 = id & 3;
            const __half* s = (tile == 0) ? Ah : (tile == 1) ? Al : Bh;
            cpa16(base + tile * TTILE + r * TROW + c4 * 16,
                  s + (size_t)r * K + koff + c4 * 8);
        }
        asm volatile("cp.async.commit_group;" ::: "memory");
    };

    const int NC = K / 32;
    load_chunk(0, 0);
    load_chunk(1, 32);

    const int arow_off = (lane & 7) + ((lane >> 3) & 1) * 8;
    const int acol_off = (lane >> 4) * 8;
    const int brow_off = (lane & 7) + (lane >> 4) * 8;
    const int bcol_off = ((lane >> 3) & 1) * 8;

    for (int ch = 0; ch < NC; ch++) {
        if (ch + 1 < NC)
            asm volatile("cp.async.wait_group 1;" ::: "memory");
        else
            asm volatile("cp.async.wait_group 0;" ::: "memory");
        __syncthreads();

        const uint32_t st = sb + (ch & 1) * TSTAGE;
        const uint32_t ah_b = st, al_b = st + TTILE, bh_b = st + 2 * TTILE;

#pragma unroll
        for (int kk = 0; kk < 32; kk += 16) {
            uint32_t fah[4][4], fal[4][4], fbh[4][2];
#pragma unroll
            for (int mi = 0; mi < 4; mi++) {
                const uint32_t ro = (wm + mi * 16 + arow_off) * TROW +
                                    (kk + acol_off) * 2;
                ldsm4(fah[mi][0], fah[mi][1], fah[mi][2], fah[mi][3], ah_b + ro);
                ldsm4(fal[mi][0], fal[mi][1], fal[mi][2], fal[mi][3], al_b + ro);
            }
#pragma unroll
            for (int bt = 0; bt < 2; bt++) {
                const uint32_t ro = (wn + bt * 16 + brow_off) * TROW +
                                    (kk + bcol_off) * 2;
                ldsm4(fbh[2 * bt][0], fbh[2 * bt][1],
                      fbh[2 * bt + 1][0], fbh[2 * bt + 1][1], bh_b + ro);
            }
#pragma unroll
            for (int mi = 0; mi < 4; mi++)
#pragma unroll
                for (int ni = 0; ni < 4; ni++) {
                    mma_f16(c[mi][ni], fah[mi], fbh[ni]);
                    mma_f16(c[mi][ni], fal[mi], fbh[ni]);
                }
        }
        __syncthreads();
        if (ch + 2 < NC) load_chunk(ch & 1, (ch + 2) * 32);
    }

    // Epilogue: c-frag (g,2t4),(g,2t4+1),(g+8,2t4),(g+8,2t4+1)
    if (MODE == 0) {
#pragma unroll
        for (int mi = 0; mi < 4; mi++)
#pragma unroll
            for (int ni = 0; ni < 4; ni++) {
                const int row0 = m0 + wm + mi * 16 + g;
                const int col = n0 + wn + ni * 8 + 2 * t4;
#pragma unroll
                for (int half = 0; half < 2; half++) {
                    const int m = row0 + half * 8;
                    float2 v = half ? make_float2(c[mi][ni][2], c[mi][ni][3])
                                    : make_float2(c[mi][ni][0], c[mi][ni][1]);
                    *reinterpret_cast<float2*>(&Csel[(size_t)m * N + col]) = v;
                }
            }
    } else {
#pragma unroll
        for (int mi = 0; mi < 4; mi++)
#pragma unroll
            for (int ni = 0; ni < 4; ni++) {
                const int row0 = m0 + wm + mi * 16 + g;
                const int col = n0 + wn + ni * 8 + 2 * t4;
#pragma unroll
                for (int half = 0; half < 2; half++) {
                    const int m = row0 + half * 8;
                    float2 v = half ? make_float2(c[mi][ni][2], c[mi][ni][3])
                                    : make_float2(c[mi][ni][0], c[mi][ni][1]);
                    int b = m >> 11, s = m & 2047;
                    int h = col >> 7, d = col & 127;
                    const int heads = (MODE == 1) ? NHn : NKVn;
                    *reinterpret_cast<float2*>(
                        &Csel[(((size_t)(b * heads + h) * Sn) + s) * HDn + d]) = v;
                }
            }
    }
}

// ---------------------------------------------------------------------------
// Flash attention, fp16 2-pass: scores = (Qh+Ql)·Kh, O = (Ph+Pl)·Vh.
// BQ=128, BK=64, 8 warps, 2-stage pipeline (Kh+Vh per stage).
// Output hi/lo fp16 straight into g_Xhi/g_Xlo.
// ---------------------------------------------------------------------------
constexpr int ARB = 272;                  // padded row bytes (136 fp16)
constexpr int KVT = 64 * ARB;             // one 64x128 fp16 tile = 17408 B
constexpr int ASTG = 2 * KVT;             // Kh, Vh per stage = 34816 B
constexpr int AT_SMEM = 2 * ASTG + 2 * 34816;  // 2 stages + Qh + Ql = 139264 B

__global__ __launch_bounds__(256, 1) void attn_mma_kernel()
{
    extern __shared__ char smem[];
    const uint32_t sb = smem_u32(smem);
    const int qt = blockIdx.x, h = blockIdx.y, b = blockIdx.z;
    const int tid = threadIdx.x, wid = tid >> 5, lane = tid & 31;
    const int g = lane >> 2, t4 = lane & 3;
    const int wm = wid * 16;
    const int kvh = h >> 2;
    const int NT = 2 * (qt + 1);

    const __half* Qhp = g_Qh + ((size_t)(b * NHn + h) * Sn + qt * 128) * HDn;
    const __half* Qlp = g_Ql + ((size_t)(b * NHn + h) * Sn + qt * 128) * HDn;
    const __half* Khp = g_Kh + ((size_t)(b * NKVn + kvh) * Sn) * HDn;
    const __half* Vhp = g_Vh + ((size_t)(b * NKVn + kvh) * Sn) * HDn;

    const uint32_t qhb = sb + 2 * ASTG, qlb = sb + 2 * ASTG + 34816;
#pragma unroll
    for (int i = 0; i < 8; i++) {
        int id = tid + i * 256, r = id >> 4, c = id & 15;
        cpa16(qhb + r * ARB + c * 16, Qhp + r * HDn + c * 8);
        cpa16(qlb + r * ARB + c * 16, Qlp + r * HDn + c * 8);
    }
    asm volatile("cp.async.commit_group;" ::: "memory");

    auto load_stage = [&](int stg, int t) {
        const uint32_t st = sb + stg * ASTG;
        const __half* kh = Khp + (size_t)t * 64 * HDn;
        const __half* vh = Vhp + (size_t)t * 64 * HDn;
#pragma unroll
        for (int i = 0; i < 4; i++) {
            int id = tid + i * 256, r = id >> 4, c = id & 15;
            cpa16(st + 0 * KVT + r * ARB + c * 16, kh + r * HDn + c * 8);
            cpa16(st + 1 * KVT + r * ARB + c * 16, vh + r * HDn + c * 8);
        }
        asm volatile("cp.async.commit_group;" ::: "memory");
    };
    load_stage(0, 0);

    asm volatile("cp.async.wait_group 1;" ::: "memory");  // Q arrived
    __syncthreads();

    const int arow = (lane & 7) + ((lane >> 3) & 1) * 8;
    const int acolB = (lane >> 4) * 16;
    uint32_t qhf[8][4], qlf[8][4];
#pragma unroll
    for (int ks = 0; ks < 8; ks++) {
        uint32_t ro = (wm + arow) * ARB + ks * 32 + acolB;
        ldsm4(qhf[ks][0], qhf[ks][1], qhf[ks][2], qhf[ks][3], qhb + ro);
        ldsm4(qlf[ks][0], qlf[ks][1], qlf[ks][2], qlf[ks][3], qlb + ro);
    }
    __syncthreads();
    load_stage(1, 1);

    float o[16][4];
#pragma unroll
    for (int j = 0; j < 16; j++)
#pragma unroll
        for (int e = 0; e < 4; e++) o[j][e] = 0.f;
    float m0 = -1e30f, m1 = -1e30f, l0 = 0.f, l1 = 0.f;

    const int brow = (lane & 7) + (lane >> 4) * 8;
    const int bcolB = ((lane >> 3) & 1) * 16;
    const int vcolB = (lane >> 4) * 16;
    const int row0g = qt * 128 + wm + g;

    for (int t = 0; t < NT; t++) {
        if (t + 1 < NT)
            asm volatile("cp.async.wait_group 1;" ::: "memory");
        else
            asm volatile("cp.async.wait_group 0;" ::: "memory");
        __syncthreads();
        const uint32_t st = sb + (t & 1) * ASTG;

        float s[8][4];
#pragma unroll
        for (int j = 0; j < 8; j++)
#pragma unroll
            for (int e = 0; e < 4; e++) s[j][e] = 0.f;

#pragma unroll
        for (int ks = 0; ks < 8; ks++) {
#pragma unroll
            for (int gr = 0; gr < 4; gr++) {
                uint32_t kh4[4];
                uint32_t ro = st + (gr * 16 + brow) * ARB + ks * 32 + bcolB;
                ldsm4(kh4[0], kh4[1], kh4[2], kh4[3], ro);
                mma_f16(s[2 * gr], qhf[ks], kh4);
                mma_f16(s[2 * gr], qlf[ks], kh4);
                mma_f16(s[2 * gr + 1], qhf[ks], kh4 + 2);
                mma_f16(s[2 * gr + 1], qlf[ks], kh4 + 2);
            }
        }

        if (t >= 2 * qt) {
#pragma unroll
            for (int j = 0; j < 8; j++) {
                int c0 = t * 64 + j * 8 + 2 * t4;
                if (c0 > row0g)     s[j][0] = -1e30f;
                if (c0 + 1 > row0g) s[j][1] = -1e30f;
                if (c0 > row0g + 8)     s[j][2] = -1e30f;
                if (c0 + 1 > row0g + 8) s[j][3] = -1e30f;
            }
        }

        float tm0 = -1e30f, tm1 = -1e30f;
#pragma unroll
        for (int j = 0; j < 8; j++) {
            tm0 = fmaxf(tm0, fmaxf(s[j][0], s[j][1]));
            tm1 = fmaxf(tm1, fmaxf(s[j][2], s[j][3]));
        }
        tm0 = fmaxf(tm0, __shfl_xor_sync(0xffffffffu, tm0, 1));
        tm0 = fmaxf(tm0, __shfl_xor_sync(0xffffffffu, tm0, 2));
        tm1 = fmaxf(tm1, __shfl_xor_sync(0xffffffffu, tm1, 1));
        tm1 = fmaxf(tm1, __shfl_xor_sync(0xffffffffu, tm1, 2));
        float mn0 = fmaxf(m0, tm0), mn1 = fmaxf(m1, tm1);
        float cor0 = fexp2((m0 - mn0) * L2E);
        float cor1 = fexp2((m1 - mn1) * L2E);
        m0 = mn0; m1 = mn1;
#pragma unroll
        for (int j = 0; j < 16; j++) {
            o[j][0] *= cor0; o[j][1] *= cor0;
            o[j][2] *= cor1; o[j][3] *= cor1;
        }
        float rs0 = 0.f, rs1 = 0.f;
#pragma unroll
        for (int j = 0; j < 8; j++) {
            s[j][0] = fexp2((s[j][0] - mn0) * L2E);
            s[j][1] = fexp2((s[j][1] - mn0) * L2E);
            s[j][2] = fexp2((s[j][2] - mn1) * L2E);
            s[j][3] = fexp2((s[j][3] - mn1) * L2E);
            rs0 += s[j][0] + s[j][1];
            rs1 += s[j][2] + s[j][3];
        }
        rs0 += __shfl_xor_sync(0xffffffffu, rs0, 1);
        rs0 += __shfl_xor_sync(0xffffffffu, rs0, 2);
        rs1 += __shfl_xor_sync(0xffffffffu, rs1, 1);
        rs1 += __shfl_xor_sync(0xffffffffu, rs1, 2);
        l0 = l0 * cor0 + rs0;
        l1 = l1 * cor1 + rs1;

#pragma unroll
        for (int ks = 0; ks < 4; ks++) {
            uint32_t pha[4], pla[4];
            pha[0] = pack_h2(s[2 * ks][0], s[2 * ks][1]);
            pha[1] = pack_h2(s[2 * ks][2], s[2 * ks][3]);
            pha[2] = pack_h2(s[2 * ks + 1][0], s[2 * ks + 1][1]);
            pha[3] = pack_h2(s[2 * ks + 1][2], s[2 * ks + 1][3]);
            pla[0] = pack_h2_res(s[2 * ks][0], s[2 * ks][1], pha[0]);
            pla[1] = pack_h2_res(s[2 * ks][2], s[2 * ks][3], pha[1]);
            pla[2] = pack_h2_res(s[2 * ks + 1][0], s[2 * ks + 1][1], pha[2]);
            pla[3] = pack_h2_res(s[2 * ks + 1][2], s[2 * ks + 1][3], pha[3]);
#pragma unroll
            for (int gr = 0; gr < 8; gr++) {
                uint32_t vh4[4];
                uint32_t ro = st + KVT + (ks * 16 + arow) * ARB +
                              gr * 32 + vcolB;
                ldsm4t(vh4[0], vh4[1], vh4[2], vh4[3], ro);
                mma_f16(o[2 * gr], pha, vh4);
                mma_f16(o[2 * gr], pla, vh4);
                mma_f16(o[2 * gr + 1], pha, vh4 + 2);
                mma_f16(o[2 * gr + 1], pla, vh4 + 2);
            }
        }
        __syncthreads();
        if (t + 2 < NT) load_stage(t & 1, t + 2);
    }

    // ---- epilogue: normalize, split hi/lo, write g_Xhi/g_Xlo [b][s][h*d] ----
    float inv0 = 1.f / l0, inv1 = 1.f / l1;
    const int r0 = qt * 128 + wm + g, r1 = r0 + 8;
#pragma unroll
    for (int j = 0; j < 16; j++) {
        int col = h * 128 + j * 8 + 2 * t4;
        float a0 = o[j][0] * inv0, a1 = o[j][1] * inv0;
        float b0 = o[j][2] * inv1, b1 = o[j][3] * inv1;
        size_t i0 = ((size_t)(b * Sn + r0)) * 4096 + col;
        size_t i1 = ((size_t)(b * Sn + r1)) * 4096 + col;
        uint32_t h0 = pack_h2(a0, a1);
        uint32_t h1 = pack_h2(b0, b1);
        *reinterpret_cast<uint32_t*>(&g_Xhi[i0]) = h0;
        *reinterpret_cast<uint32_t*>(&g_Xlo[i0]) = pack_h2_res(a0, a1, h0);
        *reinterpret_cast<uint32_t*>(&g_Xhi[i1]) = h1;
        *reinterpret_cast<uint32_t*>(&g_Xlo[i1]) = pack_h2_res(b0, b1, h1);
    }
}

// ---------------------------------------------------------------------------
extern "C" void kernel_launch(void* const* d_in, const int* in_sizes, int n_in,
                              void* d_out, int out_size)
{
    const float* hidden = (const float*)d_in[0];
    const float* Wq = (const float*)d_in[2];
    const float* Wk = (const float*)d_in[3];
    const float* Wv = (const float*)d_in[4];
    const float* Wo = (const float*)d_in[5];
    float* out = (float*)d_out;

    float *pQ, *pK, *pV;
    __half *pXh, *pXl, *pQT, *pKT, *pVT, *pOT, *pQh, *pQl, *pKh, *pVh;
    cudaGetSymbolAddress((void**)&pQ, g_Q);
    cudaGetSymbolAddress((void**)&pK, g_K);
    cudaGetSymbolAddress((void**)&pV, g_V);
    cudaGetSymbolAddress((void**)&pXh, g_Xhi);
    cudaGetSymbolAddress((void**)&pXl, g_Xlo);
    cudaGetSymbolAddress((void**)&pQT, g_WqTh);
    cudaGetSymbolAddress((void**)&pKT, g_WkTh);
    cudaGetSymbolAddress((void**)&pVT, g_WvTh);
    cudaGetSymbolAddress((void**)&pOT, g_WoTh);
    cudaGetSymbolAddress((void**)&pQh, g_Qh);
    cudaGetSymbolAddress((void**)&pQl, g_Ql);
    cudaGetSymbolAddress((void**)&pKh, g_Kh);
    cudaGetSymbolAddress((void**)&pVh, g_Vh);

    cudaFuncSetAttribute(hgemm_kernel<0>,
                         cudaFuncAttributeMaxDynamicSharedMemorySize, HG_SMEM);
    cudaFuncSetAttribute(hgemm_kernel<1>,
                         cudaFuncAttributeMaxDynamicSharedMemorySize, HG_SMEM);
    cudaFuncSetAttribute(hgemm_kernel<4>,
                         cudaFuncAttributeMaxDynamicSharedMemorySize, HG_SMEM);
    cudaFuncSetAttribute(attn_mma_kernel,
                         cudaFuncAttributeMaxDynamicSharedMemorySize, AT_SMEM);

    const int n4x = Mn * Hn / 4;
    dim3 tb(32, 8);

    // Launch order: Q-projection GEMM is launch #4 (ncu capture slot).
    split_kernel<<<n4x / 256, 256>>>(hidden, pXh, pXl, n4x);                 // 1
    tsplit_kernel<<<dim3(4096 / 32, 4096 / 32), tb>>>(Wq, pQT, Hn, 4096);    // 2
    tsplit_kernel<<<dim3(1024 / 32, 4096 / 32), tb>>>(Wk, pKT, Hn, 1024);    // 3
    hgemm_kernel<1><<<dim3(4096 / 128, Mn / 128), 256, HG_SMEM>>>(           // 4 <- profiled
        pXh, pXl, pQT, nullptr, pQ, nullptr, 4096, Hn);
    tsplit_kernel<<<dim3(1024 / 32, 4096 / 32), tb>>>(Wv, pVT, Hn, 1024);    // 5
    tsplit_kernel<<<dim3(4096 / 32, 4096 / 32), tb>>>(Wo, pOT, 4096, Hn);    // 6
    hgemm_kernel<4><<<dim3(1024 / 128, Mn / 128, 2), 256, HG_SMEM>>>(        // 7 (K+V)
        pXh, pXl, pKT, pVT, pK, pV, 1024, Hn);

    // RoPE + split: Q hi+lo (scale folded), K hi only; V hi only
    int totQ = Bn * NHn * Sn * 64;
    int totK = Bn * NKVn * Sn * 64;
    rope_split_kernel<<<totQ / 256, 256>>>(pQ, pQh, pQl, totQ, QK_SCALE);    // 8
    rope_split_kernel<<<totK / 256, 256>>>(pK, pKh, nullptr, totK, 1.f);     // 9
    const int nv4 = Bn * NKVn * Sn * HDn / 4;
    split_kernel<<<nv4 / 256, 256>>>(pV, pVh, nullptr, nv4);                 // 10

    // causal flash attention (writes hi/lo output into g_Xhi/g_Xlo)
    dim3 ga(Sn / 128, NHn, Bn);
    attn_mma_kernel<<<ga, 256, AT_SMEM>>>();                                 // 11

    // output projection (reads g_Xhi/g_Xlo written by attention)
    hgemm_kernel<0><<<dim3(4096 / 128, Mn / 128), 256, HG_SMEM>>>(           // 12
        pXh, pXl, pOT, nullptr, out, nullptr, 4096, Hn);
}

// round 14
// speedup vs baseline: 2.4602x; 1.0054x over previous
#include <cuda_runtime.h>
#include <cuda_fp16.h>
#include <math.h>
#include <stdint.h>

// Problem dims
constexpr int Bn = 2, Sn = 2048, Hn = 4096, NHn = 32, NKVn = 8, HDn = 128;
constexpr int Mn = Bn * Sn;
constexpr float QK_SCALE = 0.08838834764831845f; // 1/sqrt(128)
constexpr float L2E = 1.4426950408889634f;

// fp32 scratch (pre-RoPE projection outputs)
__device__ float g_Q[(size_t)Bn * NHn * Sn * HDn];   // [b][h][s][d]
__device__ float g_K[(size_t)Bn * NKVn * Sn * HDn];  // [b][kh][s][d]
__device__ float g_V[(size_t)Bn * NKVn * Sn * HDn];

// fp16 split scratch (A-side: hi+lo; B-side: hi only)
__device__ __half g_Xhi[(size_t)Mn * Hn];   // X split; reused for attn out
__device__ __half g_Xlo[(size_t)Mn * Hn];
__device__ __half g_WqTh[(size_t)4096 * 4096];
__device__ __half g_WkTh[(size_t)1024 * 4096];
__device__ __half g_WvTh[(size_t)1024 * 4096];
__device__ __half g_WoTh[(size_t)4096 * 4096];
// attention operands (post-RoPE): Q hi+lo (A-side), K/V hi only (B-side)
__device__ __half g_Qh[(size_t)Bn * NHn * Sn * HDn];
__device__ __half g_Ql[(size_t)Bn * NHn * Sn * HDn];
__device__ __half g_Kh[(size_t)Bn * NKVn * Sn * HDn];
__device__ __half g_Vh[(size_t)Bn * NKVn * Sn * HDn];

// ---------------------------------------------------------------------------
// helpers
// ---------------------------------------------------------------------------
__device__ __forceinline__ uint32_t smem_u32(const void* p) {
    uint32_t a;
    asm("{ .reg .u64 t; cvta.to.shared.u64 t, %1; cvt.u32.u64 %0, t; }"
        : "=r"(a) : "l"(p));
    return a;
}
__device__ __forceinline__ void cpa16(uint32_t dst, const void* src) {
    asm volatile("cp.async.cg.shared.global [%0], [%1], 16;"
                 :: "r"(dst), "l"(src) : "memory");
}
__device__ __forceinline__ void ldsm4(uint32_t& r0, uint32_t& r1,
                                      uint32_t& r2, uint32_t& r3, uint32_t a) {
    asm volatile("ldmatrix.sync.aligned.m8n8.x4.shared.b16 {%0,%1,%2,%3}, [%4];"
                 : "=r"(r0), "=r"(r1), "=r"(r2), "=r"(r3) : "r"(a));
}
__device__ __forceinline__ void ldsm4t(uint32_t& r0, uint32_t& r1,
                                       uint32_t& r2, uint32_t& r3, uint32_t a) {
    asm volatile("ldmatrix.sync.aligned.m8n8.x4.trans.shared.b16 {%0,%1,%2,%3}, [%4];"
                 : "=r"(r0), "=r"(r1), "=r"(r2), "=r"(r3) : "r"(a));
}
__device__ __forceinline__ void mma_f16(float* c, const uint32_t* a,
                                        const uint32_t* b) {
    asm volatile(
        "mma.sync.aligned.m16n8k16.row.col.f32.f16.f16.f32 "
        "{%0,%1,%2,%3}, {%4,%5,%6,%7}, {%8,%9}, {%0,%1,%2,%3};"
        : "+f"(c[0]), "+f"(c[1]), "+f"(c[2]), "+f"(c[3])
        : "r"(a[0]), "r"(a[1]), "r"(a[2]), "r"(a[3]), "r"(b[0]), "r"(b[1]));
}
// fast exp2 on the FMA pipe (y <= 0; clamp makes masked rows vanish)
__device__ __forceinline__ float fexp2(float y) {
    y = fmaxf(y, -126.f);
    float fl = floorf(y);
    float f = y - fl;
    float p = 1.8775767e-3f;
    p = fmaf(p, f, 8.9893397e-3f);
    p = fmaf(p, f, 5.5826318e-2f);
    p = fmaf(p, f, 2.4015361e-1f);
    p = fmaf(p, f, 6.9315308e-1f);
    p = fmaf(p, f, 9.9999994e-1f);
    return __int_as_float(((int)fl + 127) << 23) * p;
}
__device__ __forceinline__ uint32_t pack_h2(float a, float b) {
    __half2 v = __floats2half2_rn(a, b);
    return *reinterpret_cast<uint32_t*>(&v);
}
__device__ __forceinline__ uint32_t pack_h2_res(float a, float b, uint32_t hi) {
    __half2 hv = *reinterpret_cast<__half2*>(&hi);
    return pack_h2(a - __half2float(hv.x), b - __half2float(hv.y));
}

// ---------------------------------------------------------------------------
// Split conversion: x -> hi fp16 (+ optional lo fp16)
// ---------------------------------------------------------------------------
__global__ void split_kernel(const float* __restrict__ x,
                             __half* __restrict__ hi,
                             __half* __restrict__ lo, int n4)
{
    int i = blockIdx.x * 256 + threadIdx.x;
    if (i >= n4) return;
    float4 v = reinterpret_cast<const float4*>(x)[i];
    uint32_t h01 = pack_h2(v.x, v.y);
    uint32_t h23 = pack_h2(v.z, v.w);
    reinterpret_cast<uint32_t*>(hi)[i * 2 + 0] = h01;
    reinterpret_cast<uint32_t*>(hi)[i * 2 + 1] = h23;
    if (lo) {
        reinterpret_cast<uint32_t*>(lo)[i * 2 + 0] = pack_h2_res(v.x, v.y, h01);
        reinterpret_cast<uint32_t*>(lo)[i * 2 + 1] = pack_h2_res(v.z, v.w, h23);
    }
}

// ---------------------------------------------------------------------------
// Transpose + fp16 truncation: W[K][N] fp32 -> Th[N][K] fp16 (hi only)
// ---------------------------------------------------------------------------
__global__ void tsplit_kernel(const float* __restrict__ W,
                              __half* __restrict__ Thi, int K, int N)
{
    __shared__ float t[32][33];
    int tx = threadIdx.x, ty = threadIdx.y;
    int bx = blockIdx.x, by = blockIdx.y;
#pragma unroll
    for (int i = 0; i < 4; i++) {
        int r = by * 32 + ty + i * 8;
        t[ty + i * 8][tx] = W[(size_t)r * N + bx * 32 + tx];
    }
    __syncthreads();
#pragma unroll
    for (int i = 0; i < 4; i++) {
        int n = bx * 32 + ty + i * 8;
        int k = by * 32 + tx;
        Thi[(size_t)n * K + k] = __float2half_rn(t[tx][ty + i * 8]);
    }
}

// ---------------------------------------------------------------------------
// Fused post-projection conversions: Q rope hi+lo, K rope hi, V split hi.
// Flat grid, block-uniform branch. Per-element arithmetic identical to r13.
// ---------------------------------------------------------------------------
constexpr int RQ_BLK = Bn * NHn * Sn * 64 / 256;     // 32768
constexpr int RK_BLK = Bn * NKVn * Sn * 64 / 256;    // 8192
constexpr int SV_BLK = Bn * NKVn * Sn * HDn / 4 / 256; // 4096
constexpr int RS_BLKS = RQ_BLK + RK_BLK + SV_BLK;    // 45056

__device__ __forceinline__ void rope_seg(const float* __restrict__ X,
                                         __half* __restrict__ H,
                                         __half* __restrict__ L,
                                         int idx, float scale)
{
    int d = idx & 63;
    int s = (idx >> 6) & (Sn - 1);
    int bh = idx >> 17;
    float inv = powf(10000.f, -(float)d / 64.f);
    float ang = (float)s * inv;
    float sn, cs;
    sincosf(ang, &sn, &cs);
    size_t base = ((size_t)bh * Sn + s) * HDn;
    float x0 = X[base + d];
    float x1 = X[base + d + 64];
    float r0 = (x0 * cs - x1 * sn) * scale;
    float r1 = (x1 * cs + x0 * sn) * scale;
    __half h0 = __float2half_rn(r0);
    __half h1 = __float2half_rn(r1);
    H[base + d] = h0;
    H[base + d + 64] = h1;
    if (L) {
        L[base + d] = __float2half_rn(r0 - __half2float(h0));
        L[base + d + 64] = __float2half_rn(r1 - __half2float(h1));
    }
}

__global__ __launch_bounds__(256) void ropeall_kernel()
{
    int bid = blockIdx.x, tid = threadIdx.x;
    if (bid < RQ_BLK) {
        rope_seg(g_Q, g_Qh, g_Ql, bid * 256 + tid, QK_SCALE);
        return;
    }
    bid -= RQ_BLK;
    if (bid < RK_BLK) {
        rope_seg(g_K, g_Kh, nullptr, bid * 256 + tid, 1.f);
        return;
    }
    bid -= RK_BLK;
    {   // V hi-only split
        int i = bid * 256 + tid;
        float4 v = reinterpret_cast<const float4*>(g_V)[i];
        reinterpret_cast<uint32_t*>(g_Vh)[i * 2 + 0] = pack_h2(v.x, v.y);
        reinterpret_cast<uint32_t*>(g_Vh)[i * 2 + 1] = pack_h2(v.z, v.w);
    }
}

// ---------------------------------------------------------------------------
// fp16 2-pass GEMM on mma.sync: C = (Ah+Al) @ Bh^T.  CTA 128x128, K-chunk 32,
// 2-stage cp.async, 80 B/row. 3 tiles/chunk (Ah, Al, Bh). 2 CTAs/SM.
// MODE 0: C row-major (O projection).
// MODE 5: fused QKV. grid (32, 32, 2):
//   z=0          -> Q proj (N=4096, Q layout)
//   z=1, bx<8    -> K proj (N=1024, KV layout)
//   z=1, 8<=bx<16-> V proj (N=1024, KV layout)
//   z=1, bx>=16  -> early exit
// ---------------------------------------------------------------------------
constexpr int TROW = 80;                  // bytes per 32-element fp16 row
constexpr int TTILE = 128 * TROW;         // 10240 B
constexpr int TSTAGE = 3 * TTILE;         // 30720 B (Ah, Al, Bh)
constexpr int HG_SMEM = 2 * TSTAGE;       // 61440 B

template <int MODE>
__global__ __launch_bounds__(256, 2) void hgemm_kernel(
    const __half* __restrict__ Ahi, const __half* __restrict__ Alo,
    const __half* __restrict__ Bq, const __half* __restrict__ Bk,
    const __half* __restrict__ Bv,
    float* __restrict__ Cq, float* __restrict__ Ck, float* __restrict__ Cv,
    int N0, int K)
{
    extern __shared__ char smem[];
    const uint32_t sb = smem_u32(smem);

    const int tid = threadIdx.x;
    const int wid = tid >> 5, lane = tid & 31;
    const int g = lane >> 2, t4 = lane & 3;
    const int wr = wid >> 2, wc = wid & 3;
    const int wm = wr * 64, wn = wc * 32;

    int N = N0, heads = NHn;
    const __half* Bsel = Bq;
    float* Csel = Cq;
    int n0 = blockIdx.x * 128;
    const int m0 = blockIdx.y * 128;
    if (MODE == 5 && blockIdx.z == 1) {
        const int bx = blockIdx.x;
        if (bx >= 16) return;
        N = 1024; heads = NKVn;
        n0 = (bx & 7) * 128;
        Bsel = (bx < 8) ? Bk : Bv;
        Csel = (bx < 8) ? Ck : Cv;
    }

    const __half* Ah = Ahi + (size_t)m0 * K;
    const __half* Al = Alo + (size_t)m0 * K;
    const __half* Bh = Bsel + (size_t)n0 * K;

    float c[4][4][4];
#pragma unroll
    for (int mi = 0; mi < 4; mi++)
#pragma unroll
        for (int ni = 0; ni < 4; ni++)
#pragma unroll
            for (int r = 0; r < 4; r++) c[mi][ni][r] = 0.f;

    auto load_chunk = [&](int stage, int koff) {
        const uint32_t base = sb + stage * TSTAGE;
#pragma unroll
        for (int i = 0; i < 6; i++) {
            const int tile = i >> 1;
            const int id = tid + (i & 1) * 256;
            const int r = id >> 2, c4 = id & 3;
            const __half* s = (tile == 0) ? Ah : (tile == 1) ? Al : Bh;
            cpa16(base + tile * TTILE + r * TROW + c4 * 16,
                  s + (size_t)r * K + koff + c4 * 8);
        }
        asm volatile("cp.async.commit_group;" ::: "memory");
    };

    const int NC = K / 32;
    load_chunk(0, 0);
    load_chunk(1, 32);

    const int arow_off = (lane & 7) + ((lane >> 3) & 1) * 8;
    const int acol_off = (lane >> 4) * 8;
    const int brow_off = (lane & 7) + (lane >> 4) * 8;
    const int bcol_off = ((lane >> 3) & 1) * 8;

    for (int ch = 0; ch < NC; ch++) {
        if (ch + 1 < NC)
            asm volatile("cp.async.wait_group 1;" ::: "memory");
        else
            asm volatile("cp.async.wait_group 0;" ::: "memory");
        __syncthreads();

        const uint32_t st = sb + (ch & 1) * TSTAGE;
        const uint32_t ah_b = st, al_b = st + TTILE, bh_b = st + 2 * TTILE;

#pragma unroll
        for (int kk = 0; kk < 32; kk += 16) {
            uint32_t fah[4][4], fal[4][4], fbh[4][2];
#pragma unroll
            for (int mi = 0; mi < 4; mi++) {
                const uint32_t ro = (wm + mi * 16 + arow_off) * TROW +
                                    (kk + acol_off) * 2;
                ldsm4(fah[mi][0], fah[mi][1], fah[mi][2], fah[mi][3], ah_b + ro);
                ldsm4(fal[mi][0], fal[mi][1], fal[mi][2], fal[mi][3], al_b + ro);
            }
#pragma unroll
            for (int bt = 0; bt < 2; bt++) {
                const uint32_t ro = (wn + bt * 16 + brow_off) * TROW +
                                    (kk + bcol_off) * 2;
                ldsm4(fbh[2 * bt][0], fbh[2 * bt][1],
                      fbh[2 * bt + 1][0], fbh[2 * bt + 1][1], bh_b + ro);
            }
#pragma unroll
            for (int mi = 0; mi < 4; mi++)
#pragma unroll
                for (int ni = 0; ni < 4; ni++) {
                    mma_f16(c[mi][ni], fah[mi], fbh[ni]);
                    mma_f16(c[mi][ni], fal[mi], fbh[ni]);
                }
        }
        __syncthreads();
        if (ch + 2 < NC) load_chunk(ch & 1, (ch + 2) * 32);
    }

    // Epilogue: c-frag (g,2t4),(g,2t4+1),(g+8,2t4),(g+8,2t4+1)
    if (MODE == 0) {
#pragma unroll
        for (int mi = 0; mi < 4; mi++)
#pragma unroll
            for (int ni = 0; ni < 4; ni++) {
                const int row0 = m0 + wm + mi * 16 + g;
                const int col = n0 + wn + ni * 8 + 2 * t4;
#pragma unroll
                for (int half = 0; half < 2; half++) {
                    const int m = row0 + half * 8;
                    float2 v = half ? make_float2(c[mi][ni][2], c[mi][ni][3])
                                    : make_float2(c[mi][ni][0], c[mi][ni][1]);
                    *reinterpret_cast<float2*>(&Csel[(size_t)m * N + col]) = v;
                }
            }
    } else {
#pragma unroll
        for (int mi = 0; mi < 4; mi++)
#pragma unroll
            for (int ni = 0; ni < 4; ni++) {
                const int row0 = m0 + wm + mi * 16 + g;
                const int col = n0 + wn + ni * 8 + 2 * t4;
#pragma unroll
                for (int half = 0; half < 2; half++) {
                    const int m = row0 + half * 8;
                    float2 v = half ? make_float2(c[mi][ni][2], c[mi][ni][3])
                                    : make_float2(c[mi][ni][0], c[mi][ni][1]);
                    int b = m >> 11, s = m & 2047;
                    int h = col >> 7, d = col & 127;
                    *reinterpret_cast<float2*>(
                        &Csel[(((size_t)(b * heads + h) * Sn) + s) * HDn + d]) = v;
                }
            }
    }
}

// ---------------------------------------------------------------------------
// Flash attention, fp16 2-pass: scores = (Qh+Ql)·Kh, O = (Ph+Pl)·Vh.
// BQ=128, BK=64, 8 warps, 2-stage pipeline. LPT: qt reversed so the
// heaviest CTAs schedule first. Output hi/lo fp16 into g_Xhi/g_Xlo.
// ---------------------------------------------------------------------------
constexpr int ARB = 272;                  // padded row bytes (136 fp16)
constexpr int KVT = 64 * ARB;             // one 64x128 fp16 tile = 17408 B
constexpr int ASTG = 2 * KVT;             // Kh, Vh per stage = 34816 B
constexpr int AT_SMEM = 2 * ASTG + 2 * 34816;  // 2 stages + Qh + Ql = 139264 B

__global__ __launch_bounds__(256, 1) void attn_mma_kernel()
{
    extern __shared__ char smem[];
    const uint32_t sb = smem_u32(smem);
    const int qt = (int)gridDim.x - 1 - blockIdx.x;   // LPT order
    const int h = blockIdx.y, b = blockIdx.z;
    const int tid = threadIdx.x, wid = tid >> 5, lane = tid & 31;
    const int g = lane >> 2, t4 = lane & 3;
    const int wm = wid * 16;
    const int kvh = h >> 2;
    const int NT = 2 * (qt + 1);

    const __half* Qhp = g_Qh + ((size_t)(b * NHn + h) * Sn + qt * 128) * HDn;
    const __half* Qlp = g_Ql + ((size_t)(b * NHn + h) * Sn + qt * 128) * HDn;
    const __half* Khp = g_Kh + ((size_t)(b * NKVn + kvh) * Sn) * HDn;
    const __half* Vhp = g_Vh + ((size_t)(b * NKVn + kvh) * Sn) * HDn;

    const uint32_t qhb = sb + 2 * ASTG, qlb = sb + 2 * ASTG + 34816;
#pragma unroll
    for (int i = 0; i < 8; i++) {
        int id = tid + i * 256, r = id >> 4, c = id & 15;
        cpa16(qhb + r * ARB + c * 16, Qhp + r * HDn + c * 8);
        cpa16(qlb + r * ARB + c * 16, Qlp + r * HDn + c * 8);
    }
    asm volatile("cp.async.commit_group;" ::: "memory");

    auto load_stage = [&](int stg, int t) {
        const uint32_t st = sb + stg * ASTG;
        const __half* kh = Khp + (size_t)t * 64 * HDn;
        const __half* vh = Vhp + (size_t)t * 64 * HDn;
#pragma unroll
        for (int i = 0; i < 4; i++) {
            int id = tid + i * 256, r = id >> 4, c = id & 15;
            cpa16(st + 0 * KVT + r * ARB + c * 16, kh + r * HDn + c * 8);
            cpa16(st + 1 * KVT + r * ARB + c * 16, vh + r * HDn + c * 8);
        }
        asm volatile("cp.async.commit_group;" ::: "memory");
    };
    load_stage(0, 0);

    asm volatile("cp.async.wait_group 1;" ::: "memory");  // Q arrived
    __syncthreads();

    const int arow = (lane & 7) + ((lane >> 3) & 1) * 8;
    const int acolB = (lane >> 4) * 16;
    uint32_t qhf[8][4], qlf[8][4];
#pragma unroll
    for (int ks = 0; ks < 8; ks++) {
        uint32_t ro = (wm + arow) * ARB + ks * 32 + acolB;
        ldsm4(qhf[ks][0], qhf[ks][1], qhf[ks][2], qhf[ks][3], qhb + ro);
        ldsm4(qlf[ks][0], qlf[ks][1], qlf[ks][2], qlf[ks][3], qlb + ro);
    }
    __syncthreads();
    load_stage(1, 1);

    float o[16][4];
#pragma unroll
    for (int j = 0; j < 16; j++)
#pragma unroll
        for (int e = 0; e < 4; e++) o[j][e] = 0.f;
    float m0 = -1e30f, m1 = -1e30f, l0 = 0.f, l1 = 0.f;

    const int brow = (lane & 7) + (lane >> 4) * 8;
    const int bcolB = ((lane >> 3) & 1) * 16;
    const int vcolB = (lane >> 4) * 16;
    const int row0g = qt * 128 + wm + g;

    for (int t = 0; t < NT; t++) {
        if (t + 1 < NT)
            asm volatile("cp.async.wait_group 1;" ::: "memory");
        else
            asm volatile("cp.async.wait_group 0;" ::: "memory");
        __syncthreads();
        const uint32_t st = sb + (t & 1) * ASTG;

        float s[8][4];
#pragma unroll
        for (int j = 0; j < 8; j++)
#pragma unroll
            for (int e = 0; e < 4; e++) s[j][e] = 0.f;

#pragma unroll
        for (int ks = 0; ks < 8; ks++) {
#pragma unroll
            for (int gr = 0; gr < 4; gr++) {
                uint32_t kh4[4];
                uint32_t ro = st + (gr * 16 + brow) * ARB + ks * 32 + bcolB;
                ldsm4(kh4[0], kh4[1], kh4[2], kh4[3], ro);
                mma_f16(s[2 * gr], qhf[ks], kh4);
                mma_f16(s[2 * gr], qlf[ks], kh4);
                mma_f16(s[2 * gr + 1], qhf[ks], kh4 + 2);
                mma_f16(s[2 * gr + 1], qlf[ks], kh4 + 2);
            }
        }

        if (t >= 2 * qt) {
#pragma unroll
            for (int j = 0; j < 8; j++) {
                int c0 = t * 64 + j * 8 + 2 * t4;
                if (c0 > row0g)     s[j][0] = -1e30f;
                if (c0 + 1 > row0g) s[j][1] = -1e30f;
                if (c0 > row0g + 8)     s[j][2] = -1e30f;
                if (c0 + 1 > row0g + 8) s[j][3] = -1e30f;
            }
        }

        float tm0 = -1e30f, tm1 = -1e30f;
#pragma unroll
        for (int j = 0; j < 8; j++) {
            tm0 = fmaxf(tm0, fmaxf(s[j][0], s[j][1]));
            tm1 = fmaxf(tm1, fmaxf(s[j][2], s[j][3]));
        }
        tm0 = fmaxf(tm0, __shfl_xor_sync(0xffffffffu, tm0, 1));
        tm0 = fmaxf(tm0, __shfl_xor_sync(0xffffffffu, tm0, 2));
        tm1 = fmaxf(tm1, __shfl_xor_sync(0xffffffffu, tm1, 1));
        tm1 = fmaxf(tm1, __shfl_xor_sync(0xffffffffu, tm1, 2));
        float mn0 = fmaxf(m0, tm0), mn1 = fmaxf(m1, tm1);
        float cor0 = fexp2((m0 - mn0) * L2E);
        float cor1 = fexp2((m1 - mn1) * L2E);
        m0 = mn0; m1 = mn1;
#pragma unroll
        for (int j = 0; j < 16; j++) {
            o[j][0] *= cor0; o[j][1] *= cor0;
            o[j][2] *= cor1; o[j][3] *= cor1;
        }
        float rs0 = 0.f, rs1 = 0.f;
#pragma unroll
        for (int j = 0; j < 8; j++) {
            s[j][0] = fexp2((s[j][0] - mn0) * L2E);
            s[j][1] = fexp2((s[j][1] - mn0) * L2E);
            s[j][2] = fexp2((s[j][2] - mn1) * L2E);
            s[j][3] = fexp2((s[j][3] - mn1) * L2E);
            rs0 += s[j][0] + s[j][1];
            rs1 += s[j][2] + s[j][3];
        }
        rs0 += __shfl_xor_sync(0xffffffffu, rs0, 1);
        rs0 += __shfl_xor_sync(0xffffffffu, rs0, 2);
        rs1 += __shfl_xor_sync(0xffffffffu, rs1, 1);
        rs1 += __shfl_xor_sync(0xffffffffu, rs1, 2);
        l0 = l0 * cor0 + rs0;
        l1 = l1 * cor1 + rs1;

#pragma unroll
        for (int ks = 0; ks < 4; ks++) {
            uint32_t pha[4], pla[4];
            pha[0] = pack_h2(s[2 * ks][0], s[2 * ks][1]);
            pha[1] = pack_h2(s[2 * ks][2], s[2 * ks][3]);
            pha[2] = pack_h2(s[2 * ks + 1][0], s[2 * ks + 1][1]);
            pha[3] = pack_h2(s[2 * ks + 1][2], s[2 * ks + 1][3]);
            pla[0] = pack_h2_res(s[2 * ks][0], s[2 * ks][1], pha[0]);
            pla[1] = pack_h2_res(s[2 * ks][2], s[2 * ks][3], pha[1]);
            pla[2] = pack_h2_res(s[2 * ks + 1][0], s[2 * ks + 1][1], pha[2]);
            pla[3] = pack_h2_res(s[2 * ks + 1][2], s[2 * ks + 1][3], pha[3]);
#pragma unroll
            for (int gr = 0; gr < 8; gr++) {
                uint32_t vh4[4];
                uint32_t ro = st + KVT + (ks * 16 + arow) * ARB +
                              gr * 32 + vcolB;
                ldsm4t(vh4[0], vh4[1], vh4[2], vh4[3], ro);
                mma_f16(o[2 * gr], pha, vh4);
                mma_f16(o[2 * gr], pla, vh4);
                mma_f16(o[2 * gr + 1], pha, vh4 + 2);
                mma_f16(o[2 * gr + 1], pla, vh4 + 2);
            }
        }
        __syncthreads();
        if (t + 2 < NT) load_stage(t & 1, t + 2);
    }

    // ---- epilogue: normalize, split hi/lo, write g_Xhi/g_Xlo [b][s][h*d] ----
    float inv0 = 1.f / l0, inv1 = 1.f / l1;
    const int r0 = qt * 128 + wm + g, r1 = r0 + 8;
#pragma unroll
    for (int j = 0; j < 16; j++) {
        int col = h * 128 + j * 8 + 2 * t4;
        float a0 = o[j][0] * inv0, a1 = o[j][1] * inv0;
        float b0 = o[j][2] * inv1, b1 = o[j][3] * inv1;
        size_t i0 = ((size_t)(b * Sn + r0)) * 4096 + col;
        size_t i1 = ((size_t)(b * Sn + r1)) * 4096 + col;
        uint32_t h0 = pack_h2(a0, a1);
        uint32_t h1 = pack_h2(b0, b1);
        *reinterpret_cast<uint32_t*>(&g_Xhi[i0]) = h0;
        *reinterpret_cast<uint32_t*>(&g_Xlo[i0]) = pack_h2_res(a0, a1, h0);
        *reinterpret_cast<uint32_t*>(&g_Xhi[i1]) = h1;
        *reinterpret_cast<uint32_t*>(&g_Xlo[i1]) = pack_h2_res(b0, b1, h1);
    }
}

// ---------------------------------------------------------------------------
extern "C" void kernel_launch(void* const* d_in, const int* in_sizes, int n_in,
                              void* d_out, int out_size)
{
    const float* hidden = (const float*)d_in[0];
    const float* Wq = (const float*)d_in[2];
    const float* Wk = (const float*)d_in[3];
    const float* Wv = (const float*)d_in[4];
    const float* Wo = (const float*)d_in[5];
    float* out = (float*)d_out;

    float *pQ, *pK, *pV;
    __half *pXh, *pXl, *pQT, *pKT, *pVT, *pOT;
    cudaGetSymbolAddress((void**)&pQ, g_Q);
    cudaGetSymbolAddress((void**)&pK, g_K);
    cudaGetSymbolAddress((void**)&pV, g_V);
    cudaGetSymbolAddress((void**)&pXh, g_Xhi);
    cudaGetSymbolAddress((void**)&pXl, g_Xlo);
    cudaGetSymbolAddress((void**)&pQT, g_WqTh);
    cudaGetSymbolAddress((void**)&pKT, g_WkTh);
    cudaGetSymbolAddress((void**)&pVT, g_WvTh);
    cudaGetSymbolAddress((void**)&pOT, g_WoTh);

    cudaFuncSetAttribute(hgemm_kernel<0>,
                         cudaFuncAttributeMaxDynamicSharedMemorySize, HG_SMEM);
    cudaFuncSetAttribute(hgemm_kernel<5>,
                         cudaFuncAttributeMaxDynamicSharedMemorySize, HG_SMEM);
    cudaFuncSetAttribute(attn_mma_kernel,
                         cudaFuncAttributeMaxDynamicSharedMemorySize, AT_SMEM);

    const int n4x = Mn * Hn / 4;
    dim3 tb(32, 8);

    // 1-4: conversions
    split_kernel<<<n4x / 256, 256>>>(hidden, pXh, pXl, n4x);                 // 1
    tsplit_kernel<<<dim3(4096 / 32, 4096 / 32), tb>>>(Wq, pQT, Hn, 4096);    // 2
    tsplit_kernel<<<dim3(1024 / 32, 4096 / 32), tb>>>(Wk, pKT, Hn, 1024);    // 3
    tsplit_kernel<<<dim3(1024 / 32, 4096 / 32), tb>>>(Wv, pVT, Hn, 1024);    // 4

    // 5: fused Q+K+V projection GEMM (one launch, z-decoded)
    hgemm_kernel<5><<<dim3(32, Mn / 128, 2), 256, HG_SMEM>>>(                // 5
        pXh, pXl, pQT, pKT, pVT, pQ, pK, pV, 4096, Hn);

    tsplit_kernel<<<dim3(4096 / 32, 4096 / 32), tb>>>(Wo, pOT, 4096, Hn);    // 6

    // 7: fused RoPE(Q hi+lo) + RoPE(K hi) + V split, one launch
    ropeall_kernel<<<RS_BLKS, 256>>>();                                      // 7

    // 8: causal flash attention (LPT order; writes hi/lo into g_Xhi/g_Xlo)
    dim3 ga(Sn / 128, NHn, Bn);
    attn_mma_kernel<<<ga, 256, AT_SMEM>>>();                                 // 8

    // 9: output projection
    hgemm_kernel<0><<<dim3(4096 / 128, Mn / 128), 256, HG_SMEM>>>(           // 9
        pXh, pXl, pOT, nullptr, nullptr, out, nullptr, nullptr, 4096, Hn);
}

// round 15
// speedup vs baseline: 2.5324x; 1.0294x over previous
#include <cuda_runtime.h>
#include <cuda_fp16.h>
#include <math.h>
#include <stdint.h>

// Problem dims
constexpr int Bn = 2, Sn = 2048, Hn = 4096, NHn = 32, NKVn = 8, HDn = 128;
constexpr int Mn = Bn * Sn;
constexpr float QK_SCALE = 0.08838834764831845f; // 1/sqrt(128)
constexpr float L2E = 1.4426950408889634f;

// fp32 scratch (pre-RoPE projection outputs)
__device__ float g_Q[(size_t)Bn * NHn * Sn * HDn];   // [b][h][s][d]
__device__ float g_K[(size_t)Bn * NKVn * Sn * HDn];  // [b][kh][s][d]
__device__ float g_V[(size_t)Bn * NKVn * Sn * HDn];

// fp16 split scratch (A-side: hi+lo; B-side: hi only)
__device__ __half g_Xhi[(size_t)Mn * Hn];   // X split; reused for attn out
__device__ __half g_Xlo[(size_t)Mn * Hn];
__device__ __half g_WqTh[(size_t)4096 * 4096];
__device__ __half g_WkTh[(size_t)1024 * 4096];
__device__ __half g_WvTh[(size_t)1024 * 4096];
__device__ __half g_WoTh[(size_t)4096 * 4096];
// attention operands (post-RoPE): Q hi+lo (A-side), K/V hi only (B-side)
__device__ __half g_Qh[(size_t)Bn * NHn * Sn * HDn];
__device__ __half g_Ql[(size_t)Bn * NHn * Sn * HDn];
__device__ __half g_Kh[(size_t)Bn * NKVn * Sn * HDn];
__device__ __half g_Vh[(size_t)Bn * NKVn * Sn * HDn];

// ---------------------------------------------------------------------------
// helpers
// ---------------------------------------------------------------------------
__device__ __forceinline__ uint32_t smem_u32(const void* p) {
    uint32_t a;
    asm("{ .reg .u64 t; cvta.to.shared.u64 t, %1; cvt.u32.u64 %0, t; }"
        : "=r"(a) : "l"(p));
    return a;
}
__device__ __forceinline__ void cpa16(uint32_t dst, const void* src) {
    asm volatile("cp.async.cg.shared.global [%0], [%1], 16;"
                 :: "r"(dst), "l"(src) : "memory");
}
__device__ __forceinline__ void ldsm4(uint32_t& r0, uint32_t& r1,
                                      uint32_t& r2, uint32_t& r3, uint32_t a) {
    asm volatile("ldmatrix.sync.aligned.m8n8.x4.shared.b16 {%0,%1,%2,%3}, [%4];"
                 : "=r"(r0), "=r"(r1), "=r"(r2), "=r"(r3) : "r"(a));
}
__device__ __forceinline__ void ldsm4t(uint32_t& r0, uint32_t& r1,
                                       uint32_t& r2, uint32_t& r3, uint32_t a) {
    asm volatile("ldmatrix.sync.aligned.m8n8.x4.trans.shared.b16 {%0,%1,%2,%3}, [%4];"
                 : "=r"(r0), "=r"(r1), "=r"(r2), "=r"(r3) : "r"(a));
}
__device__ __forceinline__ void mma_f16(float* c, const uint32_t* a,
                                        const uint32_t* b) {
    asm volatile(
        "mma.sync.aligned.m16n8k16.row.col.f32.f16.f16.f32 "
        "{%0,%1,%2,%3}, {%4,%5,%6,%7}, {%8,%9}, {%0,%1,%2,%3};"
        : "+f"(c[0]), "+f"(c[1]), "+f"(c[2]), "+f"(c[3])
        : "r"(a[0]), "r"(a[1]), "r"(a[2]), "r"(a[3]), "r"(b[0]), "r"(b[1]));
}
// fast exp2 on the FMA pipe (y <= 0; clamp makes masked rows vanish)
__device__ __forceinline__ float fexp2(float y) {
    y = fmaxf(y, -126.f);
    float fl = floorf(y);
    float f = y - fl;
    float p = 1.8775767e-3f;
    p = fmaf(p, f, 8.9893397e-3f);
    p = fmaf(p, f, 5.5826318e-2f);
    p = fmaf(p, f, 2.4015361e-1f);
    p = fmaf(p, f, 6.9315308e-1f);
    p = fmaf(p, f, 9.9999994e-1f);
    return __int_as_float(((int)fl + 127) << 23) * p;
}
__device__ __forceinline__ uint32_t pack_h2(float a, float b) {
    __half2 v = __floats2half2_rn(a, b);
    return *reinterpret_cast<uint32_t*>(&v);
}
__device__ __forceinline__ uint32_t pack_h2_res(float a, float b, uint32_t hi) {
    __half2 hv = *reinterpret_cast<__half2*>(&hi);
    return pack_h2(a - __half2float(hv.x), b - __half2float(hv.y));
}

// ---------------------------------------------------------------------------
// Split conversion: x -> hi fp16 (+ optional lo fp16)
// ---------------------------------------------------------------------------
__global__ void split_kernel(const float* __restrict__ x,
                             __half* __restrict__ hi,
                             __half* __restrict__ lo, int n4)
{
    int i = blockIdx.x * 256 + threadIdx.x;
    if (i >= n4) return;
    float4 v = reinterpret_cast<const float4*>(x)[i];
    uint32_t h01 = pack_h2(v.x, v.y);
    uint32_t h23 = pack_h2(v.z, v.w);
    reinterpret_cast<uint32_t*>(hi)[i * 2 + 0] = h01;
    reinterpret_cast<uint32_t*>(hi)[i * 2 + 1] = h23;
    if (lo) {
        reinterpret_cast<uint32_t*>(lo)[i * 2 + 0] = pack_h2_res(v.x, v.y, h01);
        reinterpret_cast<uint32_t*>(lo)[i * 2 + 1] = pack_h2_res(v.z, v.w, h23);
    }
}

// ---------------------------------------------------------------------------
// Transpose + fp16 truncation: W[K][N] fp32 -> Th[N][K] fp16 (hi only)
// ---------------------------------------------------------------------------
__global__ void tsplit_kernel(const float* __restrict__ W,
                              __half* __restrict__ Thi, int K, int N)
{
    __shared__ float t[32][33];
    int tx = threadIdx.x, ty = threadIdx.y;
    int bx = blockIdx.x, by = blockIdx.y;
#pragma unroll
    for (int i = 0; i < 4; i++) {
        int r = by * 32 + ty + i * 8;
        t[ty + i * 8][tx] = W[(size_t)r * N + bx * 32 + tx];
    }
    __syncthreads();
#pragma unroll
    for (int i = 0; i < 4; i++) {
        int n = bx * 32 + ty + i * 8;
        int k = by * 32 + tx;
        Thi[(size_t)n * K + k] = __float2half_rn(t[tx][ty + i * 8]);
    }
}

// ---------------------------------------------------------------------------
// Fused post-projection conversions: Q rope hi+lo, K rope hi, V split hi.
// ---------------------------------------------------------------------------
constexpr int RQ_BLK = Bn * NHn * Sn * 64 / 256;     // 32768
constexpr int RK_BLK = Bn * NKVn * Sn * 64 / 256;    // 8192
constexpr int SV_BLK = Bn * NKVn * Sn * HDn / 4 / 256; // 4096
constexpr int RS_BLKS = RQ_BLK + RK_BLK + SV_BLK;    // 45056

__device__ __forceinline__ void rope_seg(const float* __restrict__ X,
                                         __half* __restrict__ H,
                                         __half* __restrict__ L,
                                         int idx, float scale)
{
    int d = idx & 63;
    int s = (idx >> 6) & (Sn - 1);
    int bh = idx >> 17;
    float inv = powf(10000.f, -(float)d / 64.f);
    float ang = (float)s * inv;
    float sn, cs;
    sincosf(ang, &sn, &cs);
    size_t base = ((size_t)bh * Sn + s) * HDn;
    float x0 = X[base + d];
    float x1 = X[base + d + 64];
    float r0 = (x0 * cs - x1 * sn) * scale;
    float r1 = (x1 * cs + x0 * sn) * scale;
    __half h0 = __float2half_rn(r0);
    __half h1 = __float2half_rn(r1);
    H[base + d] = h0;
    H[base + d + 64] = h1;
    if (L) {
        L[base + d] = __float2half_rn(r0 - __half2float(h0));
        L[base + d + 64] = __float2half_rn(r1 - __half2float(h1));
    }
}

__global__ __launch_bounds__(256) void ropeall_kernel()
{
    int bid = blockIdx.x, tid = threadIdx.x;
    if (bid < RQ_BLK) {
        rope_seg(g_Q, g_Qh, g_Ql, bid * 256 + tid, QK_SCALE);
        return;
    }
    bid -= RQ_BLK;
    if (bid < RK_BLK) {
        rope_seg(g_K, g_Kh, nullptr, bid * 256 + tid, 1.f);
        return;
    }
    bid -= RK_BLK;
    {   // V hi-only split
        int i = bid * 256 + tid;
        float4 v = reinterpret_cast<const float4*>(g_V)[i];
        reinterpret_cast<uint32_t*>(g_Vh)[i * 2 + 0] = pack_h2(v.x, v.y);
        reinterpret_cast<uint32_t*>(g_Vh)[i * 2 + 1] = pack_h2(v.z, v.w);
    }
}

// ---------------------------------------------------------------------------
// fp16 2-pass GEMM on mma.sync: C = (Ah+Al) @ Bh^T.  CTA 128x128, K-chunk 32,
// 2-stage cp.async, 80 B/row. 3 tiles/chunk (Ah, Al, Bh). 2 CTAs/SM.
// MODE 0: C row-major (O projection).
// MODE 5: fused QKV via blockIdx.z decode.
// ---------------------------------------------------------------------------
constexpr int TROW = 80;
constexpr int TTILE = 128 * TROW;         // 10240 B
constexpr int TSTAGE = 3 * TTILE;         // 30720 B (Ah, Al, Bh)
constexpr int HG_SMEM = 2 * TSTAGE;       // 61440 B

template <int MODE>
__global__ __launch_bounds__(256, 2) void hgemm_kernel(
    const __half* __restrict__ Ahi, const __half* __restrict__ Alo,
    const __half* __restrict__ Bq, const __half* __restrict__ Bk,
    const __half* __restrict__ Bv,
    float* __restrict__ Cq, float* __restrict__ Ck, float* __restrict__ Cv,
    int N0, int K)
{
    extern __shared__ char smem[];
    const uint32_t sb = smem_u32(smem);

    const int tid = threadIdx.x;
    const int wid = tid >> 5, lane = tid & 31;
    const int g = lane >> 2, t4 = lane & 3;
    const int wr = wid >> 2, wc = wid & 3;
    const int wm = wr * 64, wn = wc * 32;

    int N = N0, heads = NHn;
    const __half* Bsel = Bq;
    float* Csel = Cq;
    int n0 = blockIdx.x * 128;
    const int m0 = blockIdx.y * 128;
    if (MODE == 5 && blockIdx.z == 1) {
        const int bx = blockIdx.x;
        if (bx >= 16) return;
        N = 1024; heads = NKVn;
        n0 = (bx & 7) * 128;
        Bsel = (bx < 8) ? Bk : Bv;
        Csel = (bx < 8) ? Ck : Cv;
    }

    const __half* Ah = Ahi + (size_t)m0 * K;
    const __half* Al = Alo + (size_t)m0 * K;
    const __half* Bh = Bsel + (size_t)n0 * K;

    float c[4][4][4];
#pragma unroll
    for (int mi = 0; mi < 4; mi++)
#pragma unroll
        for (int ni = 0; ni < 4; ni++)
#pragma unroll
            for (int r = 0; r < 4; r++) c[mi][ni][r] = 0.f;

    auto load_chunk = [&](int stage, int koff) {
        const uint32_t base = sb + stage * TSTAGE;
#pragma unroll
        for (int i = 0; i < 6; i++) {
            const int tile = i >> 1;
            const int id = tid + (i & 1) * 256;
            const int r = id >> 2, c4 = id & 3;
            const __half* s = (tile == 0) ? Ah : (tile == 1) ? Al : Bh;
            cpa16(base + tile * TTILE + r * TROW + c4 * 16,
                  s + (size_t)r * K + koff + c4 * 8);
        }
        asm volatile("cp.async.commit_group;" ::: "memory");
    };

    const int NC = K / 32;
    load_chunk(0, 0);
    load_chunk(1, 32);

    const int arow_off = (lane & 7) + ((lane >> 3) & 1) * 8;
    const int acol_off = (lane >> 4) * 8;
    const int brow_off = (lane & 7) + (lane >> 4) * 8;
    const int bcol_off = ((lane >> 3) & 1) * 8;

    for (int ch = 0; ch < NC; ch++) {
        if (ch + 1 < NC)
            asm volatile("cp.async.wait_group 1;" ::: "memory");
        else
            asm volatile("cp.async.wait_group 0;" ::: "memory");
        __syncthreads();

        const uint32_t st = sb + (ch & 1) * TSTAGE;
        const uint32_t ah_b = st, al_b = st + TTILE, bh_b = st + 2 * TTILE;

#pragma unroll
        for (int kk = 0; kk < 32; kk += 16) {
            uint32_t fah[4][4], fal[4][4], fbh[4][2];
#pragma unroll
            for (int mi = 0; mi < 4; mi++) {
                const uint32_t ro = (wm + mi * 16 + arow_off) * TROW +
                                    (kk + acol_off) * 2;
                ldsm4(fah[mi][0], fah[mi][1], fah[mi][2], fah[mi][3], ah_b + ro);
                ldsm4(fal[mi][0], fal[mi][1], fal[mi][2], fal[mi][3], al_b + ro);
            }
#pragma unroll
            for (int bt = 0; bt < 2; bt++) {
                const uint32_t ro = (wn + bt * 16 + brow_off) * TROW +
                                    (kk + bcol_off) * 2;
                ldsm4(fbh[2 * bt][0], fbh[2 * bt][1],
                      fbh[2 * bt + 1][0], fbh[2 * bt + 1][1], bh_b + ro);
            }
#pragma unroll
            for (int mi = 0; mi < 4; mi++)
#pragma unroll
                for (int ni = 0; ni < 4; ni++) {
                    mma_f16(c[mi][ni], fah[mi], fbh[ni]);
                    mma_f16(c[mi][ni], fal[mi], fbh[ni]);
                }
        }
        __syncthreads();
        if (ch + 2 < NC) load_chunk(ch & 1, (ch + 2) * 32);
    }

    if (MODE == 0) {
#pragma unroll
        for (int mi = 0; mi < 4; mi++)
#pragma unroll
            for (int ni = 0; ni < 4; ni++) {
                const int row0 = m0 + wm + mi * 16 + g;
                const int col = n0 + wn + ni * 8 + 2 * t4;
#pragma unroll
                for (int half = 0; half < 2; half++) {
                    const int m = row0 + half * 8;
                    float2 v = half ? make_float2(c[mi][ni][2], c[mi][ni][3])
                                    : make_float2(c[mi][ni][0], c[mi][ni][1]);
                    *reinterpret_cast<float2*>(&Csel[(size_t)m * N + col]) = v;
                }
            }
    } else {
#pragma unroll
        for (int mi = 0; mi < 4; mi++)
#pragma unroll
            for (int ni = 0; ni < 4; ni++) {
                const int row0 = m0 + wm + mi * 16 + g;
                const int col = n0 + wn + ni * 8 + 2 * t4;
#pragma unroll
                for (int half = 0; half < 2; half++) {
                    const int m = row0 + half * 8;
                    float2 v = half ? make_float2(c[mi][ni][2], c[mi][ni][3])
                                    : make_float2(c[mi][ni][0], c[mi][ni][1]);
                    int b = m >> 11, s = m & 2047;
                    int h = col >> 7, d = col & 127;
                    *reinterpret_cast<float2*>(
                        &Csel[(((size_t)(b * heads + h) * Sn) + s) * HDn + d]) = v;
                }
            }
    }
}

// ---------------------------------------------------------------------------
// Flash attention, fp16: scores = (Qh+Ql)·Kh (2-pass), O = Ph·Vh (1-pass;
// P in [0,1], l is fp32-exact, so Pl adds < 1.5e-4 — dropped).
// BQ=128, BK=64, 8 warps, 2-stage pipeline, LPT order.
// ---------------------------------------------------------------------------
constexpr int ARB = 272;
constexpr int KVT = 64 * ARB;             // 17408 B
constexpr int ASTG = 2 * KVT;             // Kh, Vh per stage = 34816 B
constexpr int AT_SMEM = 2 * ASTG + 2 * 34816;  // + Qh + Ql = 139264 B

__global__ __launch_bounds__(256, 1) void attn_mma_kernel()
{
    extern __shared__ char smem[];
    const uint32_t sb = smem_u32(smem);
    const int qt = (int)gridDim.x - 1 - blockIdx.x;   // LPT order
    const int h = blockIdx.y, b = blockIdx.z;
    const int tid = threadIdx.x, wid = tid >> 5, lane = tid & 31;
    const int g = lane >> 2, t4 = lane & 3;
    const int wm = wid * 16;
    const int kvh = h >> 2;
    const int NT = 2 * (qt + 1);

    const __half* Qhp = g_Qh + ((size_t)(b * NHn + h) * Sn + qt * 128) * HDn;
    const __half* Qlp = g_Ql + ((size_t)(b * NHn + h) * Sn + qt * 128) * HDn;
    const __half* Khp = g_Kh + ((size_t)(b * NKVn + kvh) * Sn) * HDn;
    const __half* Vhp = g_Vh + ((size_t)(b * NKVn + kvh) * Sn) * HDn;

    const uint32_t qhb = sb + 2 * ASTG, qlb = sb + 2 * ASTG + 34816;
#pragma unroll
    for (int i = 0; i < 8; i++) {
        int id = tid + i * 256, r = id >> 4, c = id & 15;
        cpa16(qhb + r * ARB + c * 16, Qhp + r * HDn + c * 8);
        cpa16(qlb + r * ARB + c * 16, Qlp + r * HDn + c * 8);
    }
    asm volatile("cp.async.commit_group;" ::: "memory");

    auto load_stage = [&](int stg, int t) {
        const uint32_t st = sb + stg * ASTG;
        const __half* kh = Khp + (size_t)t * 64 * HDn;
        const __half* vh = Vhp + (size_t)t * 64 * HDn;
#pragma unroll
        for (int i = 0; i < 4; i++) {
            int id = tid + i * 256, r = id >> 4, c = id & 15;
            cpa16(st + 0 * KVT + r * ARB + c * 16, kh + r * HDn + c * 8);
            cpa16(st + 1 * KVT + r * ARB + c * 16, vh + r * HDn + c * 8);
        }
        asm volatile("cp.async.commit_group;" ::: "memory");
    };
    load_stage(0, 0);

    asm volatile("cp.async.wait_group 1;" ::: "memory");  // Q arrived
    __syncthreads();

    const int arow = (lane & 7) + ((lane >> 3) & 1) * 8;
    const int acolB = (lane >> 4) * 16;
    uint32_t qhf[8][4], qlf[8][4];
#pragma unroll
    for (int ks = 0; ks < 8; ks++) {
        uint32_t ro = (wm + arow) * ARB + ks * 32 + acolB;
        ldsm4(qhf[ks][0], qhf[ks][1], qhf[ks][2], qhf[ks][3], qhb + ro);
        ldsm4(qlf[ks][0], qlf[ks][1], qlf[ks][2], qlf[ks][3], qlb + ro);
    }
    __syncthreads();
    load_stage(1, 1);

    float o[16][4];
#pragma unroll
    for (int j = 0; j < 16; j++)
#pragma unroll
        for (int e = 0; e < 4; e++) o[j][e] = 0.f;
    float m0 = -1e30f, m1 = -1e30f, l0 = 0.f, l1 = 0.f;

    const int brow = (lane & 7) + (lane >> 4) * 8;
    const int bcolB = ((lane >> 3) & 1) * 16;
    const int vcolB = (lane >> 4) * 16;
    const int row0g = qt * 128 + wm + g;

    for (int t = 0; t < NT; t++) {
        if (t + 1 < NT)
            asm volatile("cp.async.wait_group 1;" ::: "memory");
        else
            asm volatile("cp.async.wait_group 0;" ::: "memory");
        __syncthreads();
        const uint32_t st = sb + (t & 1) * ASTG;

        float s[8][4];
#pragma unroll
        for (int j = 0; j < 8; j++)
#pragma unroll
            for (int e = 0; e < 4; e++) s[j][e] = 0.f;

#pragma unroll
        for (int ks = 0; ks < 8; ks++) {
#pragma unroll
            for (int gr = 0; gr < 4; gr++) {
                uint32_t kh4[4];
                uint32_t ro = st + (gr * 16 + brow) * ARB + ks * 32 + bcolB;
                ldsm4(kh4[0], kh4[1], kh4[2], kh4[3], ro);
                mma_f16(s[2 * gr], qhf[ks], kh4);
                mma_f16(s[2 * gr], qlf[ks], kh4);
                mma_f16(s[2 * gr + 1], qhf[ks], kh4 + 2);
                mma_f16(s[2 * gr + 1], qlf[ks], kh4 + 2);
            }
        }

        if (t >= 2 * qt) {
#pragma unroll
            for (int j = 0; j < 8; j++) {
                int c0 = t * 64 + j * 8 + 2 * t4;
                if (c0 > row0g)     s[j][0] = -1e30f;
                if (c0 + 1 > row0g) s[j][1] = -1e30f;
                if (c0 > row0g + 8)     s[j][2] = -1e30f;
                if (c0 + 1 > row0g + 8) s[j][3] = -1e30f;
            }
        }

        float tm0 = -1e30f, tm1 = -1e30f;
#pragma unroll
        for (int j = 0; j < 8; j++) {
            tm0 = fmaxf(tm0, fmaxf(s[j][0], s[j][1]));
            tm1 = fmaxf(tm1, fmaxf(s[j][2], s[j][3]));
        }
        tm0 = fmaxf(tm0, __shfl_xor_sync(0xffffffffu, tm0, 1));
        tm0 = fmaxf(tm0, __shfl_xor_sync(0xffffffffu, tm0, 2));
        tm1 = fmaxf(tm1, __shfl_xor_sync(0xffffffffu, tm1, 1));
        tm1 = fmaxf(tm1, __shfl_xor_sync(0xffffffffu, tm1, 2));
        float mn0 = fmaxf(m0, tm0), mn1 = fmaxf(m1, tm1);
        float cor0 = fexp2((m0 - mn0) * L2E);
        float cor1 = fexp2((m1 - mn1) * L2E);
        m0 = mn0; m1 = mn1;
#pragma unroll
        for (int j = 0; j < 16; j++) {
            o[j][0] *= cor0; o[j][1] *= cor0;
            o[j][2] *= cor1; o[j][3] *= cor1;
        }
        float rs0 = 0.f, rs1 = 0.f;
#pragma unroll
        for (int j = 0; j < 8; j++) {
            s[j][0] = fexp2((s[j][0] - mn0) * L2E);
            s[j][1] = fexp2((s[j][1] - mn0) * L2E);
            s[j][2] = fexp2((s[j][2] - mn1) * L2E);
            s[j][3] = fexp2((s[j][3] - mn1) * L2E);
            rs0 += s[j][0] + s[j][1];
            rs1 += s[j][2] + s[j][3];
        }
        rs0 += __shfl_xor_sync(0xffffffffu, rs0, 1);
        rs0 += __shfl_xor_sync(0xffffffffu, rs0, 2);
        rs1 += __shfl_xor_sync(0xffffffffu, rs1, 1);
        rs1 += __shfl_xor_sync(0xffffffffu, rs1, 2);
        l0 = l0 * cor0 + rs0;
        l1 = l1 * cor1 + rs1;

        // ---- O += P V (1-pass: Ph only) ----
#pragma unroll
        for (int ks = 0; ks < 4; ks++) {
            uint32_t pha[4];
            pha[0] = pack_h2(s[2 * ks][0], s[2 * ks][1]);
            pha[1] = pack_h2(s[2 * ks][2], s[2 * ks][3]);
            pha[2] = pack_h2(s[2 * ks + 1][0], s[2 * ks + 1][1]);
            pha[3] = pack_h2(s[2 * ks + 1][2], s[2 * ks + 1][3]);
#pragma unroll
            for (int gr = 0; gr < 8; gr++) {
                uint32_t vh4[4];
                uint32_t ro = st + KVT + (ks * 16 + arow) * ARB +
                              gr * 32 + vcolB;
                ldsm4t(vh4[0], vh4[1], vh4[2], vh4[3], ro);
                mma_f16(o[2 * gr], pha, vh4);
                mma_f16(o[2 * gr + 1], pha, vh4 + 2);
            }
        }
        __syncthreads();
        if (t + 2 < NT) load_stage(t & 1, t + 2);
    }

    // ---- epilogue: normalize, split hi/lo, write g_Xhi/g_Xlo [b][s][h*d] ----
    float inv0 = 1.f / l0, inv1 = 1.f / l1;
    const int r0 = qt * 128 + wm + g, r1 = r0 + 8;
#pragma unroll
    for (int j = 0; j < 16; j++) {
        int col = h * 128 + j * 8 + 2 * t4;
        float a0 = o[j][0] * inv0, a1 = o[j][1] * inv0;
        float b0 = o[j][2] * inv1, b1 = o[j][3] * inv1;
        size_t i0 = ((size_t)(b * Sn + r0)) * 4096 + col;
        size_t i1 = ((size_t)(b * Sn + r1)) * 4096 + col;
        uint32_t h0 = pack_h2(a0, a1);
        uint32_t h1 = pack_h2(b0, b1);
        *reinterpret_cast<uint32_t*>(&g_Xhi[i0]) = h0;
        *reinterpret_cast<uint32_t*>(&g_Xlo[i0]) = pack_h2_res(a0, a1, h0);
        *reinterpret_cast<uint32_t*>(&g_Xhi[i1]) = h1;
        *reinterpret_cast<uint32_t*>(&g_Xlo[i1]) = pack_h2_res(b0, b1, h1);
    }
}

// ---------------------------------------------------------------------------
extern "C" void kernel_launch(void* const* d_in, const int* in_sizes, int n_in,
                              void* d_out, int out_size)
{
    const float* hidden = (const float*)d_in[0];
    const float* Wq = (const float*)d_in[2];
    const float* Wk = (const float*)d_in[3];
    const float* Wv = (const float*)d_in[4];
    const float* Wo = (const float*)d_in[5];
    float* out = (float*)d_out;

    float *pQ, *pK, *pV;
    __half *pXh, *pXl, *pQT, *pKT, *pVT, *pOT;
    cudaGetSymbolAddress((void**)&pQ, g_Q);
    cudaGetSymbolAddress((void**)&pK, g_K);
    cudaGetSymbolAddress((void**)&pV, g_V);
    cudaGetSymbolAddress((void**)&pXh, g_Xhi);
    cudaGetSymbolAddress((void**)&pXl, g_Xlo);
    cudaGetSymbolAddress((void**)&pQT, g_WqTh);
    cudaGetSymbolAddress((void**)&pKT, g_WkTh);
    cudaGetSymbolAddress((void**)&pVT, g_WvTh);
    cudaGetSymbolAddress((void**)&pOT, g_WoTh);

    cudaFuncSetAttribute(hgemm_kernel<0>,
                         cudaFuncAttributeMaxDynamicSharedMemorySize, HG_SMEM);
    cudaFuncSetAttribute(hgemm_kernel<5>,
                         cudaFuncAttributeMaxDynamicSharedMemorySize, HG_SMEM);
    cudaFuncSetAttribute(attn_mma_kernel,
                         cudaFuncAttributeMaxDynamicSharedMemorySize, AT_SMEM);

    const int n4x = Mn * Hn / 4;
    dim3 tb(32, 8);

    split_kernel<<<n4x / 256, 256>>>(hidden, pXh, pXl, n4x);                 // 1
    tsplit_kernel<<<dim3(4096 / 32, 4096 / 32), tb>>>(Wq, pQT, Hn, 4096);    // 2
    tsplit_kernel<<<dim3(1024 / 32, 4096 / 32), tb>>>(Wk, pKT, Hn, 1024);    // 3
    tsplit_kernel<<<dim3(1024 / 32, 4096 / 32), tb>>>(Wv, pVT, Hn, 1024);    // 4

    // fused Q+K+V projection GEMM
    hgemm_kernel<5><<<dim3(32, Mn / 128, 2), 256, HG_SMEM>>>(                // 5
        pXh, pXl, pQT, pKT, pVT, pQ, pK, pV, 4096, Hn);

    tsplit_kernel<<<dim3(4096 / 32, 4096 / 32), tb>>>(Wo, pOT, 4096, Hn);    // 6

    // fused RoPE(Q hi+lo) + RoPE(K hi) + V split
    ropeall_kernel<<<RS_BLKS, 256>>>();                                      // 7

    // causal flash attention (LPT; writes hi/lo into g_Xhi/g_Xlo)
    dim3 ga(Sn / 128, NHn, Bn);
    attn_mma_kernel<<<ga, 256, AT_SMEM>>>();                                 // 8

    // output projection
    hgemm_kernel<0><<<dim3(4096 / 128, Mn / 128), 256, HG_SMEM>>>(           // 9
        pXh, pXl, pOT, nullptr, nullptr, out, nullptr, nullptr, 4096, Hn);
}

// round 16
// speedup vs baseline: 2.9863x; 1.1792x over previous
#include <cuda_runtime.h>
#include <cuda_fp16.h>
#include <math.h>
#include <stdint.h>

// Problem dims
constexpr int Bn = 2, Sn = 2048, Hn = 4096, NHn = 32, NKVn = 8, HDn = 128;
constexpr int Mn = Bn * Sn;
constexpr float QK_SCALE = 0.08838834764831845f; // 1/sqrt(128)
constexpr float L2E = 1.4426950408889634f;

// fp32 scratch (pre-RoPE projection outputs)
__device__ float g_Q[(size_t)Bn * NHn * Sn * HDn];   // [b][h][s][d]
__device__ float g_K[(size_t)Bn * NKVn * Sn * HDn];  // [b][kh][s][d]
__device__ float g_V[(size_t)Bn * NKVn * Sn * HDn];

// fp16 split scratch (A-side: hi+lo; B-side: hi only)
__device__ __half g_Xhi[(size_t)Mn * Hn];   // X split; reused for attn out
__device__ __half g_Xlo[(size_t)Mn * Hn];
__device__ __half g_WqTh[(size_t)4096 * 4096];
__device__ __half g_WkTh[(size_t)1024 * 4096];
__device__ __half g_WvTh[(size_t)1024 * 4096];
__device__ __half g_WoTh[(size_t)4096 * 4096];
// attention operands (post-RoPE): Q hi+lo (A-side), K/V hi only (B-side)
__device__ __half g_Qh[(size_t)Bn * NHn * Sn * HDn];
__device__ __half g_Ql[(size_t)Bn * NHn * Sn * HDn];
__device__ __half g_Kh[(size_t)Bn * NKVn * Sn * HDn];
__device__ __half g_Vh[(size_t)Bn * NKVn * Sn * HDn];

// ---------------------------------------------------------------------------
// helpers
// ---------------------------------------------------------------------------
__device__ __forceinline__ uint32_t smem_u32(const void* p) {
    uint32_t a;
    asm("{ .reg .u64 t; cvta.to.shared.u64 t, %1; cvt.u32.u64 %0, t; }"
        : "=r"(a) : "l"(p));
    return a;
}
__device__ __forceinline__ void cpa16(uint32_t dst, const void* src) {
    asm volatile("cp.async.cg.shared.global [%0], [%1], 16;"
                 :: "r"(dst), "l"(src) : "memory");
}
__device__ __forceinline__ void ldsm4(uint32_t& r0, uint32_t& r1,
                                      uint32_t& r2, uint32_t& r3, uint32_t a) {
    asm volatile("ldmatrix.sync.aligned.m8n8.x4.shared.b16 {%0,%1,%2,%3}, [%4];"
                 : "=r"(r0), "=r"(r1), "=r"(r2), "=r"(r3) : "r"(a));
}
__device__ __forceinline__ void ldsm4t(uint32_t& r0, uint32_t& r1,
                                       uint32_t& r2, uint32_t& r3, uint32_t a) {
    asm volatile("ldmatrix.sync.aligned.m8n8.x4.trans.shared.b16 {%0,%1,%2,%3}, [%4];"
                 : "=r"(r0), "=r"(r1), "=r"(r2), "=r"(r3) : "r"(a));
}
__device__ __forceinline__ void mma_f16(float* c, const uint32_t* a,
                                        const uint32_t* b) {
    asm volatile(
        "mma.sync.aligned.m16n8k16.row.col.f32.f16.f16.f32 "
        "{%0,%1,%2,%3}, {%4,%5,%6,%7}, {%8,%9}, {%0,%1,%2,%3};"
        : "+f"(c[0]), "+f"(c[1]), "+f"(c[2]), "+f"(c[3])
        : "r"(a[0]), "r"(a[1]), "r"(a[2]), "r"(a[3]), "r"(b[0]), "r"(b[1]));
}
// fast exp2 on the FMA pipe (y <= 0; clamp makes masked rows vanish)
__device__ __forceinline__ float fexp2(float y) {
    y = fmaxf(y, -126.f);
    float fl = floorf(y);
    float f = y - fl;
    float p = 1.8775767e-3f;
    p = fmaf(p, f, 8.9893397e-3f);
    p = fmaf(p, f, 5.5826318e-2f);
    p = fmaf(p, f, 2.4015361e-1f);
    p = fmaf(p, f, 6.9315308e-1f);
    p = fmaf(p, f, 9.9999994e-1f);
    return __int_as_float(((int)fl + 127) << 23) * p;
}
__device__ __forceinline__ uint32_t pack_h2(float a, float b) {
    __half2 v = __floats2half2_rn(a, b);
    return *reinterpret_cast<uint32_t*>(&v);
}
__device__ __forceinline__ uint32_t pack_h2_res(float a, float b, uint32_t hi) {
    __half2 hv = *reinterpret_cast<__half2*>(&hi);
    return pack_h2(a - __half2float(hv.x), b - __half2float(hv.y));
}

// ---------------------------------------------------------------------------
// Split conversion: x -> hi fp16 (+ optional lo fp16)
// ---------------------------------------------------------------------------
__global__ void split_kernel(const float* __restrict__ x,
                             __half* __restrict__ hi,
                             __half* __restrict__ lo, int n4)
{
    int i = blockIdx.x * 256 + threadIdx.x;
    if (i >= n4) return;
    float4 v = reinterpret_cast<const float4*>(x)[i];
    uint32_t h01 = pack_h2(v.x, v.y);
    uint32_t h23 = pack_h2(v.z, v.w);
    reinterpret_cast<uint32_t*>(hi)[i * 2 + 0] = h01;
    reinterpret_cast<uint32_t*>(hi)[i * 2 + 1] = h23;
    if (lo) {
        reinterpret_cast<uint32_t*>(lo)[i * 2 + 0] = pack_h2_res(v.x, v.y, h01);
        reinterpret_cast<uint32_t*>(lo)[i * 2 + 1] = pack_h2_res(v.z, v.w, h23);
    }
}

// ---------------------------------------------------------------------------
// Transpose + fp16 truncation: W[K][N] fp32 -> Th[N][K] fp16 (hi only)
// ---------------------------------------------------------------------------
__global__ void tsplit_kernel(const float* __restrict__ W,
                              __half* __restrict__ Thi, int K, int N)
{
    __shared__ float t[32][33];
    int tx = threadIdx.x, ty = threadIdx.y;
    int bx = blockIdx.x, by = blockIdx.y;
#pragma unroll
    for (int i = 0; i < 4; i++) {
        int r = by * 32 + ty + i * 8;
        t[ty + i * 8][tx] = W[(size_t)r * N + bx * 32 + tx];
    }
    __syncthreads();
#pragma unroll
    for (int i = 0; i < 4; i++) {
        int n = bx * 32 + ty + i * 8;
        int k = by * 32 + tx;
        Thi[(size_t)n * K + k] = __float2half_rn(t[tx][ty + i * 8]);
    }
}

// ---------------------------------------------------------------------------
// Fused post-projection conversions: Q rope hi+lo, K rope hi, V split hi.
// ---------------------------------------------------------------------------
constexpr int RQ_BLK = Bn * NHn * Sn * 64 / 256;     // 32768
constexpr int RK_BLK = Bn * NKVn * Sn * 64 / 256;    // 8192
constexpr int SV_BLK = Bn * NKVn * Sn * HDn / 4 / 256; // 4096
constexpr int RS_BLKS = RQ_BLK + RK_BLK + SV_BLK;    // 45056

__device__ __forceinline__ void rope_seg(const float* __restrict__ X,
                                         __half* __restrict__ H,
                                         __half* __restrict__ L,
                                         int idx, float scale)
{
    int d = idx & 63;
    int s = (idx >> 6) & (Sn - 1);
    int bh = idx >> 17;
    float inv = powf(10000.f, -(float)d / 64.f);
    float ang = (float)s * inv;
    float sn, cs;
    sincosf(ang, &sn, &cs);
    size_t base = ((size_t)bh * Sn + s) * HDn;
    float x0 = X[base + d];
    float x1 = X[base + d + 64];
    float r0 = (x0 * cs - x1 * sn) * scale;
    float r1 = (x1 * cs + x0 * sn) * scale;
    __half h0 = __float2half_rn(r0);
    __half h1 = __float2half_rn(r1);
    H[base + d] = h0;
    H[base + d + 64] = h1;
    if (L) {
        L[base + d] = __float2half_rn(r0 - __half2float(h0));
        L[base + d + 64] = __float2half_rn(r1 - __half2float(h1));
    }
}

__global__ __launch_bounds__(256) void ropeall_kernel()
{
    int bid = blockIdx.x, tid = threadIdx.x;
    if (bid < RQ_BLK) {
        rope_seg(g_Q, g_Qh, g_Ql, bid * 256 + tid, QK_SCALE);
        return;
    }
    bid -= RQ_BLK;
    if (bid < RK_BLK) {
        rope_seg(g_K, g_Kh, nullptr, bid * 256 + tid, 1.f);
        return;
    }
    bid -= RK_BLK;
    {   // V hi-only split
        int i = bid * 256 + tid;
        float4 v = reinterpret_cast<const float4*>(g_V)[i];
        reinterpret_cast<uint32_t*>(g_Vh)[i * 2 + 0] = pack_h2(v.x, v.y);
        reinterpret_cast<uint32_t*>(g_Vh)[i * 2 + 1] = pack_h2(v.z, v.w);
    }
}

// ---------------------------------------------------------------------------
// fp16 GEMM on mma.sync: CTA 128x128, K-chunk 32, 2-stage cp.async, 80 B/row,
// 2 CTAs/SM.
// MODE 5: fused QKV, 2-pass C = (Ah+Al)@Bh^T, blockIdx.z decode.
// MODE 6: O projection, 1-pass C = Ah@Bh^T, row-major out (A-lo dropped:
//         attention output truncation adds ~2e-4 in quadrature, measured-safe).
// ---------------------------------------------------------------------------
constexpr int TROW = 80;
constexpr int TTILE = 128 * TROW;         // 10240 B
constexpr int TSTAGE = 3 * TTILE;         // 30720 B (Ah, Al, Bh)
constexpr int HG_SMEM = 2 * TSTAGE;       // 61440 B

template <int MODE>
__global__ __launch_bounds__(256, 2) void hgemm_kernel(
    const __half* __restrict__ Ahi, const __half* __restrict__ Alo,
    const __half* __restrict__ Bq, const __half* __restrict__ Bk,
    const __half* __restrict__ Bv,
    float* __restrict__ Cq, float* __restrict__ Ck, float* __restrict__ Cv,
    int N0, int K)
{
    extern __shared__ char smem[];
    const uint32_t sb = smem_u32(smem);

    const int tid = threadIdx.x;
    const int wid = tid >> 5, lane = tid & 31;
    const int g = lane >> 2, t4 = lane & 3;
    const int wr = wid >> 2, wc = wid & 3;
    const int wm = wr * 64, wn = wc * 32;

    int N = N0, heads = NHn;
    const __half* Bsel = Bq;
    float* Csel = Cq;
    int n0 = blockIdx.x * 128;
    const int m0 = blockIdx.y * 128;
    if (MODE == 5 && blockIdx.z == 1) {
        const int bx = blockIdx.x;
        if (bx >= 16) return;
        N = 1024; heads = NKVn;
        n0 = (bx & 7) * 128;
        Bsel = (bx < 8) ? Bk : Bv;
        Csel = (bx < 8) ? Ck : Cv;
    }

    const __half* Ah = Ahi + (size_t)m0 * K;
    const __half* Al = (MODE == 6) ? nullptr : Alo + (size_t)m0 * K;
    const __half* Bh = Bsel + (size_t)n0 * K;

    float c[4][4][4];
#pragma unroll
    for (int mi = 0; mi < 4; mi++)
#pragma unroll
        for (int ni = 0; ni < 4; ni++)
#pragma unroll
            for (int r = 0; r < 4; r++) c[mi][ni][r] = 0.f;

    auto load_chunk = [&](int stage, int koff) {
        const uint32_t base = sb + stage * TSTAGE;
#pragma unroll
        for (int i = 0; i < 6; i++) {
            const int tile = i >> 1;
            if (MODE == 6 && tile == 1) continue;   // no A-lo tile
            const int id = tid + (i & 1) * 256;
            const int r = id >> 2, c4 = id & 3;
            const __half* s = (tile == 0) ? Ah : (tile == 1) ? Al : Bh;
            cpa16(base + tile * TTILE + r * TROW + c4 * 16,
                  s + (size_t)r * K + koff + c4 * 8);
        }
        asm volatile("cp.async.commit_group;" ::: "memory");
    };

    const int NC = K / 32;
    load_chunk(0, 0);
    load_chunk(1, 32);

    const int arow_off = (lane & 7) + ((lane >> 3) & 1) * 8;
    const int acol_off = (lane >> 4) * 8;
    const int brow_off = (lane & 7) + (lane >> 4) * 8;
    const int bcol_off = ((lane >> 3) & 1) * 8;

    for (int ch = 0; ch < NC; ch++) {
        if (ch + 1 < NC)
            asm volatile("cp.async.wait_group 1;" ::: "memory");
        else
            asm volatile("cp.async.wait_group 0;" ::: "memory");
        __syncthreads();

        const uint32_t st = sb + (ch & 1) * TSTAGE;
        const uint32_t ah_b = st, al_b = st + TTILE, bh_b = st + 2 * TTILE;

#pragma unroll
        for (int kk = 0; kk < 32; kk += 16) {
            uint32_t fah[4][4], fal[4][4], fbh[4][2];
#pragma unroll
            for (int mi = 0; mi < 4; mi++) {
                const uint32_t ro = (wm + mi * 16 + arow_off) * TROW +
                                    (kk + acol_off) * 2;
                ldsm4(fah[mi][0], fah[mi][1], fah[mi][2], fah[mi][3], ah_b + ro);
                if (MODE != 6)
                    ldsm4(fal[mi][0], fal[mi][1], fal[mi][2], fal[mi][3],
                          al_b + ro);
            }
#pragma unroll
            for (int bt = 0; bt < 2; bt++) {
                const uint32_t ro = (wn + bt * 16 + brow_off) * TROW +
                                    (kk + bcol_off) * 2;
                ldsm4(fbh[2 * bt][0], fbh[2 * bt][1],
                      fbh[2 * bt + 1][0], fbh[2 * bt + 1][1], bh_b + ro);
            }
#pragma unroll
            for (int mi = 0; mi < 4; mi++)
#pragma unroll
                for (int ni = 0; ni < 4; ni++) {
                    mma_f16(c[mi][ni], fah[mi], fbh[ni]);
                    if (MODE != 6)
                        mma_f16(c[mi][ni], fal[mi], fbh[ni]);
                }
        }
        __syncthreads();
        if (ch + 2 < NC) load_chunk(ch & 1, (ch + 2) * 32);
    }

    if (MODE == 6) {
        // row-major fp32 store (output projection)
#pragma unroll
        for (int mi = 0; mi < 4; mi++)
#pragma unroll
            for (int ni = 0; ni < 4; ni++) {
                const int row0 = m0 + wm + mi * 16 + g;
                const int col = n0 + wn + ni * 8 + 2 * t4;
#pragma unroll
                for (int half = 0; half < 2; half++) {
                    const int m = row0 + half * 8;
                    float2 v = half ? make_float2(c[mi][ni][2], c[mi][ni][3])
                                    : make_float2(c[mi][ni][0], c[mi][ni][1]);
                    *reinterpret_cast<float2*>(&Csel[(size_t)m * N + col]) = v;
                }
            }
    } else {
#pragma unroll
        for (int mi = 0; mi < 4; mi++)
#pragma unroll
            for (int ni = 0; ni < 4; ni++) {
                const int row0 = m0 + wm + mi * 16 + g;
                const int col = n0 + wn + ni * 8 + 2 * t4;
#pragma unroll
                for (int half = 0; half < 2; half++) {
                    const int m = row0 + half * 8;
                    float2 v = half ? make_float2(c[mi][ni][2], c[mi][ni][3])
                                    : make_float2(c[mi][ni][0], c[mi][ni][1]);
                    int b = m >> 11, s = m & 2047;
                    int h = col >> 7, d = col & 127;
                    *reinterpret_cast<float2*>(
                        &Csel[(((size_t)(b * heads + h) * Sn) + s) * HDn + d]) = v;
                }
            }
    }
}

// ---------------------------------------------------------------------------
// Flash attention, fp16: scores = (Qh+Ql)·Kh (2-pass), O = Ph·Vh (1-pass).
// BQ=128, BK=64, 8 warps, 2-stage pipeline, LPT order.
// Output hi fp16 only into g_Xhi (O-proj is 1-pass; lo not needed).
// ---------------------------------------------------------------------------
constexpr int ARB = 272;
constexpr int KVT = 64 * ARB;             // 17408 B
constexpr int ASTG = 2 * KVT;             // Kh, Vh per stage = 34816 B
constexpr int AT_SMEM = 2 * ASTG + 2 * 34816;  // + Qh + Ql = 139264 B

__global__ __launch_bounds__(256, 1) void attn_mma_kernel()
{
    extern __shared__ char smem[];
    const uint32_t sb = smem_u32(smem);
    const int qt = (int)gridDim.x - 1 - blockIdx.x;   // LPT order
    const int h = blockIdx.y, b = blockIdx.z;
    const int tid = threadIdx.x, wid = tid >> 5, lane = tid & 31;
    const int g = lane >> 2, t4 = lane & 3;
    const int wm = wid * 16;
    const int kvh = h >> 2;
    const int NT = 2 * (qt + 1);

    const __half* Qhp = g_Qh + ((size_t)(b * NHn + h) * Sn + qt * 128) * HDn;
    const __half* Qlp = g_Ql + ((size_t)(b * NHn + h) * Sn + qt * 128) * HDn;
    const __half* Khp = g_Kh + ((size_t)(b * NKVn + kvh) * Sn) * HDn;
    const __half* Vhp = g_Vh + ((size_t)(b * NKVn + kvh) * Sn) * HDn;

    const uint32_t qhb = sb + 2 * ASTG, qlb = sb + 2 * ASTG + 34816;
#pragma unroll
    for (int i = 0; i < 8; i++) {
        int id = tid + i * 256, r = id >> 4, c = id & 15;
        cpa16(qhb + r * ARB + c * 16, Qhp + r * HDn + c * 8);
        cpa16(qlb + r * ARB + c * 16, Qlp + r * HDn + c * 8);
    }
    asm volatile("cp.async.commit_group;" ::: "memory");

    auto load_stage = [&](int stg, int t) {
        const uint32_t st = sb + stg * ASTG;
        const __half* kh = Khp + (size_t)t * 64 * HDn;
        const __half* vh = Vhp + (size_t)t * 64 * HDn;
#pragma unroll
        for (int i = 0; i < 4; i++) {
            int id = tid + i * 256, r = id >> 4, c = id & 15;
            cpa16(st + 0 * KVT + r * ARB + c * 16, kh + r * HDn + c * 8);
            cpa16(st + 1 * KVT + r * ARB + c * 16, vh + r * HDn + c * 8);
        }
        asm volatile("cp.async.commit_group;" ::: "memory");
    };
    load_stage(0, 0);

    asm volatile("cp.async.wait_group 1;" ::: "memory");  // Q arrived
    __syncthreads();

    const int arow = (lane & 7) + ((lane >> 3) & 1) * 8;
    const int acolB = (lane >> 4) * 16;
    uint32_t qhf[8][4], qlf[8][4];
#pragma unroll
    for (int ks = 0; ks < 8; ks++) {
        uint32_t ro = (wm + arow) * ARB + ks * 32 + acolB;
        ldsm4(qhf[ks][0], qhf[ks][1], qhf[ks][2], qhf[ks][3], qhb + ro);
        ldsm4(qlf[ks][0], qlf[ks][1], qlf[ks][2], qlf[ks][3], qlb + ro);
    }
    __syncthreads();
    load_stage(1, 1);

    float o[16][4];
#pragma unroll
    for (int j = 0; j < 16; j++)
#pragma unroll
        for (int e = 0; e < 4; e++) o[j][e] = 0.f;
    float m0 = -1e30f, m1 = -1e30f, l0 = 0.f, l1 = 0.f;

    const int brow = (lane & 7) + (lane >> 4) * 8;
    const int bcolB = ((lane >> 3) & 1) * 16;
    const int vcolB = (lane >> 4) * 16;
    const int row0g = qt * 128 + wm + g;

    for (int t = 0; t < NT; t++) {
        if (t + 1 < NT)
            asm volatile("cp.async.wait_group 1;" ::: "memory");
        else
            asm volatile("cp.async.wait_group 0;" ::: "memory");
        __syncthreads();
        const uint32_t st = sb + (t & 1) * ASTG;

        float s[8][4];
#pragma unroll
        for (int j = 0; j < 8; j++)
#pragma unroll
            for (int e = 0; e < 4; e++) s[j][e] = 0.f;

#pragma unroll
        for (int ks = 0; ks < 8; ks++) {
#pragma unroll
            for (int gr = 0; gr < 4; gr++) {
                uint32_t kh4[4];
                uint32_t ro = st + (gr * 16 + brow) * ARB + ks * 32 + bcolB;
                ldsm4(kh4[0], kh4[1], kh4[2], kh4[3], ro);
                mma_f16(s[2 * gr], qhf[ks], kh4);
                mma_f16(s[2 * gr], qlf[ks], kh4);
                mma_f16(s[2 * gr + 1], qhf[ks], kh4 + 2);
                mma_f16(s[2 * gr + 1], qlf[ks], kh4 + 2);
            }
        }

        if (t >= 2 * qt) {
#pragma unroll
            for (int j = 0; j < 8; j++) {
                int c0 = t * 64 + j * 8 + 2 * t4;
                if (c0 > row0g)     s[j][0] = -1e30f;
                if (c0 + 1 > row0g) s[j][1] = -1e30f;
                if (c0 > row0g + 8)     s[j][2] = -1e30f;
                if (c0 + 1 > row0g + 8) s[j][3] = -1e30f;
            }
        }

        float tm0 = -1e30f, tm1 = -1e30f;
#pragma unroll
        for (int j = 0; j < 8; j++) {
            tm0 = fmaxf(tm0, fmaxf(s[j][0], s[j][1]));
            tm1 = fmaxf(tm1, fmaxf(s[j][2], s[j][3]));
        }
        tm0 = fmaxf(tm0, __shfl_xor_sync(0xffffffffu, tm0, 1));
        tm0 = fmaxf(tm0, __shfl_xor_sync(0xffffffffu, tm0, 2));
        tm1 = fmaxf(tm1, __shfl_xor_sync(0xffffffffu, tm1, 1));
        tm1 = fmaxf(tm1, __shfl_xor_sync(0xffffffffu, tm1, 2));
        float mn0 = fmaxf(m0, tm0), mn1 = fmaxf(m1, tm1);
        float cor0 = fexp2((m0 - mn0) * L2E);
        float cor1 = fexp2((m1 - mn1) * L2E);
        m0 = mn0; m1 = mn1;
#pragma unroll
        for (int j = 0; j < 16; j++) {
            o[j][0] *= cor0; o[j][1] *= cor0;
            o[j][2] *= cor1; o[j][3] *= cor1;
        }
        float rs0 = 0.f, rs1 = 0.f;
#pragma unroll
        for (int j = 0; j < 8; j++) {
            s[j][0] = fexp2((s[j][0] - mn0) * L2E);
            s[j][1] = fexp2((s[j][1] - mn0) * L2E);
            s[j][2] = fexp2((s[j][2] - mn1) * L2E);
            s[j][3] = fexp2((s[j][3] - mn1) * L2E);
            rs0 += s[j][0] + s[j][1];
            rs1 += s[j][2] + s[j][3];
        }
        rs0 += __shfl_xor_sync(0xffffffffu, rs0, 1);
        rs0 += __shfl_xor_sync(0xffffffffu, rs0, 2);
        rs1 += __shfl_xor_sync(0xffffffffu, rs1, 1);
        rs1 += __shfl_xor_sync(0xffffffffu, rs1, 2);
        l0 = l0 * cor0 + rs0;
        l1 = l1 * cor1 + rs1;

        // ---- O += P V (1-pass: Ph only) ----
#pragma unroll
        for (int ks = 0; ks < 4; ks++) {
            uint32_t pha[4];
            pha[0] = pack_h2(s[2 * ks][0], s[2 * ks][1]);
            pha[1] = pack_h2(s[2 * ks][2], s[2 * ks][3]);
            pha[2] = pack_h2(s[2 * ks + 1][0], s[2 * ks + 1][1]);
            pha[3] = pack_h2(s[2 * ks + 1][2], s[2 * ks + 1][3]);
#pragma unroll
            for (int gr = 0; gr < 8; gr++) {
                uint32_t vh4[4];
                uint32_t ro = st + KVT + (ks * 16 + arow) * ARB +
                              gr * 32 + vcolB;
                ldsm4t(vh4[0], vh4[1], vh4[2], vh4[3], ro);
                mma_f16(o[2 * gr], pha, vh4);
                mma_f16(o[2 * gr + 1], pha, vh4 + 2);
            }
        }
        __syncthreads();
        if (t + 2 < NT) load_stage(t & 1, t + 2);
    }

    // ---- epilogue: normalize, write hi fp16 into g_Xhi [b][s][h*d] ----
    float inv0 = 1.f / l0, inv1 = 1.f / l1;
    const int r0 = qt * 128 + wm + g, r1 = r0 + 8;
#pragma unroll
    for (int j = 0; j < 16; j++) {
        int col = h * 128 + j * 8 + 2 * t4;
        size_t i0 = ((size_t)(b * Sn + r0)) * 4096 + col;
        size_t i1 = ((size_t)(b * Sn + r1)) * 4096 + col;
        *reinterpret_cast<uint32_t*>(&g_Xhi[i0]) =
            pack_h2(o[j][0] * inv0, o[j][1] * inv0);
        *reinterpret_cast<uint32_t*>(&g_Xhi[i1]) =
            pack_h2(o[j][2] * inv1, o[j][3] * inv1);
    }
}

// ---------------------------------------------------------------------------
extern "C" void kernel_launch(void* const* d_in, const int* in_sizes, int n_in,
                              void* d_out, int out_size)
{
    const float* hidden = (const float*)d_in[0];
    const float* Wq = (const float*)d_in[2];
    const float* Wk = (const float*)d_in[3];
    const float* Wv = (const float*)d_in[4];
    const float* Wo = (const float*)d_in[5];
    float* out = (float*)d_out;

    float *pQ, *pK, *pV;
    __half *pXh, *pXl, *pQT, *pKT, *pVT, *pOT;
    cudaGetSymbolAddress((void**)&pQ, g_Q);
    cudaGetSymbolAddress((void**)&pK, g_K);
    cudaGetSymbolAddress((void**)&pV, g_V);
    cudaGetSymbolAddress((void**)&pXh, g_Xhi);
    cudaGetSymbolAddress((void**)&pXl, g_Xlo);
    cudaGetSymbolAddress((void**)&pQT, g_WqTh);
    cudaGetSymbolAddress((void**)&pKT, g_WkTh);
    cudaGetSymbolAddress((void**)&pVT, g_WvTh);
    cudaGetSymbolAddress((void**)&pOT, g_WoTh);

    cudaFuncSetAttribute(hgemm_kernel<5>,
                         cudaFuncAttributeMaxDynamicSharedMemorySize, HG_SMEM);
    cudaFuncSetAttribute(hgemm_kernel<6>,
                         cudaFuncAttributeMaxDynamicSharedMemorySize, HG_SMEM);
    cudaFuncSetAttribute(attn_mma_kernel,
                         cudaFuncAttributeMaxDynamicSharedMemorySize, AT_SMEM);

    const int n4x = Mn * Hn / 4;
    dim3 tb(32, 8);

    split_kernel<<<n4x / 256, 256>>>(hidden, pXh, pXl, n4x);                 // 1
    tsplit_kernel<<<dim3(4096 / 32, 4096 / 32), tb>>>(Wq, pQT, Hn, 4096);    // 2
    tsplit_kernel<<<dim3(1024 / 32, 4096 / 32), tb>>>(Wk, pKT, Hn, 1024);    // 3
    tsplit_kernel<<<dim3(1024 / 32, 4096 / 32), tb>>>(Wv, pVT, Hn, 1024);    // 4

    // fused Q+K+V projection GEMM (2-pass)
    hgemm_kernel<5><<<dim3(32, Mn / 128, 2), 256, HG_SMEM>>>(                // 5
        pXh, pXl, pQT, pKT, pVT, pQ, pK, pV, 4096, Hn);

    tsplit_kernel<<<dim3(4096 / 32, 4096 / 32), tb>>>(Wo, pOT, 4096, Hn);    // 6

    // fused RoPE(Q hi+lo) + RoPE(K hi) + V split
    ropeall_kernel<<<RS_BLKS, 256>>>();                                      // 7

    // causal flash attention (LPT; writes hi fp16 into g_Xhi)
    dim3 ga(Sn / 128, NHn, Bn);
    attn_mma_kernel<<<ga, 256, AT_SMEM>>>();                                 // 8

    // output projection (1-pass fp16: out = Xhi @ WoT)
    hgemm_kernel<6><<<dim3(4096 / 128, Mn / 128), 256, HG_SMEM>>>(           // 9
        pXh, nullptr, pOT, nullptr, nullptr, out, nullptr, nullptr, 4096, Hn);
}

// round 17
// speedup vs baseline: 3.0952x; 1.0365x over previous
#include <cuda_runtime.h>
#include <cuda_fp16.h>
#include <math.h>
#include <stdint.h>

// Problem dims
constexpr int Bn = 2, Sn = 2048, Hn = 4096, NHn = 32, NKVn = 8, HDn = 128;
constexpr int Mn = Bn * Sn;
constexpr float QK_SCALE = 0.08838834764831845f; // 1/sqrt(128)
constexpr float L2E = 1.4426950408889634f;

// fp32 scratch (pre-RoPE projection outputs)
__device__ float g_Q[(size_t)Bn * NHn * Sn * HDn];   // [b][h][s][d]
__device__ float g_K[(size_t)Bn * NKVn * Sn * HDn];  // [b][kh][s][d]
__device__ float g_V[(size_t)Bn * NKVn * Sn * HDn];

// fp16 split scratch (X: hi+lo for QKV proj; weights hi only)
__device__ __half g_Xhi[(size_t)Mn * Hn];   // X split; reused for attn out
__device__ __half g_Xlo[(size_t)Mn * Hn];
__device__ __half g_WqTh[(size_t)4096 * 4096];
__device__ __half g_WkTh[(size_t)1024 * 4096];
__device__ __half g_WvTh[(size_t)1024 * 4096];
__device__ __half g_WoTh[(size_t)4096 * 4096];
// attention operands (post-RoPE): all hi-only fp16
__device__ __half g_Qh[(size_t)Bn * NHn * Sn * HDn];
__device__ __half g_Kh[(size_t)Bn * NKVn * Sn * HDn];
__device__ __half g_Vh[(size_t)Bn * NKVn * Sn * HDn];

// ---------------------------------------------------------------------------
// helpers
// ---------------------------------------------------------------------------
__device__ __forceinline__ uint32_t smem_u32(const void* p) {
    uint32_t a;
    asm("{ .reg .u64 t; cvta.to.shared.u64 t, %1; cvt.u32.u64 %0, t; }"
        : "=r"(a) : "l"(p));
    return a;
}
__device__ __forceinline__ void cpa16(uint32_t dst, const void* src) {
    asm volatile("cp.async.cg.shared.global [%0], [%1], 16;"
                 :: "r"(dst), "l"(src) : "memory");
}
__device__ __forceinline__ void ldsm4(uint32_t& r0, uint32_t& r1,
                                      uint32_t& r2, uint32_t& r3, uint32_t a) {
    asm volatile("ldmatrix.sync.aligned.m8n8.x4.shared.b16 {%0,%1,%2,%3}, [%4];"
                 : "=r"(r0), "=r"(r1), "=r"(r2), "=r"(r3) : "r"(a));
}
__device__ __forceinline__ void ldsm4t(uint32_t& r0, uint32_t& r1,
                                       uint32_t& r2, uint32_t& r3, uint32_t a) {
    asm volatile("ldmatrix.sync.aligned.m8n8.x4.trans.shared.b16 {%0,%1,%2,%3}, [%4];"
                 : "=r"(r0), "=r"(r1), "=r"(r2), "=r"(r3) : "r"(a));
}
__device__ __forceinline__ void mma_f16(float* c, const uint32_t* a,
                                        const uint32_t* b) {
    asm volatile(
        "mma.sync.aligned.m16n8k16.row.col.f32.f16.f16.f32 "
        "{%0,%1,%2,%3}, {%4,%5,%6,%7}, {%8,%9}, {%0,%1,%2,%3};"
        : "+f"(c[0]), "+f"(c[1]), "+f"(c[2]), "+f"(c[3])
        : "r"(a[0]), "r"(a[1]), "r"(a[2]), "r"(a[3]), "r"(b[0]), "r"(b[1]));
}
// fast exp2 on the FMA pipe (y <= 0; clamp makes masked rows vanish)
__device__ __forceinline__ float fexp2(float y) {
    y = fmaxf(y, -126.f);
    float fl = floorf(y);
    float f = y - fl;
    float p = 1.8775767e-3f;
    p = fmaf(p, f, 8.9893397e-3f);
    p = fmaf(p, f, 5.5826318e-2f);
    p = fmaf(p, f, 2.4015361e-1f);
    p = fmaf(p, f, 6.9315308e-1f);
    p = fmaf(p, f, 9.9999994e-1f);
    return __int_as_float(((int)fl + 127) << 23) * p;
}
__device__ __forceinline__ uint32_t pack_h2(float a, float b) {
    __half2 v = __floats2half2_rn(a, b);
    return *reinterpret_cast<uint32_t*>(&v);
}
__device__ __forceinline__ uint32_t pack_h2_res(float a, float b, uint32_t hi) {
    __half2 hv = *reinterpret_cast<__half2*>(&hi);
    return pack_h2(a - __half2float(hv.x), b - __half2float(hv.y));
}

// ---------------------------------------------------------------------------
// Split conversion: x -> hi fp16 (+ optional lo fp16)
// ---------------------------------------------------------------------------
__global__ void split_kernel(const float* __restrict__ x,
                             __half* __restrict__ hi,
                             __half* __restrict__ lo, int n4)
{
    int i = blockIdx.x * 256 + threadIdx.x;
    if (i >= n4) return;
    float4 v = reinterpret_cast<const float4*>(x)[i];
    uint32_t h01 = pack_h2(v.x, v.y);
    uint32_t h23 = pack_h2(v.z, v.w);
    reinterpret_cast<uint32_t*>(hi)[i * 2 + 0] = h01;
    reinterpret_cast<uint32_t*>(hi)[i * 2 + 1] = h23;
    if (lo) {
        reinterpret_cast<uint32_t*>(lo)[i * 2 + 0] = pack_h2_res(v.x, v.y, h01);
        reinterpret_cast<uint32_t*>(lo)[i * 2 + 1] = pack_h2_res(v.z, v.w, h23);
    }
}

// ---------------------------------------------------------------------------
// Transpose + fp16 truncation: W[K][N] fp32 -> Th[N][K] fp16 (hi only)
// ---------------------------------------------------------------------------
__global__ void tsplit_kernel(const float* __restrict__ W,
                              __half* __restrict__ Thi, int K, int N)
{
    __shared__ float t[32][33];
    int tx = threadIdx.x, ty = threadIdx.y;
    int bx = blockIdx.x, by = blockIdx.y;
#pragma unroll
    for (int i = 0; i < 4; i++) {
        int r = by * 32 + ty + i * 8;
        t[ty + i * 8][tx] = W[(size_t)r * N + bx * 32 + tx];
    }
    __syncthreads();
#pragma unroll
    for (int i = 0; i < 4; i++) {
        int n = bx * 32 + ty + i * 8;
        int k = by * 32 + tx;
        Thi[(size_t)n * K + k] = __float2half_rn(t[tx][ty + i * 8]);
    }
}

// ---------------------------------------------------------------------------
// Fused post-projection conversions: Q rope hi, K rope hi, V split hi.
// ---------------------------------------------------------------------------
constexpr int RQ_BLK = Bn * NHn * Sn * 64 / 256;     // 32768
constexpr int RK_BLK = Bn * NKVn * Sn * 64 / 256;    // 8192
constexpr int SV_BLK = Bn * NKVn * Sn * HDn / 4 / 256; // 4096
constexpr int RS_BLKS = RQ_BLK + RK_BLK + SV_BLK;    // 45056

__device__ __forceinline__ void rope_seg(const float* __restrict__ X,
                                         __half* __restrict__ H,
                                         int idx, float scale)
{
    int d = idx & 63;
    int s = (idx >> 6) & (Sn - 1);
    int bh = idx >> 17;
    float inv = powf(10000.f, -(float)d / 64.f);
    float ang = (float)s * inv;
    float sn, cs;
    sincosf(ang, &sn, &cs);
    size_t base = ((size_t)bh * Sn + s) * HDn;
    float x0 = X[base + d];
    float x1 = X[base + d + 64];
    float r0 = (x0 * cs - x1 * sn) * scale;
    float r1 = (x1 * cs + x0 * sn) * scale;
    H[base + d] = __float2half_rn(r0);
    H[base + d + 64] = __float2half_rn(r1);
}

__global__ __launch_bounds__(256) void ropeall_kernel()
{
    int bid = blockIdx.x, tid = threadIdx.x;
    if (bid < RQ_BLK) {
        rope_seg(g_Q, g_Qh, bid * 256 + tid, QK_SCALE);
        return;
    }
    bid -= RQ_BLK;
    if (bid < RK_BLK) {
        rope_seg(g_K, g_Kh, bid * 256 + tid, 1.f);
        return;
    }
    bid -= RK_BLK;
    {   // V hi-only split
        int i = bid * 256 + tid;
        float4 v = reinterpret_cast<const float4*>(g_V)[i];
        reinterpret_cast<uint32_t*>(g_Vh)[i * 2 + 0] = pack_h2(v.x, v.y);
        reinterpret_cast<uint32_t*>(g_Vh)[i * 2 + 1] = pack_h2(v.z, v.w);
    }
}

// ---------------------------------------------------------------------------
// fp16 GEMM on mma.sync: CTA 128x128, K-chunk 32, 2-stage cp.async, 80 B/row,
// 2 CTAs/SM.
// MODE 5: fused QKV, 2-pass C = (Ah+Al)@Bh^T, blockIdx.z decode.
// MODE 6: O projection, 1-pass C = Ah@Bh^T, row-major out.
// ---------------------------------------------------------------------------
constexpr int TROW = 80;
constexpr int TTILE = 128 * TROW;         // 10240 B
constexpr int TSTAGE = 3 * TTILE;         // 30720 B (Ah, Al, Bh)
constexpr int HG_SMEM = 2 * TSTAGE;       // 61440 B

template <int MODE>
__global__ __launch_bounds__(256, 2) void hgemm_kernel(
    const __half* __restrict__ Ahi, const __half* __restrict__ Alo,
    const __half* __restrict__ Bq, const __half* __restrict__ Bk,
    const __half* __restrict__ Bv,
    float* __restrict__ Cq, float* __restrict__ Ck, float* __restrict__ Cv,
    int N0, int K)
{
    extern __shared__ char smem[];
    const uint32_t sb = smem_u32(smem);

    const int tid = threadIdx.x;
    const int wid = tid >> 5, lane = tid & 31;
    const int g = lane >> 2, t4 = lane & 3;
    const int wr = wid >> 2, wc = wid & 3;
    const int wm = wr * 64, wn = wc * 32;

    int N = N0, heads = NHn;
    const __half* Bsel = Bq;
    float* Csel = Cq;
    int n0 = blockIdx.x * 128;
    const int m0 = blockIdx.y * 128;
    if (MODE == 5 && blockIdx.z == 1) {
        const int bx = blockIdx.x;
        if (bx >= 16) return;
        N = 1024; heads = NKVn;
        n0 = (bx & 7) * 128;
        Bsel = (bx < 8) ? Bk : Bv;
        Csel = (bx < 8) ? Ck : Cv;
    }

    const __half* Ah = Ahi + (size_t)m0 * K;
    const __half* Al = (MODE == 6) ? nullptr : Alo + (size_t)m0 * K;
    const __half* Bh = Bsel + (size_t)n0 * K;

    float c[4][4][4];
#pragma unroll
    for (int mi = 0; mi < 4; mi++)
#pragma unroll
        for (int ni = 0; ni < 4; ni++)
#pragma unroll
            for (int r = 0; r < 4; r++) c[mi][ni][r] = 0.f;

    auto load_chunk = [&](int stage, int koff) {
        const uint32_t base = sb + stage * TSTAGE;
#pragma unroll
        for (int i = 0; i < 6; i++) {
            const int tile = i >> 1;
            if (MODE == 6 && tile == 1) continue;   // no A-lo tile
            const int id = tid + (i & 1) * 256;
            const int r = id >> 2, c4 = id & 3;
            const __half* s = (tile == 0) ? Ah : (tile == 1) ? Al : Bh;
            cpa16(base + tile * TTILE + r * TROW + c4 * 16,
                  s + (size_t)r * K + koff + c4 * 8);
        }
        asm volatile("cp.async.commit_group;" ::: "memory");
    };

    const int NC = K / 32;
    load_chunk(0, 0);
    load_chunk(1, 32);

    const int arow_off = (lane & 7) + ((lane >> 3) & 1) * 8;
    const int acol_off = (lane >> 4) * 8;
    const int brow_off = (lane & 7) + (lane >> 4) * 8;
    const int bcol_off = ((lane >> 3) & 1) * 8;

    for (int ch = 0; ch < NC; ch++) {
        if (ch + 1 < NC)
            asm volatile("cp.async.wait_group 1;" ::: "memory");
        else
            asm volatile("cp.async.wait_group 0;" ::: "memory");
        __syncthreads();

        const uint32_t st = sb + (ch & 1) * TSTAGE;
        const uint32_t ah_b = st, al_b = st + TTILE, bh_b = st + 2 * TTILE;

#pragma unroll
        for (int kk = 0; kk < 32; kk += 16) {
            uint32_t fah[4][4], fal[4][4], fbh[4][2];
#pragma unroll
            for (int mi = 0; mi < 4; mi++) {
                const uint32_t ro = (wm + mi * 16 + arow_off) * TROW +
                                    (kk + acol_off) * 2;
                ldsm4(fah[mi][0], fah[mi][1], fah[mi][2], fah[mi][3], ah_b + ro);
                if (MODE != 6)
                    ldsm4(fal[mi][0], fal[mi][1], fal[mi][2], fal[mi][3],
                          al_b + ro);
            }
#pragma unroll
            for (int bt = 0; bt < 2; bt++) {
                const uint32_t ro = (wn + bt * 16 + brow_off) * TROW +
                                    (kk + bcol_off) * 2;
                ldsm4(fbh[2 * bt][0], fbh[2 * bt][1],
                      fbh[2 * bt + 1][0], fbh[2 * bt + 1][1], bh_b + ro);
            }
#pragma unroll
            for (int mi = 0; mi < 4; mi++)
#pragma unroll
                for (int ni = 0; ni < 4; ni++) {
                    mma_f16(c[mi][ni], fah[mi], fbh[ni]);
                    if (MODE != 6)
                        mma_f16(c[mi][ni], fal[mi], fbh[ni]);
                }
        }
        __syncthreads();
        if (ch + 2 < NC) load_chunk(ch & 1, (ch + 2) * 32);
    }

    if (MODE == 6) {
#pragma unroll
        for (int mi = 0; mi < 4; mi++)
#pragma unroll
            for (int ni = 0; ni < 4; ni++) {
                const int row0 = m0 + wm + mi * 16 + g;
                const int col = n0 + wn + ni * 8 + 2 * t4;
#pragma unroll
                for (int half = 0; half < 2; half++) {
                    const int m = row0 + half * 8;
                    float2 v = half ? make_float2(c[mi][ni][2], c[mi][ni][3])
                                    : make_float2(c[mi][ni][0], c[mi][ni][1]);
                    *reinterpret_cast<float2*>(&Csel[(size_t)m * N + col]) = v;
                }
            }
    } else {
#pragma unroll
        for (int mi = 0; mi < 4; mi++)
#pragma unroll
            for (int ni = 0; ni < 4; ni++) {
                const int row0 = m0 + wm + mi * 16 + g;
                const int col = n0 + wn + ni * 8 + 2 * t4;
#pragma unroll
                for (int half = 0; half < 2; half++) {
                    const int m = row0 + half * 8;
                    float2 v = half ? make_float2(c[mi][ni][2], c[mi][ni][3])
                                    : make_float2(c[mi][ni][0], c[mi][ni][1]);
                    int b = m >> 11, s = m & 2047;
                    int h = col >> 7, d = col & 127;
                    *reinterpret_cast<float2*>(
                        &Csel[(((size_t)(b * heads + h) * Sn) + s) * HDn + d]) = v;
                }
            }
    }
}

// ---------------------------------------------------------------------------
// Flash attention, fp16 1-pass: scores = Qh·Kh, O = Ph·Vh.
// BQ=128, BK=64, 8 warps, 2-stage pipeline, LPT order.
// Output hi fp16 into g_Xhi.
// ---------------------------------------------------------------------------
constexpr int ARB = 272;
constexpr int KVT = 64 * ARB;             // 17408 B
constexpr int ASTG = 2 * KVT;             // Kh, Vh per stage = 34816 B
constexpr int AT_SMEM = 2 * ASTG + 34816; // + Qh = 104448 B

__global__ __launch_bounds__(256, 1) void attn_mma_kernel()
{
    extern __shared__ char smem[];
    const uint32_t sb = smem_u32(smem);
    const int qt = (int)gridDim.x - 1 - blockIdx.x;   // LPT order
    const int h = blockIdx.y, b = blockIdx.z;
    const int tid = threadIdx.x, wid = tid >> 5, lane = tid & 31;
    const int g = lane >> 2, t4 = lane & 3;
    const int wm = wid * 16;
    const int kvh = h >> 2;
    const int NT = 2 * (qt + 1);

    const __half* Qhp = g_Qh + ((size_t)(b * NHn + h) * Sn + qt * 128) * HDn;
    const __half* Khp = g_Kh + ((size_t)(b * NKVn + kvh) * Sn) * HDn;
    const __half* Vhp = g_Vh + ((size_t)(b * NKVn + kvh) * Sn) * HDn;

    const uint32_t qhb = sb + 2 * ASTG;
#pragma unroll
    for (int i = 0; i < 8; i++) {
        int id = tid + i * 256, r = id >> 4, c = id & 15;
        cpa16(qhb + r * ARB + c * 16, Qhp + r * HDn + c * 8);
    }
    asm volatile("cp.async.commit_group;" ::: "memory");

    auto load_stage = [&](int stg, int t) {
        const uint32_t st = sb + stg * ASTG;
        const __half* kh = Khp + (size_t)t * 64 * HDn;
        const __half* vh = Vhp + (size_t)t * 64 * HDn;
#pragma unroll
        for (int i = 0; i < 4; i++) {
            int id = tid + i * 256, r = id >> 4, c = id & 15;
            cpa16(st + 0 * KVT + r * ARB + c * 16, kh + r * HDn + c * 8);
            cpa16(st + 1 * KVT + r * ARB + c * 16, vh + r * HDn + c * 8);
        }
        asm volatile("cp.async.commit_group;" ::: "memory");
    };
    load_stage(0, 0);

    asm volatile("cp.async.wait_group 1;" ::: "memory");  // Q arrived
    __syncthreads();

    const int arow = (lane & 7) + ((lane >> 3) & 1) * 8;
    const int acolB = (lane >> 4) * 16;
    uint32_t qhf[8][4];
#pragma unroll
    for (int ks = 0; ks < 8; ks++) {
        uint32_t ro = (wm + arow) * ARB + ks * 32 + acolB;
        ldsm4(qhf[ks][0], qhf[ks][1], qhf[ks][2], qhf[ks][3], qhb + ro);
    }
    __syncthreads();
    load_stage(1, 1);

    float o[16][4];
#pragma unroll
    for (int j = 0; j < 16; j++)
#pragma unroll
        for (int e = 0; e < 4; e++) o[j][e] = 0.f;
    float m0 = -1e30f, m1 = -1e30f, l0 = 0.f, l1 = 0.f;

    const int brow = (lane & 7) + (lane >> 4) * 8;
    const int bcolB = ((lane >> 3) & 1) * 16;
    const int vcolB = (lane >> 4) * 16;
    const int row0g = qt * 128 + wm + g;

    for (int t = 0; t < NT; t++) {
        if (t + 1 < NT)
            asm volatile("cp.async.wait_group 1;" ::: "memory");
        else
            asm volatile("cp.async.wait_group 0;" ::: "memory");
        __syncthreads();
        const uint32_t st = sb + (t & 1) * ASTG;

        float s[8][4];
#pragma unroll
        for (int j = 0; j < 8; j++)
#pragma unroll
            for (int e = 0; e < 4; e++) s[j][e] = 0.f;

#pragma unroll
        for (int ks = 0; ks < 8; ks++) {
#pragma unroll
            for (int gr = 0; gr < 4; gr++) {
                uint32_t kh4[4];
                uint32_t ro = st + (gr * 16 + brow) * ARB + ks * 32 + bcolB;
                ldsm4(kh4[0], kh4[1], kh4[2], kh4[3], ro);
                mma_f16(s[2 * gr], qhf[ks], kh4);
                mma_f16(s[2 * gr + 1], qhf[ks], kh4 + 2);
            }
        }

        if (t >= 2 * qt) {
#pragma unroll
            for (int j = 0; j < 8; j++) {
                int c0 = t * 64 + j * 8 + 2 * t4;
                if (c0 > row0g)     s[j][0] = -1e30f;
                if (c0 + 1 > row0g) s[j][1] = -1e30f;
                if (c0 > row0g + 8)     s[j][2] = -1e30f;
                if (c0 + 1 > row0g + 8) s[j][3] = -1e30f;
            }
        }

        float tm0 = -1e30f, tm1 = -1e30f;
#pragma unroll
        for (int j = 0; j < 8; j++) {
            tm0 = fmaxf(tm0, fmaxf(s[j][0], s[j][1]));
            tm1 = fmaxf(tm1, fmaxf(s[j][2], s[j][3]));
        }
        tm0 = fmaxf(tm0, __shfl_xor_sync(0xffffffffu, tm0, 1));
        tm0 = fmaxf(tm0, __shfl_xor_sync(0xffffffffu, tm0, 2));
        tm1 = fmaxf(tm1, __shfl_xor_sync(0xffffffffu, tm1, 1));
        tm1 = fmaxf(tm1, __shfl_xor_sync(0xffffffffu, tm1, 2));
        float mn0 = fmaxf(m0, tm0), mn1 = fmaxf(m1, tm1);
        float cor0 = fexp2((m0 - mn0) * L2E);
        float cor1 = fexp2((m1 - mn1) * L2E);
        m0 = mn0; m1 = mn1;
#pragma unroll
        for (int j = 0; j < 16; j++) {
            o[j][0] *= cor0; o[j][1] *= cor0;
            o[j][2] *= cor1; o[j][3] *= cor1;
        }
        float rs0 = 0.f, rs1 = 0.f;
#pragma unroll
        for (int j = 0; j < 8; j++) {
            s[j][0] = fexp2((s[j][0] - mn0) * L2E);
            s[j][1] = fexp2((s[j][1] - mn0) * L2E);
            s[j][2] = fexp2((s[j][2] - mn1) * L2E);
            s[j][3] = fexp2((s[j][3] - mn1) * L2E);
            rs0 += s[j][0] + s[j][1];
            rs1 += s[j][2] + s[j][3];
        }
        rs0 += __shfl_xor_sync(0xffffffffu, rs0, 1);
        rs0 += __shfl_xor_sync(0xffffffffu, rs0, 2);
        rs1 += __shfl_xor_sync(0xffffffffu, rs1, 1);
        rs1 += __shfl_xor_sync(0xffffffffu, rs1, 2);
        l0 = l0 * cor0 + rs0;
        l1 = l1 * cor1 + rs1;

        // ---- O += P V (1-pass: Ph only) ----
#pragma unroll
        for (int ks = 0; ks < 4; ks++) {
            uint32_t pha[4];
            pha[0] = pack_h2(s[2 * ks][0], s[2 * ks][1]);
            pha[1] = pack_h2(s[2 * ks][2], s[2 * ks][3]);
            pha[2] = pack_h2(s[2 * ks + 1][0], s[2 * ks + 1][1]);
            pha[3] = pack_h2(s[2 * ks + 1][2], s[2 * ks + 1][3]);
#pragma unroll
            for (int gr = 0; gr < 8; gr++) {
                uint32_t vh4[4];
                uint32_t ro = st + KVT + (ks * 16 + arow) * ARB +
                              gr * 32 + vcolB;
                ldsm4t(vh4[0], vh4[1], vh4[2], vh4[3], ro);
                mma_f16(o[2 * gr], pha, vh4);
                mma_f16(o[2 * gr + 1], pha, vh4 + 2);
            }
        }
        __syncthreads();
        if (t + 2 < NT) load_stage(t & 1, t + 2);
    }

    // ---- epilogue: normalize, write hi fp16 into g_Xhi [b][s][h*d] ----
    float inv0 = 1.f / l0, inv1 = 1.f / l1;
    const int r0 = qt * 128 + wm + g, r1 = r0 + 8;
#pragma unroll
    for (int j = 0; j < 16; j++) {
        int col = h * 128 + j * 8 + 2 * t4;
        size_t i0 = ((size_t)(b * Sn + r0)) * 4096 + col;
        size_t i1 = ((size_t)(b * Sn + r1)) * 4096 + col;
        *reinterpret_cast<uint32_t*>(&g_Xhi[i0]) =
            pack_h2(o[j][0] * inv0, o[j][1] * inv0);
        *reinterpret_cast<uint32_t*>(&g_Xhi[i1]) =
            pack_h2(o[j][2] * inv1, o[j][3] * inv1);
    }
}

// ---------------------------------------------------------------------------
extern "C" void kernel_launch(void* const* d_in, const int* in_sizes, int n_in,
                              void* d_out, int out_size)
{
    const float* hidden = (const float*)d_in[0];
    const float* Wq = (const float*)d_in[2];
    const float* Wk = (const float*)d_in[3];
    const float* Wv = (const float*)d_in[4];
    const float* Wo = (const float*)d_in[5];
    float* out = (float*)d_out;

    float *pQ, *pK, *pV;
    __half *pXh, *pXl, *pQT, *pKT, *pVT, *pOT;
    cudaGetSymbolAddress((void**)&pQ, g_Q);
    cudaGetSymbolAddress((void**)&pK, g_K);
    cudaGetSymbolAddress((void**)&pV, g_V);
    cudaGetSymbolAddress((void**)&pXh, g_Xhi);
    cudaGetSymbolAddress((void**)&pXl, g_Xlo);
    cudaGetSymbolAddress((void**)&pQT, g_WqTh);
    cudaGetSymbolAddress((void**)&pKT, g_WkTh);
    cudaGetSymbolAddress((void**)&pVT, g_WvTh);
    cudaGetSymbolAddress((void**)&pOT, g_WoTh);

    cudaFuncSetAttribute(hgemm_kernel<5>,
                         cudaFuncAttributeMaxDynamicSharedMemorySize, HG_SMEM);
    cudaFuncSetAttribute(hgemm_kernel<6>,
                         cudaFuncAttributeMaxDynamicSharedMemorySize, HG_SMEM);
    cudaFuncSetAttribute(attn_mma_kernel,
                         cudaFuncAttributeMaxDynamicSharedMemorySize, AT_SMEM);

    const int n4x = Mn * Hn / 4;
    dim3 tb(32, 8);

    split_kernel<<<n4x / 256, 256>>>(hidden, pXh, pXl, n4x);                 // 1
    tsplit_kernel<<<dim3(4096 / 32, 4096 / 32), tb>>>(Wq, pQT, Hn, 4096);    // 2
    tsplit_kernel<<<dim3(1024 / 32, 4096 / 32), tb>>>(Wk, pKT, Hn, 1024);    // 3
    tsplit_kernel<<<dim3(1024 / 32, 4096 / 32), tb>>>(Wv, pVT, Hn, 1024);    // 4

    // fused Q+K+V projection GEMM (2-pass)
    hgemm_kernel<5><<<dim3(32, Mn / 128, 2), 256, HG_SMEM>>>(                // 5
        pXh, pXl, pQT, pKT, pVT, pQ, pK, pV, 4096, Hn);

    tsplit_kernel<<<dim3(4096 / 32, 4096 / 32), tb>>>(Wo, pOT, 4096, Hn);    // 6

    // fused RoPE(Q hi) + RoPE(K hi) + V split
    ropeall_kernel<<<RS_BLKS, 256>>>();                                      // 7

    // causal flash attention (LPT; 1-pass QK and PV; writes hi into g_Xhi)
    dim3 ga(Sn / 128, NHn, Bn);
    attn_mma_kernel<<<ga, 256, AT_SMEM>>>();                                 // 8

    // output projection (1-pass fp16: out = Xhi @ WoT)
    hgemm_kernel<6><<<dim3(4096 / 128, Mn / 128), 256, HG_SMEM>>>(           // 9
        pXh, nullptr, pOT, nullptr, nullptr, out, nullptr, nullptr, 4096, Hn);
}